// round 7
// baseline (speedup 1.0000x reference)
#include <cuda_runtime.h>
#include <cstdint>

// Problem dims
#define B_    8
#define N_    1024
#define R_    16384
#define HID_  512
#define MROWS (B_ * R_)      // 131072
#define NROWS (B_ * N_)      // 8192

// ---------------- scratch (device globals; no allocations allowed) ----------
__device__ __align__(128) float g_node[MROWS * 64];    // node_obj; later edgeT [16384,512]
__device__ __align__(128) float g_bufA[MROWS * HID_];  // h1
__device__ __align__(128) float g_bufB[MROWS * HID_];  // h2
__device__ __align__(128) float g_agg [N_ * 512];      // agg2 [1024, 512]  (col = b*64+e)
__device__ __align__(128) float g_upd [NROWS * 96];    // update_node [8192,96]
__device__ __align__(128) float g_hobj[NROWS * HID_];  // object hidden [8192,512]
__device__ __align__(128) float g_objT[N_ * 256];      // objT [1024, 256]  (col = b*32+d)

// ---------------- helpers ----------------------------------------------------
__device__ __forceinline__ float f2tf(float x) {
    uint32_t u;
    asm("cvt.rna.tf32.f32 %0, %1;" : "=r"(u) : "f"(x));
    return __uint_as_float(u);
}

__device__ __forceinline__ void mma_tf32(float d[4], const uint32_t* a, const uint32_t* b) {
    asm volatile(
        "mma.sync.aligned.m16n8k8.row.col.f32.tf32.tf32.f32 "
        "{%0,%1,%2,%3},{%4,%5,%6,%7},{%8,%9},{%0,%1,%2,%3};\n"
        : "+f"(d[0]), "+f"(d[1]), "+f"(d[2]), "+f"(d[3])
        : "r"(a[0]), "r"(a[1]), "r"(a[2]), "r"(a[3]), "r"(b[0]), "r"(b[1]));
}

// Fragment-order smem index for A element (k, m); per-stage layout:
// [(k>>3)*(BM/16) + (m>>4)] blocks of 32 lanes x 4 regs.
template<int BM>
__device__ __forceinline__ int a_fidx(int k, int m) {
    int lane = ((m & 7) << 2) | (k & 3);
    int reg  = ((m >> 3) & 1) | (((k >> 2) & 1) << 1);
    return (((k >> 3) * (BM / 16) + (m >> 4)) * 32 + lane) * 4 + reg;
}
// Fragment-order smem index for B element (k, n)
template<int BN>
__device__ __forceinline__ int b_fidx(int k, int n) {
    int lane = ((n & 7) << 2) | (k & 3);
    int reg  = (k >> 2) & 1;
    return (((k >> 3) * (BN / 8) + (n >> 3)) * 32 + lane) * 2 + reg;
}

// MODE: 0 = C[row*N+col]=bias+act  1 = gather-scatter to node  2 = edgeT store  3 = split-K atomic
template<int MODE, bool RELU>
__device__ __forceinline__ void store_one(float* __restrict__ C, const float* __restrict__ bias,
                                          int row, int col, int N, int off, float v) {
    if (MODE == 0) {
        v += bias[col]; if (RELU) v = fmaxf(v, 0.f);
        C[(size_t)row * N + col] = v;
    } else if (MODE == 1) {
        int b = col >> 5, d = col & 31;
        C[(((size_t)b << 14) + row) * 64 + off + d] = v;
    } else if (MODE == 2) {
        v += bias[col]; if (RELU) v = fmaxf(v, 0.f);
        int b = row >> 14, r = row & 16383;
        C[(size_t)r * 512 + (b << 6) + col] = v;
    } else {
        atomicAdd(&C[(size_t)row * N + col], v);
    }
}

// ---------------- tf32 tensor-core GEMM: C = act(A @ W + bias) ---------------
// BM=BN=128, BK=16, 256 threads, 8 warps (2m x 4n), warp tile 64x32.
// Fragment-ordered smem + register-prefetch double buffering.
template<int MODE, bool RELU, bool ATRANS>
__global__ __launch_bounds__(256, 2) void mma_gemm(
    const float* __restrict__ A, const float* __restrict__ W,
    const float* __restrict__ bias, float* __restrict__ C,
    int N, int lda, int klen, int off)
{
    constexpr int BM = 128, BN = 128, BK = 16;
    constexpr int ASTG = BM * BK, BSTG = BN * BK;   // 2048 each
    __shared__ float Asm[2 * ASTG];
    __shared__ float Bsm[2 * BSTG];

    const int tid = threadIdx.x, lane = tid & 31, wid = tid >> 5;
    const int wm = (wid >> 2) * 64, wn = (wid & 3) * 32;
    const int row0 = blockIdx.y * BM, col0 = blockIdx.x * BN;
    const int kstart = blockIdx.z * klen;
    const int ntiles = klen / BK;

    float acc[4][4][4];
    #pragma unroll
    for (int mi = 0; mi < 4; mi++)
        #pragma unroll
        for (int ni = 0; ni < 4; ni++)
            #pragma unroll
            for (int j = 0; j < 4; j++) acc[mi][ni][j] = 0.f;

    float4 apre[2], bpre[2];

    // ---- G2R ----
    auto g2r = [&](int kk) {
        #pragma unroll
        for (int p = 0; p < 2; p++) {
            int i = tid * 4 + p * 1024;
            if (!ATRANS) {
                int r = i / BK, c = i % BK;
                apre[p] = *(const float4*)&A[(size_t)(row0 + r) * lda + kk + c];
            } else {
                int k = i / BM, m = i % BM;
                apre[p] = *(const float4*)&A[(size_t)(kk + k) * lda + row0 + m];
            }
            int kw = i / BN, n = i % BN;
            bpre[p] = *(const float4*)&W[(size_t)(kk + kw) * N + col0 + n];
        }
    };
    // ---- R2S (with tf32 rounding) ----
    auto r2s = [&](int st) {
        float* As = Asm + st * ASTG;
        float* Bs = Bsm + st * BSTG;
        #pragma unroll
        for (int p = 0; p < 2; p++) {
            int i = tid * 4 + p * 1024;
            if (!ATRANS) {
                int r = i / BK, c = i % BK;
                int base = a_fidx<BM>(c, r);      // j -> +4
                As[base + 0]  = f2tf(apre[p].x);
                As[base + 4]  = f2tf(apre[p].y);
                As[base + 8]  = f2tf(apre[p].z);
                As[base + 12] = f2tf(apre[p].w);
            } else {
                int k = i / BM, m = i % BM;
                int base = a_fidx<BM>(k, m);      // j -> +16
                As[base + 0]  = f2tf(apre[p].x);
                As[base + 16] = f2tf(apre[p].y);
                As[base + 32] = f2tf(apre[p].z);
                As[base + 48] = f2tf(apre[p].w);
            }
            int kw = i / BN, n = i % BN;
            int bb = b_fidx<BN>(kw, n);           // j -> +8
            Bs[bb + 0]  = f2tf(bpre[p].x);
            Bs[bb + 8]  = f2tf(bpre[p].y);
            Bs[bb + 16] = f2tf(bpre[p].z);
            Bs[bb + 24] = f2tf(bpre[p].w);
        }
    };

    g2r(kstart);
    r2s(0);
    __syncthreads();

    for (int t = 0; t < ntiles; t++) {
        const int st = t & 1;
        if (t + 1 < ntiles) g2r(kstart + (t + 1) * BK);
        const float4* Af = (const float4*)(Asm + st * ASTG);
        const float2* Bf = (const float2*)(Bsm + st * BSTG);
        #pragma unroll
        for (int s = 0; s < 2; s++) {
            float4 a4[4]; float2 b2[4];
            #pragma unroll
            for (int mi = 0; mi < 4; mi++)
                a4[mi] = Af[(s * (BM / 16) + (wm >> 4) + mi) * 32 + lane];
            #pragma unroll
            for (int ni = 0; ni < 4; ni++)
                b2[ni] = Bf[(s * (BN / 8) + (wn >> 3) + ni) * 32 + lane];
            #pragma unroll
            for (int mi = 0; mi < 4; mi++)
                #pragma unroll
                for (int ni = 0; ni < 4; ni++)
                    mma_tf32(acc[mi][ni], (const uint32_t*)&a4[mi], (const uint32_t*)&b2[ni]);
        }
        if (t + 1 < ntiles) {
            __syncthreads();
            r2s((t + 1) & 1);
        }
        __syncthreads();
    }

    // epilogue
    const int lc = lane & 3, lg = lane >> 2;
    #pragma unroll
    for (int mi = 0; mi < 4; mi++) {
        int r0 = row0 + wm + mi * 16 + lg;
        #pragma unroll
        for (int ni = 0; ni < 4; ni++) {
            int c0 = col0 + wn + ni * 8 + lc * 2;
            store_one<MODE, RELU>(C, bias, r0,     c0,     N, off, acc[mi][ni][0]);
            store_one<MODE, RELU>(C, bias, r0,     c0 + 1, N, off, acc[mi][ni][1]);
            store_one<MODE, RELU>(C, bias, r0 + 8, c0,     N, off, acc[mi][ni][2]);
            store_one<MODE, RELU>(C, bias, r0 + 8, c0 + 1, N, off, acc[mi][ni][3]);
        }
    }
}

// ---------------- fused rw3+rw4: edgeT = relu(relu(h2@W3+b3)@W4+b4) ----------
// BM=128, BN=64, 128 threads, 4 warps (2m x 2n), warp tile 64x32.
__global__ __launch_bounds__(128, 3) void rw34_kernel(
    const float* __restrict__ A,   // h2 [MROWS, 512]
    const float* __restrict__ W3, const float* __restrict__ b3,
    const float* __restrict__ W4, const float* __restrict__ b4,
    float* __restrict__ C)         // edgeT [16384, 512] (col = b*64+e)
{
    constexpr int BM = 128, BN = 64, BK = 16, K1 = 512;
    constexpr int ASTG = BM * BK, BSTG = BN * BK;   // 2048, 1024
    __shared__ float sm[12288];                      // 48KB
    float* Asm = sm;                // phase1 A stages [0, 4096)
    float* Bsm = sm + 2 * ASTG;     // phase1 B stages [4096, 6144)
    float* Hs  = sm;                // phase2 h3 A-frag [0, 8192)
    float* W4s = sm + 8192;         // phase2 W4 B-frag [8192, 12288)

    const int tid = threadIdx.x, lane = tid & 31, wid = tid >> 5;
    const int wm = (wid >> 1) * 64, wn = (wid & 1) * 32;
    const int row0 = blockIdx.x * BM;
    const int lc = lane & 3, lg = lane >> 2;

    float acc[4][4][4];
    #pragma unroll
    for (int mi = 0; mi < 4; mi++)
        #pragma unroll
        for (int ni = 0; ni < 4; ni++)
            #pragma unroll
            for (int j = 0; j < 4; j++) acc[mi][ni][j] = 0.f;

    float4 apre[4], bpre[2];
    auto g2r = [&](int kk) {
        #pragma unroll
        for (int p = 0; p < 4; p++) {
            int i = tid * 4 + p * 512;
            int r = i / BK, c = i % BK;
            apre[p] = *(const float4*)&A[(size_t)(row0 + r) * K1 + kk + c];
        }
        #pragma unroll
        for (int p = 0; p < 2; p++) {
            int i = tid * 4 + p * 512;
            int kw = i / BN, n = i % BN;
            bpre[p] = *(const float4*)&W3[(size_t)(kw + kk) * BN + n];
        }
    };
    auto r2s = [&](int st) {
        float* As = Asm + st * ASTG;
        float* Bs = Bsm + st * BSTG;
        #pragma unroll
        for (int p = 0; p < 4; p++) {
            int i = tid * 4 + p * 512;
            int r = i / BK, c = i % BK;
            int base = a_fidx<BM>(c, r);
            As[base + 0]  = f2tf(apre[p].x);
            As[base + 4]  = f2tf(apre[p].y);
            As[base + 8]  = f2tf(apre[p].z);
            As[base + 12] = f2tf(apre[p].w);
        }
        #pragma unroll
        for (int p = 0; p < 2; p++) {
            int i = tid * 4 + p * 512;
            int kw = i / BN, n = i % BN;
            int bb = b_fidx<BN>(kw, n);
            Bs[bb + 0]  = f2tf(bpre[p].x);
            Bs[bb + 8]  = f2tf(bpre[p].y);
            Bs[bb + 16] = f2tf(bpre[p].z);
            Bs[bb + 24] = f2tf(bpre[p].w);
        }
    };

    g2r(0);
    r2s(0);
    __syncthreads();
    const int ntiles = K1 / BK;   // 32
    for (int t = 0; t < ntiles; t++) {
        const int st = t & 1;
        if (t + 1 < ntiles) g2r((t + 1) * BK);
        const float4* Af = (const float4*)(Asm + st * ASTG);
        const float2* Bf = (const float2*)(Bsm + st * BSTG);
        #pragma unroll
        for (int s = 0; s < 2; s++) {
            float4 a4[4]; float2 b2[4];
            #pragma unroll
            for (int mi = 0; mi < 4; mi++)
                a4[mi] = Af[(s * (BM / 16) + (wm >> 4) + mi) * 32 + lane];
            #pragma unroll
            for (int ni = 0; ni < 4; ni++)
                b2[ni] = Bf[(s * (BN / 8) + (wn >> 3) + ni) * 32 + lane];
            #pragma unroll
            for (int mi = 0; mi < 4; mi++)
                #pragma unroll
                for (int ni = 0; ni < 4; ni++)
                    mma_tf32(acc[mi][ni], (const uint32_t*)&a4[mi], (const uint32_t*)&b2[ni]);
        }
        if (t + 1 < ntiles) { __syncthreads(); r2s((t + 1) & 1); }
        __syncthreads();
    }

    // h3 = relu(acc + b3) -> Hs in A-fragment layout (BM=128, K=64 -> kb 0..7)
    #pragma unroll
    for (int mi = 0; mi < 4; mi++) {
        int m0 = wm + mi * 16 + lg;
        #pragma unroll
        for (int ni = 0; ni < 4; ni++) {
            int c0 = wn + ni * 8 + lc * 2;
            float v0 = fmaxf(acc[mi][ni][0] + b3[c0],     0.f);
            float v1 = fmaxf(acc[mi][ni][1] + b3[c0 + 1], 0.f);
            float v2 = fmaxf(acc[mi][ni][2] + b3[c0],     0.f);
            float v3 = fmaxf(acc[mi][ni][3] + b3[c0 + 1], 0.f);
            Hs[a_fidx<BM>(c0,     m0)]     = f2tf(v0);
            Hs[a_fidx<BM>(c0 + 1, m0)]     = f2tf(v1);
            Hs[a_fidx<BM>(c0,     m0 + 8)] = f2tf(v2);
            Hs[a_fidx<BM>(c0 + 1, m0 + 8)] = f2tf(v3);
        }
    }
    // W4 [64x64] -> B-fragment layout
    #pragma unroll
    for (int p = 0; p < 8; p++) {
        int i = tid * 4 + p * 512;
        int k = i >> 6, n = i & 63;
        float4 v = *(const float4*)&W4[(size_t)k * 64 + n];
        int bb = b_fidx<64>(k, n);
        W4s[bb + 0]  = f2tf(v.x);
        W4s[bb + 8]  = f2tf(v.y);
        W4s[bb + 16] = f2tf(v.z);
        W4s[bb + 24] = f2tf(v.w);
    }
    __syncthreads();

    // phase 2: edge = relu(h3 @ W4 + b4), K=64 (8 k-blocks)
    #pragma unroll
    for (int mi = 0; mi < 4; mi++)
        #pragma unroll
        for (int ni = 0; ni < 4; ni++)
            #pragma unroll
            for (int j = 0; j < 4; j++) acc[mi][ni][j] = 0.f;

    const float4* Hf = (const float4*)Hs;
    const float2* Wf = (const float2*)W4s;
    #pragma unroll
    for (int s = 0; s < 8; s++) {
        float4 a4[4]; float2 b2[4];
        #pragma unroll
        for (int mi = 0; mi < 4; mi++)
            a4[mi] = Hf[(s * (BM / 16) + (wm >> 4) + mi) * 32 + lane];
        #pragma unroll
        for (int ni = 0; ni < 4; ni++)
            b2[ni] = Wf[(s * 8 + (wn >> 3) + ni) * 32 + lane];
        #pragma unroll
        for (int mi = 0; mi < 4; mi++)
            #pragma unroll
            for (int ni = 0; ni < 4; ni++)
                mma_tf32(acc[mi][ni], (const uint32_t*)&a4[mi], (const uint32_t*)&b2[ni]);
    }

    // epilogue: edgeT[r, b*64+e]
    #pragma unroll
    for (int mi = 0; mi < 4; mi++) {
        int row = row0 + wm + mi * 16 + lg;
        int b = row >> 14, r = row & 16383;
        #pragma unroll
        for (int ni = 0; ni < 4; ni++) {
            int c0 = wn + ni * 8 + lc * 2;
            float v0 = fmaxf(acc[mi][ni][0] + b4[c0],     0.f);
            float v1 = fmaxf(acc[mi][ni][1] + b4[c0 + 1], 0.f);
            float v2 = fmaxf(acc[mi][ni][2] + b4[c0],     0.f);
            float v3 = fmaxf(acc[mi][ni][3] + b4[c0 + 1], 0.f);
            C[(size_t)r * 512 + (b << 6) + c0]            = v0;
            C[(size_t)r * 512 + (b << 6) + c0 + 1]        = v1;
            int row2 = row + 8; int b2i = row2 >> 14, r2 = row2 & 16383;
            C[(size_t)r2 * 512 + (b2i << 6) + c0]         = v2;
            C[(size_t)r2 * 512 + (b2i << 6) + c0 + 1]     = v3;
        }
    }
}

// ---------------- SIMT fp32 GEMM (tiny final layer) --------------------------
template<int BM, int BN, int BK, int TM, int TN, bool RELU>
__global__ __launch_bounds__((BM/TM)*(BN/TN)) void gemm_kernel(
    const float* __restrict__ A, const float* __restrict__ W,
    const float* __restrict__ bias, float* __restrict__ C,
    int M, int K, int N)
{
    __shared__ float As[BK][BM];
    __shared__ float Ws[BK][BN];
    const int nthr = (BM / TM) * (BN / TN);
    const int tid = threadIdx.x;
    const int tn = tid % (BN / TN);
    const int tm = tid / (BN / TN);
    const int row0 = blockIdx.y * BM;
    const int col0 = blockIdx.x * BN;

    float acc[TM][TN];
    #pragma unroll
    for (int m = 0; m < TM; m++)
        #pragma unroll
        for (int n = 0; n < TN; n++) acc[m][n] = 0.f;

    for (int k0 = 0; k0 < K; k0 += BK) {
        #pragma unroll
        for (int i = tid * 4; i < BM * BK; i += nthr * 4) {
            int r = i / BK, c = i % BK;
            float4 v = *(const float4*)&A[(size_t)(row0 + r) * K + k0 + c];
            As[c + 0][r] = v.x; As[c + 1][r] = v.y;
            As[c + 2][r] = v.z; As[c + 3][r] = v.w;
        }
        #pragma unroll
        for (int i = tid * 4; i < BK * BN; i += nthr * 4) {
            int r = i / BN, c = i % BN;
            *(float4*)&Ws[r][c] = *(const float4*)&W[(size_t)(k0 + r) * N + col0 + c];
        }
        __syncthreads();
        #pragma unroll
        for (int k = 0; k < BK; k++) {
            float a[TM], b[TN];
            #pragma unroll
            for (int m = 0; m < TM; m++) a[m] = As[k][tm * TM + m];
            #pragma unroll
            for (int n = 0; n < TN; n++) b[n] = Ws[k][tn * TN + n];
            #pragma unroll
            for (int m = 0; m < TM; m++)
                #pragma unroll
                for (int n = 0; n < TN; n++) acc[m][n] += a[m] * b[n];
        }
        __syncthreads();
    }
    #pragma unroll
    for (int m = 0; m < TM; m++) {
        int row = row0 + tm * TM + m;
        #pragma unroll
        for (int n = 0; n < TN; n++) {
            int col = col0 + tn * TN + n;
            float v = acc[m][n] + bias[col];
            if (RELU) v = fmaxf(v, 0.f);
            C[(size_t)row * N + col] = v;
        }
    }
}

// ---------------- small utility kernels --------------------------------------
__global__ void pack_objT_kernel(const float* __restrict__ obj, float* __restrict__ objT) {
    int i = blockIdx.x * blockDim.x + threadIdx.x;
    if (i < N_ * 256) {
        int n = i >> 8, c = i & 255;
        int b = c >> 5, d = c & 31;
        objT[i] = obj[((size_t)b * N_ + n) * 32 + d];
    }
}

__global__ void zero_kernel(float* p, int n) {
    int i = blockIdx.x * blockDim.x + threadIdx.x;
    if (i < n) p[i] = 0.f;
}

__global__ void concat_kernel(const float* __restrict__ obj,
                              const float* __restrict__ agg2,
                              float* __restrict__ upd) {
    int i = blockIdx.x * blockDim.x + threadIdx.x;
    if (i < NROWS * 96) {
        int row = i / 96, j = i % 96;
        int b = row >> 10, n = row & 1023;
        upd[i] = (j < 32) ? obj[(size_t)row * 32 + j]
                          : agg2[(size_t)n * 512 + (b << 6) + (j - 32)];
    }
}

// ---------------- launch ----------------------------------------------------
extern "C" void kernel_launch(void* const* d_in, const int* in_sizes, int n_in,
                              void* d_out, int out_size) {
    const float* obj = (const float*)d_in[0];
    const float* Rs  = (const float*)d_in[1];
    const float* Rrm = (const float*)d_in[2];
    const float* rw1 = (const float*)d_in[3];  const float* rb1 = (const float*)d_in[4];
    const float* rw2 = (const float*)d_in[5];  const float* rb2 = (const float*)d_in[6];
    const float* rw3 = (const float*)d_in[7];  const float* rb3 = (const float*)d_in[8];
    const float* rw4 = (const float*)d_in[9];  const float* rb4 = (const float*)d_in[10];
    const float* ow1 = (const float*)d_in[11]; const float* ob1 = (const float*)d_in[12];
    const float* ow2 = (const float*)d_in[13]; const float* ob2 = (const float*)d_in[14];
    float* out = (float*)d_out;

    float *node, *bufA, *bufB, *agg2, *upd, *hobj, *objT;
    cudaGetSymbolAddress((void**)&node, g_node);
    cudaGetSymbolAddress((void**)&bufA, g_bufA);
    cudaGetSymbolAddress((void**)&bufB, g_bufB);
    cudaGetSymbolAddress((void**)&agg2, g_agg);
    cudaGetSymbolAddress((void**)&upd,  g_upd);
    cudaGetSymbolAddress((void**)&hobj, g_hobj);
    cudaGetSymbolAddress((void**)&objT, g_objT);

    // 0. pack obj into [1024, 256] (col = b*32+d)
    pack_objT_kernel<<<(N_ * 256 + 255) / 256, 256>>>(obj, objT);

    // 1. gathers as GEMMs: C[r, b*32+d] = sum_n R[n,r] * objT[n, b*32+d]
    mma_gemm<1, false, true><<<dim3(2, R_ / 128), 256>>>(
        Rs,  objT, nullptr, node, 256, R_, N_, 0);
    mma_gemm<1, false, true><<<dim3(2, R_ / 128), 256>>>(
        Rrm, objT, nullptr, node, 256, R_, N_, 32);

    // 2. relational MLP
    mma_gemm<0, true, false><<<dim3(HID_ / 128, MROWS / 128), 256>>>(
        node, rw1, rb1, bufA, HID_, 64, 64, 0);
    mma_gemm<0, true, false><<<dim3(HID_ / 128, MROWS / 128), 256>>>(
        bufA, rw2, rb2, bufB, HID_, HID_, HID_, 0);
    // fused rw3+rw4 -> edgeT[r, b*64+e] into g_node
    rw34_kernel<<<MROWS / 128, 128>>>(bufB, rw3, rb3, rw4, rb4, node);

    // 3. aggregate: agg2[n, b*64+e] = sum_r Rr[n,r] * edgeT[r, b*64+e] (split-K=8)
    zero_kernel<<<(N_ * 512 + 255) / 256, 256>>>(agg2, N_ * 512);
    mma_gemm<3, false, false><<<dim3(4, N_ / 128, 8), 256>>>(
        Rrm, node, nullptr, agg2, 512, R_, R_ / 8, 0);

    // 4. object MLP
    concat_kernel<<<(NROWS * 96 + 255) / 256, 256>>>(obj, agg2, upd);
    mma_gemm<0, true, false><<<dim3(HID_ / 128, NROWS / 128), 256>>>(
        upd, ow1, ob1, hobj, HID_, 96, 96, 0);
    gemm_kernel<128, 32, 8, 8, 2, false><<<dim3(1, NROWS / 128), 256>>>(
        hobj, ow2, ob2, out, NROWS, HID_, 32);
}

// round 8
// speedup vs baseline: 2.4545x; 2.4545x over previous
#include <cuda_runtime.h>
#include <cstdint>

// Problem dims
#define B_    8
#define N_    1024
#define R_    16384
#define DOBJ  32
#define DEFF  64
#define HID_  512
#define MROWS (B_ * R_)      // 131072
#define NROWS (B_ * N_)      // 8192

// ---------------- scratch (device globals; no allocations allowed) ----------
__device__ __align__(128) float g_node[MROWS * 64];    // node_obj; later edgeT [16384,512] (same size)
__device__ __align__(128) float g_bufA[MROWS * HID_];  // h1; later h3 [.,64] at front
__device__ __align__(128) float g_bufB[MROWS * HID_];  // h2
__device__ __align__(128) float g_agg [N_ * 512];      // agg2 [1024, 512]  (col = b*64+e)
__device__ __align__(128) float g_upd [NROWS * 96];    // update_node [8192,96]
__device__ __align__(128) float g_hobj[NROWS * HID_];  // object hidden [8192,512]
__device__ __align__(128) float g_objT[N_ * 256];      // objT [1024, 256]  (col = b*32+d)

// ---------------- helpers ----------------------------------------------------
__device__ __forceinline__ float f2tf(float x) {
    uint32_t u;
    asm("cvt.rna.tf32.f32 %0, %1;" : "=r"(u) : "f"(x));
    return __uint_as_float(u);
}

__device__ __forceinline__ void mma_tf32(float d[4], const uint32_t a[4], const uint32_t b[2]) {
    asm volatile(
        "mma.sync.aligned.m16n8k8.row.col.f32.tf32.tf32.f32 "
        "{%0,%1,%2,%3},{%4,%5,%6,%7},{%8,%9},{%0,%1,%2,%3};\n"
        : "+f"(d[0]), "+f"(d[1]), "+f"(d[2]), "+f"(d[3])
        : "r"(a[0]), "r"(a[1]), "r"(a[2]), "r"(a[3]), "r"(b[0]), "r"(b[1]));
}

// MODE: 0 = C[row*N+col]=bias+act  1 = gather-scatter to node  2 = edgeT store  3 = split-K atomic
template<int MODE, bool RELU>
__device__ __forceinline__ void store_one(float* __restrict__ C, const float* __restrict__ bias,
                                          int row, int col, int N, int off, float v) {
    if (MODE == 0) {
        v += bias[col]; if (RELU) v = fmaxf(v, 0.f);
        C[(size_t)row * N + col] = v;
    } else if (MODE == 1) {
        int b = col >> 5, d = col & 31;
        C[(((size_t)b << 14) + row) * 64 + off + d] = v;
    } else if (MODE == 2) {
        v += bias[col]; if (RELU) v = fmaxf(v, 0.f);
        int b = row >> 14, r = row & 16383;
        C[(size_t)r * 512 + (b << 6) + col] = v;
    } else {
        atomicAdd(&C[(size_t)row * N + col], v);
    }
}

// ---------------- tf32 tensor-core GEMM: C = act(A[M,K] @ W[K,N] + bias) -----
// ATRANS: A physically stored [K][M] with row stride lda (used for Rs^T / Rr^T gathers).
// blockIdx.z * klen gives the K-range start (split-K for MODE 3).
// Double-buffered smem, ONE __syncthreads per K-tile:
//   iter t: g2r(t+1) -> compute(st) -> r2s(st^1) -> sync
// Writes target the buffer whose readers were fenced by the previous barrier.
template<int BM, int BN, int MODE, bool RELU, bool ATRANS>
__global__ __launch_bounds__((BM/64)*(BN/32)*32, 2) void mma_gemm(
    const float* __restrict__ A, const float* __restrict__ W,
    const float* __restrict__ bias, float* __restrict__ C,
    int K, int N, int lda, int klen, int off)
{
    constexpr int BK = 16;
    constexpr int NW_N = BN / 32;
    constexpr int THREADS = (BM/64) * (BN/32) * 32;
    constexpr int AELT = BM * BK / (THREADS * 4);   // float4 per thread for A
    constexpr int BELT = BN * BK / (THREADS * 4);
    __shared__ float Asm[2][BK][BM + 8];
    __shared__ float Wsm[2][BK][BN + 8];

    const int tid = threadIdx.x, lane = tid & 31, wid = tid >> 5;
    const int wm = (wid / NW_N) * 64, wn = (wid % NW_N) * 32;
    const int row0 = blockIdx.y * BM, col0 = blockIdx.x * BN;
    const int kstart = blockIdx.z * klen;
    const int ntiles = klen / BK;

    float acc[4][4][4];
    #pragma unroll
    for (int mi = 0; mi < 4; mi++)
        #pragma unroll
        for (int ni = 0; ni < 4; ni++)
            #pragma unroll
            for (int j = 0; j < 4; j++) acc[mi][ni][j] = 0.f;

    float4 apre[AELT], bpre[BELT];

    auto g2r = [&](int kk) {
        #pragma unroll
        for (int p = 0; p < AELT; p++) {
            int i = tid * 4 + p * THREADS * 4;
            if (!ATRANS) {
                int r = i / BK, c = i % BK;
                apre[p] = *(const float4*)&A[(size_t)(row0 + r) * lda + kk + c];
            } else {
                int k = i / BM, m = i % BM;
                apre[p] = *(const float4*)&A[(size_t)(kk + k) * lda + row0 + m];
            }
        }
        #pragma unroll
        for (int p = 0; p < BELT; p++) {
            int i = tid * 4 + p * THREADS * 4;
            int kw = i / BN, n = i % BN;
            bpre[p] = *(const float4*)&W[(size_t)(kk + kw) * N + col0 + n];
        }
    };
    auto r2s = [&](int st) {
        #pragma unroll
        for (int p = 0; p < AELT; p++) {
            int i = tid * 4 + p * THREADS * 4;
            if (!ATRANS) {
                int r = i / BK, c = i % BK;
                Asm[st][c + 0][r] = f2tf(apre[p].x);
                Asm[st][c + 1][r] = f2tf(apre[p].y);
                Asm[st][c + 2][r] = f2tf(apre[p].z);
                Asm[st][c + 3][r] = f2tf(apre[p].w);
            } else {
                int k = i / BM, m = i % BM;
                Asm[st][k][m + 0] = f2tf(apre[p].x);
                Asm[st][k][m + 1] = f2tf(apre[p].y);
                Asm[st][k][m + 2] = f2tf(apre[p].z);
                Asm[st][k][m + 3] = f2tf(apre[p].w);
            }
        }
        #pragma unroll
        for (int p = 0; p < BELT; p++) {
            int i = tid * 4 + p * THREADS * 4;
            int kw = i / BN, n = i % BN;
            Wsm[st][kw][n + 0] = f2tf(bpre[p].x);
            Wsm[st][kw][n + 1] = f2tf(bpre[p].y);
            Wsm[st][kw][n + 2] = f2tf(bpre[p].z);
            Wsm[st][kw][n + 3] = f2tf(bpre[p].w);
        }
    };

    g2r(kstart);
    r2s(0);
    __syncthreads();

    const int lc = lane & 3, lg = lane >> 2;
    for (int t = 0; t < ntiles; t++) {
        const int st = t & 1;
        if (t + 1 < ntiles) g2r(kstart + (t + 1) * BK);
        #pragma unroll
        for (int s = 0; s < 2; s++) {
            const int k = s * 8;
            uint32_t a[4][4], b[4][2];
            #pragma unroll
            for (int mi = 0; mi < 4; mi++) {
                int mb = wm + mi * 16 + lg;
                a[mi][0] = __float_as_uint(Asm[st][k + lc][mb]);
                a[mi][1] = __float_as_uint(Asm[st][k + lc][mb + 8]);
                a[mi][2] = __float_as_uint(Asm[st][k + lc + 4][mb]);
                a[mi][3] = __float_as_uint(Asm[st][k + lc + 4][mb + 8]);
            }
            #pragma unroll
            for (int ni = 0; ni < 4; ni++) {
                int nb = wn + ni * 8 + lg;
                b[ni][0] = __float_as_uint(Wsm[st][k + lc][nb]);
                b[ni][1] = __float_as_uint(Wsm[st][k + lc + 4][nb]);
            }
            #pragma unroll
            for (int mi = 0; mi < 4; mi++)
                #pragma unroll
                for (int ni = 0; ni < 4; ni++)
                    mma_tf32(acc[mi][ni], a[mi], b[ni]);
        }
        if (t + 1 < ntiles) r2s(st ^ 1);
        __syncthreads();
    }

    // epilogue
    #pragma unroll
    for (int mi = 0; mi < 4; mi++) {
        int r0 = row0 + wm + mi * 16 + lg;
        #pragma unroll
        for (int ni = 0; ni < 4; ni++) {
            int c0 = col0 + wn + ni * 8 + lc * 2;
            store_one<MODE, RELU>(C, bias, r0,     c0,     N, off, acc[mi][ni][0]);
            store_one<MODE, RELU>(C, bias, r0,     c0 + 1, N, off, acc[mi][ni][1]);
            store_one<MODE, RELU>(C, bias, r0 + 8, c0,     N, off, acc[mi][ni][2]);
            store_one<MODE, RELU>(C, bias, r0 + 8, c0 + 1, N, off, acc[mi][ni][3]);
        }
    }
}

// ---------------- SIMT fp32 GEMM (kept for the tiny final layer) -------------
template<int BM, int BN, int BK, int TM, int TN, bool RELU>
__global__ __launch_bounds__((BM/TM)*(BN/TN)) void gemm_kernel(
    const float* __restrict__ A, const float* __restrict__ W,
    const float* __restrict__ bias, float* __restrict__ C,
    int M, int K, int N)
{
    __shared__ float As[BK][BM];
    __shared__ float Ws[BK][BN];
    const int nthr = (BM / TM) * (BN / TN);
    const int tid = threadIdx.x;
    const int tn = tid % (BN / TN);
    const int tm = tid / (BN / TN);
    const int row0 = blockIdx.y * BM;
    const int col0 = blockIdx.x * BN;

    float acc[TM][TN];
    #pragma unroll
    for (int m = 0; m < TM; m++)
        #pragma unroll
        for (int n = 0; n < TN; n++) acc[m][n] = 0.f;

    for (int k0 = 0; k0 < K; k0 += BK) {
        #pragma unroll
        for (int i = tid * 4; i < BM * BK; i += nthr * 4) {
            int r = i / BK, c = i % BK;
            float4 v = *(const float4*)&A[(size_t)(row0 + r) * K + k0 + c];
            As[c + 0][r] = v.x; As[c + 1][r] = v.y;
            As[c + 2][r] = v.z; As[c + 3][r] = v.w;
        }
        #pragma unroll
        for (int i = tid * 4; i < BK * BN; i += nthr * 4) {
            int r = i / BN, c = i % BN;
            *(float4*)&Ws[r][c] = *(const float4*)&W[(size_t)(k0 + r) * N + col0 + c];
        }
        __syncthreads();
        #pragma unroll
        for (int k = 0; k < BK; k++) {
            float a[TM], b[TN];
            #pragma unroll
            for (int m = 0; m < TM; m++) a[m] = As[k][tm * TM + m];
            #pragma unroll
            for (int n = 0; n < TN; n++) b[n] = Ws[k][tn * TN + n];
            #pragma unroll
            for (int m = 0; m < TM; m++)
                #pragma unroll
                for (int n = 0; n < TN; n++) acc[m][n] += a[m] * b[n];
        }
        __syncthreads();
    }
    #pragma unroll
    for (int m = 0; m < TM; m++) {
        int row = row0 + tm * TM + m;
        #pragma unroll
        for (int n = 0; n < TN; n++) {
            int col = col0 + tn * TN + n;
            float v = acc[m][n] + bias[col];
            if (RELU) v = fmaxf(v, 0.f);
            C[(size_t)row * N + col] = v;
        }
    }
}

// ---------------- small utility kernels --------------------------------------
__global__ void pack_objT_kernel(const float* __restrict__ obj, float* __restrict__ objT) {
    int i = blockIdx.x * blockDim.x + threadIdx.x;   // over 1024*256
    if (i < N_ * 256) {
        int n = i >> 8, c = i & 255;          // c = b*32+d
        int b = c >> 5, d = c & 31;
        objT[i] = obj[((size_t)b * N_ + n) * 32 + d];
    }
}

__global__ void zero_kernel(float* p, int n) {
    int i = blockIdx.x * blockDim.x + threadIdx.x;
    if (i < n) p[i] = 0.f;
}

__global__ void concat_kernel(const float* __restrict__ obj,
                              const float* __restrict__ agg2,   // [1024, 512], col=b*64+e
                              float* __restrict__ upd) {        // [8192, 96]
    int i = blockIdx.x * blockDim.x + threadIdx.x;
    if (i < NROWS * 96) {
        int row = i / 96, j = i % 96;
        int b = row >> 10, n = row & 1023;
        upd[i] = (j < 32) ? obj[(size_t)row * 32 + j]
                          : agg2[(size_t)n * 512 + (b << 6) + (j - 32)];
    }
}

// ---------------- launch ----------------------------------------------------
extern "C" void kernel_launch(void* const* d_in, const int* in_sizes, int n_in,
                              void* d_out, int out_size) {
    const float* obj = (const float*)d_in[0];
    const float* Rs  = (const float*)d_in[1];
    const float* Rrm = (const float*)d_in[2];
    const float* rw1 = (const float*)d_in[3];  const float* rb1 = (const float*)d_in[4];
    const float* rw2 = (const float*)d_in[5];  const float* rb2 = (const float*)d_in[6];
    const float* rw3 = (const float*)d_in[7];  const float* rb3 = (const float*)d_in[8];
    const float* rw4 = (const float*)d_in[9];  const float* rb4 = (const float*)d_in[10];
    const float* ow1 = (const float*)d_in[11]; const float* ob1 = (const float*)d_in[12];
    const float* ow2 = (const float*)d_in[13]; const float* ob2 = (const float*)d_in[14];
    float* out = (float*)d_out;

    float *node, *bufA, *bufB, *agg2, *upd, *hobj, *objT;
    cudaGetSymbolAddress((void**)&node, g_node);
    cudaGetSymbolAddress((void**)&bufA, g_bufA);
    cudaGetSymbolAddress((void**)&bufB, g_bufB);
    cudaGetSymbolAddress((void**)&agg2, g_agg);
    cudaGetSymbolAddress((void**)&upd,  g_upd);
    cudaGetSymbolAddress((void**)&hobj, g_hobj);
    cudaGetSymbolAddress((void**)&objT, g_objT);

    // 0. pack obj into [1024, 256] (col = b*32+d)
    pack_objT_kernel<<<(N_ * 256 + 255) / 256, 256>>>(obj, objT);

    // 1. gathers as GEMMs: C[r, b*32+d] = sum_n R[n,r] * objT[n, b*32+d]
    //    A = R^T (ATRANS, lda = R_), scatter epilogue into node[b,r,64]
    mma_gemm<128, 128, 1, false, true><<<dim3(2, R_ / 128), 256>>>(
        Rs,  objT, nullptr, node, N_, 256, R_, N_, 0);
    mma_gemm<128, 128, 1, false, true><<<dim3(2, R_ / 128), 256>>>(
        Rrm, objT, nullptr, node, N_, 256, R_, N_, 32);

    // 2. relational MLP (tf32 tensor cores)
    mma_gemm<128, 128, 0, true, false><<<dim3(HID_ / 128, MROWS / 128), 256>>>(
        node, rw1, rb1, bufA, 64, HID_, 64, 64, 0);
    mma_gemm<128, 128, 0, true, false><<<dim3(HID_ / 128, MROWS / 128), 256>>>(
        bufA, rw2, rb2, bufB, HID_, HID_, HID_, HID_, 0);
    mma_gemm<128, 64, 0, true, false><<<dim3(1, MROWS / 128), 128>>>(
        bufB, rw3, rb3, bufA, HID_, 64, HID_, HID_, 0);
    // layer4 writes transposed edge layout edgeT[r, b*64+e] into g_node (same size)
    mma_gemm<128, 64, 2, true, false><<<dim3(1, MROWS / 128), 128>>>(
        bufA, rw4, rb4, node, 64, 64, 64, 64, 0);

    // 3. aggregate: agg2[n, b*64+e] = sum_r Rr[n,r] * edgeT[r, b*64+e]  (split-K=8, atomic)
    zero_kernel<<<(N_ * 512 + 255) / 256, 256>>>(agg2, N_ * 512);
    mma_gemm<128, 128, 3, false, false><<<dim3(4, N_ / 128, 8), 256>>>(
        Rrm, node, nullptr, agg2, R_, 512, R_, R_ / 8, 0);

    // 4. object MLP
    concat_kernel<<<(NROWS * 96 + 255) / 256, 256>>>(obj, agg2, upd);
    mma_gemm<128, 128, 0, true, false><<<dim3(HID_ / 128, NROWS / 128), 256>>>(
        upd, ow1, ob1, hobj, 96, HID_, 96, 96, 0);
    // final tiny layer in exact fp32 SIMT (keeps output precision)
    gemm_kernel<128, 32, 8, 8, 2, false><<<dim3(1, NROWS / 128), 256>>>(
        hobj, ow2, ob2, out, NROWS, HID_, 32);
}

// round 9
// speedup vs baseline: 3.8178x; 1.5555x over previous
#include <cuda_runtime.h>
#include <cuda_fp16.h>
#include <cstdint>

// Problem dims
#define B_    8
#define N_    1024
#define R_    16384
#define HID_  512
#define MROWS (B_ * R_)      // 131072
#define NROWS (B_ * N_)      // 8192

// ---------------- scratch (device globals; no allocations allowed) ----------
__device__ __align__(128) __half gh_RsT [R_ * N_];      // Rs^T fp16 [16384,1024]
__device__ __align__(128) __half gh_RrT [R_ * N_];      // Rr^T fp16 [16384,1024]
__device__ __align__(128) __half gh_Rr  [N_ * R_];      // Rr fp16 [1024,16384]
__device__ __align__(128) __half gh_objT[N_ * 256];     // objT fp16 [1024,256] col=b*32+d
__device__ __align__(128) __half gh_node[MROWS * 64];   // node fp16 [131072,64]
__device__ __align__(128) __half gh_h1  [MROWS * HID_]; // h1 fp16
__device__ __align__(128) __half gh_h2  [MROWS * HID_]; // h2 fp16
__device__ __align__(128) __half gh_h3  [MROWS * 64];   // h3 fp16
__device__ __align__(128) __half gh_edgeT[R_ * 512];    // edgeT fp16 [16384,512] col=b*64+e
__device__ __align__(128) __half gh_upd [NROWS * 96];   // upd fp16 [8192,96]
__device__ __align__(128) float  g_agg  [N_ * 512];     // agg fp32 [1024,512] col=b*64+e
__device__ __align__(128) float  g_hobj [NROWS * HID_]; // hobj fp32 [8192,512]

// ---------------- fp16 MMA m16n8k16 ------------------------------------------
__device__ __forceinline__ void mma_f16(float d[4], uint32_t a0, uint32_t a1,
                                        uint32_t a2, uint32_t a3,
                                        uint32_t b0, uint32_t b1) {
    asm volatile(
        "mma.sync.aligned.m16n8k16.row.col.f32.f16.f16.f32 "
        "{%0,%1,%2,%3},{%4,%5,%6,%7},{%8,%9},{%0,%1,%2,%3};\n"
        : "+f"(d[0]), "+f"(d[1]), "+f"(d[2]), "+f"(d[3])
        : "r"(a0), "r"(a1), "r"(a2), "r"(a3), "r"(b0), "r"(b1));
}

// m-interleave: m -> ((m>>4)<<4) | ((m&7)<<1) | ((m>>3)&1)  (m, m+8 adjacent)
__device__ __forceinline__ int mperm(int m) {
    return ((m >> 4) << 4) | ((m & 7) << 1) | ((m >> 3) & 1);
}

// ---------------- fp16 tensor-core GEMM --------------------------------------
// A: fp16 [M][K] row-major (lda halfs). W: fp32 [K][N] or fp16 [K][N] (BH).
// MODE: 0 = fp16 out  1 = gather-scatter fp16 node  2 = edgeT fp16  3 = atomic fp32  4 = fp32 out
template<int BM, int BN, int MODE, bool RELU, bool BH>
__global__ __launch_bounds__((BM/64)*(BN/32)*32, 2) void hmma_gemm(
    const __half* __restrict__ A, const void* __restrict__ W,
    const float* __restrict__ bias, void* __restrict__ C,
    int N, int lda, int klen, int off)
{
    constexpr int BK = 16;
    constexpr int NW_N = BN / 32;
    constexpr int THREADS = (BM/64) * NW_N * 32;
    constexpr int AELT = BM * BK / (THREADS * 4);   // uint2 loads per thread
    // smem in half2 units
    __shared__ uint32_t Ah[2][8][BM + 8];
    __shared__ uint32_t Bh[2][8][BN + 8];

    const int tid = threadIdx.x, lane = tid & 31, wid = tid >> 5;
    const int wm = (wid / NW_N) * 64, wn = (wid % NW_N) * 32;
    const int row0 = blockIdx.y * BM, col0 = blockIdx.x * BN;
    const int kstart = blockIdx.z * klen;
    const int ntiles = klen / BK;
    const int lc = lane & 3, lg = lane >> 2;

    float acc[4][4][4];
    #pragma unroll
    for (int mi = 0; mi < 4; mi++)
        #pragma unroll
        for (int ni = 0; ni < 4; ni++)
            #pragma unroll
            for (int j = 0; j < 4; j++) acc[mi][ni][j] = 0.f;

    uint2 apre[AELT];
    float4 bra_f, brb_f;      // fp32 W rows k, k+1
    uint2  bra_h, brb_h;      // fp16 W rows k, k+1
    const int bj = tid * 4;                 // index over 8 x BN half2 grid
    const int bk2 = bj / BN, bn = bj % BN;

    auto g2r = [&](int kk) {
        #pragma unroll
        for (int p = 0; p < AELT; p++) {
            int i = tid * 4 + p * THREADS * 4;
            int r = i >> 4, c = i & 15;
            apre[p] = *(const uint2*)&A[(size_t)(row0 + r) * lda + kk + c];
        }
        if (BH) {
            const __half* Wh = (const __half*)W;
            bra_h = *(const uint2*)&Wh[(size_t)(kk + 2 * bk2)     * N + col0 + bn];
            brb_h = *(const uint2*)&Wh[(size_t)(kk + 2 * bk2 + 1) * N + col0 + bn];
        } else {
            const float* Wf = (const float*)W;
            bra_f = *(const float4*)&Wf[(size_t)(kk + 2 * bk2)     * N + col0 + bn];
            brb_f = *(const float4*)&Wf[(size_t)(kk + 2 * bk2 + 1) * N + col0 + bn];
        }
    };
    auto r2s = [&](int st) {
        #pragma unroll
        for (int p = 0; p < AELT; p++) {
            int i = tid * 4 + p * THREADS * 4;
            int r = i >> 4, c = i & 15;
            int mp = mperm(r);
            Ah[st][(c >> 1)][mp]     = apre[p].x;   // halfs c, c+1
            Ah[st][(c >> 1) + 1][mp] = apre[p].y;   // halfs c+2, c+3
        }
        uint32_t z0, z1, z2, z3;
        if (BH) {
            z0 = __byte_perm(bra_h.x, brb_h.x, 0x5410);
            z1 = __byte_perm(bra_h.x, brb_h.x, 0x7632);
            z2 = __byte_perm(bra_h.y, brb_h.y, 0x5410);
            z3 = __byte_perm(bra_h.y, brb_h.y, 0x7632);
        } else {
            z0 = __half2_raw(__floats2half2_rn(bra_f.x, brb_f.x)).x | ((uint32_t)__half2_raw(__floats2half2_rn(bra_f.x, brb_f.x)).y << 16);
            // (use direct reinterpret instead)
            __half2 h0 = __floats2half2_rn(bra_f.x, brb_f.x);
            __half2 h1 = __floats2half2_rn(bra_f.y, brb_f.y);
            __half2 h2 = __floats2half2_rn(bra_f.z, brb_f.z);
            __half2 h3 = __floats2half2_rn(bra_f.w, brb_f.w);
            z0 = *(uint32_t*)&h0; z1 = *(uint32_t*)&h1;
            z2 = *(uint32_t*)&h2; z3 = *(uint32_t*)&h3;
        }
        *(uint4*)&Bh[st][bk2][bn] = make_uint4(z0, z1, z2, z3);
    };

    g2r(kstart);
    r2s(0);
    __syncthreads();

    for (int t = 0; t < ntiles; t++) {
        const int st = t & 1;
        if (t + 1 < ntiles) g2r(kstart + (t + 1) * BK);
        #pragma unroll
        for (int mi = 0; mi < 4; mi++) {
            const int ac = wm + mi * 16 + lg * 2;
            uint2 a01 = *(const uint2*)&Ah[st][lc][ac];
            uint2 a23 = *(const uint2*)&Ah[st][lc + 4][ac];
            #pragma unroll
            for (int ni = 0; ni < 4; ni++) {
                const int bc = wn + ni * 8 + lg;
                mma_f16(acc[mi][ni], a01.x, a01.y, a23.x, a23.y,
                        Bh[st][lc][bc], Bh[st][lc + 4][bc]);
            }
        }
        if (t + 1 < ntiles) r2s(st ^ 1);
        __syncthreads();
    }

    // epilogue
    #pragma unroll
    for (int mi = 0; mi < 4; mi++) {
        int r0 = row0 + wm + mi * 16 + lg;
        #pragma unroll
        for (int ni = 0; ni < 4; ni++) {
            int c0 = col0 + wn + ni * 8 + lc * 2;
            #pragma unroll
            for (int h = 0; h < 2; h++) {
                int row = r0 + h * 8;
                float v0 = acc[mi][ni][h * 2 + 0];
                float v1 = acc[mi][ni][h * 2 + 1];
                if (MODE == 0 || MODE == 2 || MODE == 4) {
                    v0 += bias[c0]; v1 += bias[c0 + 1];
                    if (RELU) { v0 = fmaxf(v0, 0.f); v1 = fmaxf(v1, 0.f); }
                }
                if (MODE == 0) {
                    __half2 hv = __floats2half2_rn(v0, v1);
                    *(__half2*)&((__half*)C)[(size_t)row * N + c0] = hv;
                } else if (MODE == 1) {
                    int b = c0 >> 5, d = c0 & 31;
                    __half2 hv = __floats2half2_rn(v0, v1);
                    *(__half2*)&((__half*)C)[(((size_t)b << 14) + row) * 64 + off + d] = hv;
                } else if (MODE == 2) {
                    int b = row >> 14, r = row & 16383;
                    __half2 hv = __floats2half2_rn(v0, v1);
                    *(__half2*)&((__half*)C)[(size_t)r * 512 + (b << 6) + c0] = hv;
                } else if (MODE == 3) {
                    atomicAdd(&((float*)C)[(size_t)row * N + c0], v0);
                    atomicAdd(&((float*)C)[(size_t)row * N + c0 + 1], v1);
                } else {
                    ((float*)C)[(size_t)row * N + c0]     = v0;
                    ((float*)C)[(size_t)row * N + c0 + 1] = v1;
                }
            }
        }
    }
}

// ---------------- transpose+convert: RT_h[r][n] = (half)R[n][r]; opt Rh copy --
__global__ __launch_bounds__(256) void transpose_h_kernel(
    const float* __restrict__ R, __half* __restrict__ RT, __half* Rh)
{
    __shared__ __half sm[32][33];
    const int tx = threadIdx.x & 31, ty = threadIdx.x >> 5;
    const int rb = blockIdx.x * 32, nb = blockIdx.y * 32;
    #pragma unroll
    for (int j = 0; j < 4; j++) {
        int n = nb + ty + j * 8, r = rb + tx;
        __half h = __float2half_rn(R[(size_t)n * R_ + r]);
        if (Rh) Rh[(size_t)n * R_ + r] = h;
        sm[ty + j * 8][tx] = h;
    }
    __syncthreads();
    #pragma unroll
    for (int j = 0; j < 4; j++) {
        int r = rb + ty + j * 8, n = nb + tx;
        RT[(size_t)r * N_ + n] = sm[tx][ty + j * 8];
    }
}

// ---------------- small utility kernels --------------------------------------
__global__ void pack_objT_h_kernel(const float* __restrict__ obj, __half* __restrict__ objT) {
    int i = blockIdx.x * blockDim.x + threadIdx.x;
    if (i < N_ * 256) {
        int n = i >> 8, c = i & 255;
        int b = c >> 5, d = c & 31;
        objT[i] = __float2half_rn(obj[((size_t)b * N_ + n) * 32 + d]);
    }
}

__global__ void zero_kernel(float* p, int n) {
    int i = blockIdx.x * blockDim.x + threadIdx.x;
    if (i < n) p[i] = 0.f;
}

__global__ void concat_h_kernel(const float* __restrict__ obj,
                                const float* __restrict__ agg2,
                                __half* __restrict__ upd) {
    int i = blockIdx.x * blockDim.x + threadIdx.x;
    if (i < NROWS * 96) {
        int row = i / 96, j = i % 96;
        int b = row >> 10, n = row & 1023;
        float v = (j < 32) ? obj[(size_t)row * 32 + j]
                           : agg2[(size_t)n * 512 + (b << 6) + (j - 32)];
        upd[i] = __float2half_rn(v);
    }
}

// ---------------- SIMT fp32 GEMM (tiny final layer) --------------------------
template<int BM, int BN, int BK, int TM, int TN, bool RELU>
__global__ __launch_bounds__((BM/TM)*(BN/TN)) void gemm_kernel(
    const float* __restrict__ A, const float* __restrict__ W,
    const float* __restrict__ bias, float* __restrict__ C,
    int M, int K, int N)
{
    __shared__ float As[BK][BM];
    __shared__ float Ws[BK][BN];
    const int nthr = (BM / TM) * (BN / TN);
    const int tid = threadIdx.x;
    const int tn = tid % (BN / TN);
    const int tm = tid / (BN / TN);
    const int row0 = blockIdx.y * BM;
    const int col0 = blockIdx.x * BN;

    float acc[TM][TN];
    #pragma unroll
    for (int m = 0; m < TM; m++)
        #pragma unroll
        for (int n = 0; n < TN; n++) acc[m][n] = 0.f;

    for (int k0 = 0; k0 < K; k0 += BK) {
        #pragma unroll
        for (int i = tid * 4; i < BM * BK; i += nthr * 4) {
            int r = i / BK, c = i % BK;
            float4 v = *(const float4*)&A[(size_t)(row0 + r) * K + k0 + c];
            As[c + 0][r] = v.x; As[c + 1][r] = v.y;
            As[c + 2][r] = v.z; As[c + 3][r] = v.w;
        }
        #pragma unroll
        for (int i = tid * 4; i < BK * BN; i += nthr * 4) {
            int r = i / BN, c = i % BN;
            *(float4*)&Ws[r][c] = *(const float4*)&W[(size_t)(k0 + r) * N + col0 + c];
        }
        __syncthreads();
        #pragma unroll
        for (int k = 0; k < BK; k++) {
            float a[TM], b[TN];
            #pragma unroll
            for (int m = 0; m < TM; m++) a[m] = As[k][tm * TM + m];
            #pragma unroll
            for (int n = 0; n < TN; n++) b[n] = Ws[k][tn * TN + n];
            #pragma unroll
            for (int m = 0; m < TM; m++)
                #pragma unroll
                for (int n = 0; n < TN; n++) acc[m][n] += a[m] * b[n];
        }
        __syncthreads();
    }
    #pragma unroll
    for (int m = 0; m < TM; m++) {
        int row = row0 + tm * TM + m;
        #pragma unroll
        for (int n = 0; n < TN; n++) {
            int col = col0 + tn * TN + n;
            float v = acc[m][n] + bias[col];
            if (RELU) v = fmaxf(v, 0.f);
            C[(size_t)row * N + col] = v;
        }
    }
}

// ---------------- launch ----------------------------------------------------
extern "C" void kernel_launch(void* const* d_in, const int* in_sizes, int n_in,
                              void* d_out, int out_size) {
    const float* obj = (const float*)d_in[0];
    const float* Rs  = (const float*)d_in[1];
    const float* Rrm = (const float*)d_in[2];
    const float* rw1 = (const float*)d_in[3];  const float* rb1 = (const float*)d_in[4];
    const float* rw2 = (const float*)d_in[5];  const float* rb2 = (const float*)d_in[6];
    const float* rw3 = (const float*)d_in[7];  const float* rb3 = (const float*)d_in[8];
    const float* rw4 = (const float*)d_in[9];  const float* rb4 = (const float*)d_in[10];
    const float* ow1 = (const float*)d_in[11]; const float* ob1 = (const float*)d_in[12];
    const float* ow2 = (const float*)d_in[13]; const float* ob2 = (const float*)d_in[14];
    float* out = (float*)d_out;

    __half *RsT, *RrT, *Rrh, *objT, *node, *h1, *h2, *h3, *edgeT, *upd;
    float *agg2, *hobj;
    cudaGetSymbolAddress((void**)&RsT,  gh_RsT);
    cudaGetSymbolAddress((void**)&RrT,  gh_RrT);
    cudaGetSymbolAddress((void**)&Rrh,  gh_Rr);
    cudaGetSymbolAddress((void**)&objT, gh_objT);
    cudaGetSymbolAddress((void**)&node, gh_node);
    cudaGetSymbolAddress((void**)&h1,   gh_h1);
    cudaGetSymbolAddress((void**)&h2,   gh_h2);
    cudaGetSymbolAddress((void**)&h3,   gh_h3);
    cudaGetSymbolAddress((void**)&edgeT,gh_edgeT);
    cudaGetSymbolAddress((void**)&upd,  gh_upd);
    cudaGetSymbolAddress((void**)&agg2, g_agg);
    cudaGetSymbolAddress((void**)&hobj, g_hobj);

    // 0. convert/transpose R matrices + pack obj
    transpose_h_kernel<<<dim3(R_ / 32, N_ / 32), 256>>>(Rs,  RsT, nullptr);
    transpose_h_kernel<<<dim3(R_ / 32, N_ / 32), 256>>>(Rrm, RrT, Rrh);
    pack_objT_h_kernel<<<(N_ * 256 + 255) / 256, 256>>>(obj, objT);

    // 1. gathers: node[b,r,off+d] = sum_n RT[r,n] * objT[n, b*32+d]
    hmma_gemm<128, 128, 1, false, true><<<dim3(2, R_ / 128), 256>>>(
        RsT, objT, nullptr, node, 256, N_, N_, 0);
    hmma_gemm<128, 128, 1, false, true><<<dim3(2, R_ / 128), 256>>>(
        RrT, objT, nullptr, node, 256, N_, N_, 32);

    // 2. relational MLP (fp16 tensor cores, fp32 accum)
    hmma_gemm<128, 128, 0, true, false><<<dim3(HID_ / 128, MROWS / 128), 256>>>(
        node, rw1, rb1, h1, HID_, 64, 64, 0);
    hmma_gemm<128, 128, 0, true, false><<<dim3(HID_ / 128, MROWS / 128), 256>>>(
        h1, rw2, rb2, h2, HID_, HID_, HID_, 0);
    hmma_gemm<128, 64, 0, true, false><<<dim3(1, MROWS / 128), 128>>>(
        h2, rw3, rb3, h3, 64, HID_, HID_, 0);
    hmma_gemm<128, 64, 2, true, false><<<dim3(1, MROWS / 128), 128>>>(
        h3, rw4, rb4, edgeT, 64, 64, 64, 0);

    // 3. aggregate: agg2[n, b*64+e] = sum_r Rr[n,r] * edgeT[r, b*64+e] (split-K=8)
    zero_kernel<<<(N_ * 512 + 255) / 256, 256>>>(agg2, N_ * 512);
    hmma_gemm<128, 128, 3, false, true><<<dim3(4, N_ / 128, 8), 256>>>(
        Rrh, edgeT, nullptr, agg2, 512, R_, R_ / 8, 0);

    // 4. object MLP
    concat_h_kernel<<<(NROWS * 96 + 255) / 256, 256>>>(obj, agg2, upd);
    hmma_gemm<128, 128, 4, true, false><<<dim3(HID_ / 128, NROWS / 128), 256>>>(
        upd, ow1, ob1, hobj, HID_, 96, 96, 0);
    gemm_kernel<128, 32, 8, 8, 2, false><<<dim3(1, NROWS / 128), 256>>>(
        hobj, ow2, ob2, out, NROWS, HID_, 32);
}

// round 10
// speedup vs baseline: 5.4277x; 1.4217x over previous
#include <cuda_runtime.h>
#include <cuda_fp16.h>
#include <cstdint>

// Problem dims
#define B_    8
#define N_    1024
#define R_    16384
#define HID_  512
#define MROWS (B_ * R_)      // 131072
#define NROWS (B_ * N_)      // 8192

// ---------------- scratch (device globals; no allocations allowed) ----------
__device__ __align__(128) __half gh_RsT [R_ * N_];      // Rs^T fp16 [16384,1024]
__device__ __align__(128) __half gh_RrT [R_ * N_];      // Rr^T fp16 [16384,1024]
__device__ __align__(128) __half gh_Rr  [N_ * R_];      // Rr fp16 [1024,16384]
__device__ __align__(128) __half gh_objT[N_ * 256];     // objT fp16 [1024,256] col=b*32+d
__device__ __align__(128) __half gh_node[MROWS * 64];   // node fp16
__device__ __align__(128) __half gh_h1  [MROWS * HID_];
__device__ __align__(128) __half gh_h2  [MROWS * HID_];
__device__ __align__(128) __half gh_h3  [MROWS * 64];
__device__ __align__(128) __half gh_edgeT[R_ * 512];    // edgeT fp16 [16384,512] col=b*64+e
__device__ __align__(128) __half gh_upd [NROWS * 96];
__device__ __align__(128) float  g_agg  [N_ * 512];     // agg fp32 [1024,512]
__device__ __align__(128) float  g_hobj [NROWS * HID_];
// fp16 weights
__device__ __align__(128) __half gh_w1[64 * HID_];
__device__ __align__(128) __half gh_w2[HID_ * HID_];
__device__ __align__(128) __half gh_w3[HID_ * 64];
__device__ __align__(128) __half gh_w4[64 * 64];
__device__ __align__(128) __half gh_o1[96 * HID_];

// ---------------- asm helpers ------------------------------------------------
__device__ __forceinline__ void mma_f16(float d[4], uint32_t a0, uint32_t a1,
                                        uint32_t a2, uint32_t a3,
                                        uint32_t b0, uint32_t b1) {
    asm volatile(
        "mma.sync.aligned.m16n8k16.row.col.f32.f16.f16.f32 "
        "{%0,%1,%2,%3},{%4,%5,%6,%7},{%8,%9},{%0,%1,%2,%3};\n"
        : "+f"(d[0]), "+f"(d[1]), "+f"(d[2]), "+f"(d[3])
        : "r"(a0), "r"(a1), "r"(a2), "r"(a3), "r"(b0), "r"(b1));
}
__device__ __forceinline__ void ldsm_x4(uint32_t r[4], uint32_t addr) {
    asm volatile("ldmatrix.sync.aligned.m8n8.x4.shared.b16 {%0,%1,%2,%3}, [%4];"
                 : "=r"(r[0]), "=r"(r[1]), "=r"(r[2]), "=r"(r[3]) : "r"(addr));
}
__device__ __forceinline__ void ldsm_x4_t(uint32_t r[4], uint32_t addr) {
    asm volatile("ldmatrix.sync.aligned.m8n8.x4.trans.shared.b16 {%0,%1,%2,%3}, [%4];"
                 : "=r"(r[0]), "=r"(r[1]), "=r"(r[2]), "=r"(r[3]) : "r"(addr));
}
#define CP16(dst, src) \
    asm volatile("cp.async.cg.shared.global [%0], [%1], 16;" :: "r"(dst), "l"(src))
#define CP_COMMIT() asm volatile("cp.async.commit_group;")
#define CP_WAIT(n)  asm volatile("cp.async.wait_group %0;" :: "n"(n))

// ---------------- fp16 cp.async + ldmatrix GEMM ------------------------------
// A fp16 [M][lda], W fp16 [K][N], both row-major. BK=32 halfs, 3 stages.
// MODE: 0 = fp16 out  1 = gather-scatter fp16 node  2 = edgeT fp16  3 = atomic fp32  4 = fp32 out
template<int BM, int BN, int MODE, bool RELU>
__global__ __launch_bounds__((BM/64)*(BN/32)*32, 2) void hmma_gemm(
    const __half* __restrict__ A, const __half* __restrict__ W,
    const float* __restrict__ bias, void* __restrict__ C,
    int N, int lda, int klen, int off)
{
    constexpr int BK = 32, STAGES = 3;
    constexpr int NW_N = BN / 32;
    constexpr int THREADS = (BM/64) * NW_N * 32;
    constexpr int ACH = BM * 4;           // 16B chunks in A tile
    constexpr int BCHR = BN / 8;          // chunks per B row
    constexpr int BCH = BK * BCHR;
    constexpr int APT = ACH / THREADS, BPT = BCH / THREADS;
    __shared__ __half Asm[STAGES][BM * BK];
    __shared__ __half Bsm[STAGES][BK * BN];

    const int tid = threadIdx.x, lane = tid & 31, wid = tid >> 5;
    const int wm = (wid / NW_N) * 64, wn = (wid % NW_N) * 32;
    const int row0 = blockIdx.y * BM, col0 = blockIdx.x * BN;
    const int kstart = blockIdx.z * klen;
    const int ntiles = klen / BK;

    const uint32_t a_s0 = (uint32_t)__cvta_generic_to_shared(&Asm[0][0]);
    const uint32_t b_s0 = (uint32_t)__cvta_generic_to_shared(&Bsm[0][0]);

    float acc[4][4][4];
    #pragma unroll
    for (int mi = 0; mi < 4; mi++)
        #pragma unroll
        for (int ni = 0; ni < 4; ni++)
            #pragma unroll
            for (int j = 0; j < 4; j++) acc[mi][ni][j] = 0.f;

    auto stage_copy = [&](int t, int st) {
        if (t < ntiles) {
            const int kk = kstart + t * BK;
            #pragma unroll
            for (int p = 0; p < APT; p++) {
                int q = tid + p * THREADS;
                int r = q >> 2, c = q & 3;
                uint32_t dst = a_s0 + (uint32_t)(st * BM * BK + (r * 4 + (c ^ ((r >> 1) & 3))) * 8) * 2;
                CP16(dst, &A[(size_t)(row0 + r) * lda + kk + c * 8]);
            }
            #pragma unroll
            for (int p = 0; p < BPT; p++) {
                int q = tid + p * THREADS;
                int k = q / BCHR, c = q % BCHR;
                uint32_t dst = b_s0 + (uint32_t)(st * BK * BN + (k * BCHR + (c ^ (k & 7))) * 8) * 2;
                CP16(dst, &W[(size_t)(kk + k) * N + col0 + c * 8]);
            }
        }
        CP_COMMIT();
    };

    #pragma unroll
    for (int t = 0; t < STAGES - 1; t++) stage_copy(t, t);

    for (int t = 0; t < ntiles; t++) {
        CP_WAIT(STAGES - 2);
        __syncthreads();
        stage_copy(t + STAGES - 1, (t + STAGES - 1) % STAGES);
        const int st = t % STAGES;
        const uint32_t abase = a_s0 + (uint32_t)(st * BM * BK) * 2;
        const uint32_t bbase = b_s0 + (uint32_t)(st * BK * BN) * 2;
        #pragma unroll
        for (int s = 0; s < 2; s++) {
            uint32_t af[4][4], bf[2][4];
            #pragma unroll
            for (int mi = 0; mi < 4; mi++) {
                int r = wm + mi * 16 + (lane & 15);
                int c = s * 2 + (lane >> 4);
                ldsm_x4(af[mi], abase + (uint32_t)((r * 4 + (c ^ ((r >> 1) & 3))) * 16));
            }
            #pragma unroll
            for (int np = 0; np < 2; np++) {
                int k = s * 16 + (lane & 15);
                int c = (wn >> 3) + np * 2 + (lane >> 4);
                ldsm_x4_t(bf[np], bbase + (uint32_t)((k * BCHR + (c ^ (k & 7))) * 16));
            }
            #pragma unroll
            for (int mi = 0; mi < 4; mi++)
                #pragma unroll
                for (int ni = 0; ni < 4; ni++)
                    mma_f16(acc[mi][ni], af[mi][0], af[mi][1], af[mi][2], af[mi][3],
                            bf[ni >> 1][(ni & 1) * 2], bf[ni >> 1][(ni & 1) * 2 + 1]);
        }
    }

    // epilogue
    const int lc = lane & 3, lg = lane >> 2;
    #pragma unroll
    for (int mi = 0; mi < 4; mi++) {
        int r0 = row0 + wm + mi * 16 + lg;
        #pragma unroll
        for (int ni = 0; ni < 4; ni++) {
            int c0 = col0 + wn + ni * 8 + lc * 2;
            #pragma unroll
            for (int h = 0; h < 2; h++) {
                int row = r0 + h * 8;
                float v0 = acc[mi][ni][h * 2 + 0];
                float v1 = acc[mi][ni][h * 2 + 1];
                if (MODE == 0 || MODE == 2 || MODE == 4) {
                    v0 += bias[c0]; v1 += bias[c0 + 1];
                    if (RELU) { v0 = fmaxf(v0, 0.f); v1 = fmaxf(v1, 0.f); }
                }
                if (MODE == 0) {
                    *(__half2*)&((__half*)C)[(size_t)row * N + c0] = __floats2half2_rn(v0, v1);
                } else if (MODE == 1) {
                    int b = c0 >> 5, d = c0 & 31;
                    *(__half2*)&((__half*)C)[(((size_t)b << 14) + row) * 64 + off + d] =
                        __floats2half2_rn(v0, v1);
                } else if (MODE == 2) {
                    int b = row >> 14, r = row & 16383;
                    *(__half2*)&((__half*)C)[(size_t)r * 512 + (b << 6) + c0] =
                        __floats2half2_rn(v0, v1);
                } else if (MODE == 3) {
                    atomicAdd(&((float*)C)[(size_t)row * N + c0], v0);
                    atomicAdd(&((float*)C)[(size_t)row * N + c0 + 1], v1);
                } else {
                    ((float*)C)[(size_t)row * N + c0]     = v0;
                    ((float*)C)[(size_t)row * N + c0 + 1] = v1;
                }
            }
        }
    }
}

// ---------------- transpose+convert: RT_h[r][n] = (half)R[n][r]; opt Rh copy --
__global__ __launch_bounds__(256) void transpose_h_kernel(
    const float* __restrict__ R, __half* __restrict__ RT, __half* Rh)
{
    __shared__ __half sm[32][33];
    const int tx = threadIdx.x & 31, ty = threadIdx.x >> 5;
    const int rb = blockIdx.x * 32, nb = blockIdx.y * 32;
    #pragma unroll
    for (int j = 0; j < 4; j++) {
        int n = nb + ty + j * 8, r = rb + tx;
        __half h = __float2half_rn(R[(size_t)n * R_ + r]);
        if (Rh) Rh[(size_t)n * R_ + r] = h;
        sm[ty + j * 8][tx] = h;
    }
    __syncthreads();
    #pragma unroll
    for (int j = 0; j < 4; j++) {
        int r = rb + ty + j * 8, n = nb + tx;
        RT[(size_t)r * N_ + n] = sm[tx][ty + j * 8];
    }
}

// ---------------- small utility kernels --------------------------------------
__global__ void f2h_kernel(const float* __restrict__ src, __half* __restrict__ dst, int n) {
    int i = blockIdx.x * blockDim.x + threadIdx.x;
    if (i < n) dst[i] = __float2half_rn(src[i]);
}

__global__ void pack_objT_h_kernel(const float* __restrict__ obj, __half* __restrict__ objT) {
    int i = blockIdx.x * blockDim.x + threadIdx.x;
    if (i < N_ * 256) {
        int n = i >> 8, c = i & 255;
        int b = c >> 5, d = c & 31;
        objT[i] = __float2half_rn(obj[((size_t)b * N_ + n) * 32 + d]);
    }
}

__global__ void zero_kernel(float* p, int n) {
    int i = blockIdx.x * blockDim.x + threadIdx.x;
    if (i < n) p[i] = 0.f;
}

__global__ void concat_h_kernel(const float* __restrict__ obj,
                                const float* __restrict__ agg2,
                                __half* __restrict__ upd) {
    int i = blockIdx.x * blockDim.x + threadIdx.x;
    if (i < NROWS * 96) {
        int row = i / 96, j = i % 96;
        int b = row >> 10, n = row & 1023;
        float v = (j < 32) ? obj[(size_t)row * 32 + j]
                           : agg2[(size_t)n * 512 + (b << 6) + (j - 32)];
        upd[i] = __float2half_rn(v);
    }
}

// ---------------- SIMT fp32 GEMM (tiny final layer) --------------------------
template<int BM, int BN, int BK, int TM, int TN, bool RELU>
__global__ __launch_bounds__((BM/TM)*(BN/TN)) void gemm_kernel(
    const float* __restrict__ A, const float* __restrict__ W,
    const float* __restrict__ bias, float* __restrict__ C,
    int M, int K, int N)
{
    __shared__ float As[BK][BM];
    __shared__ float Ws[BK][BN];
    const int nthr = (BM / TM) * (BN / TN);
    const int tid = threadIdx.x;
    const int tn = tid % (BN / TN);
    const int tm = tid / (BN / TN);
    const int row0 = blockIdx.y * BM;
    const int col0 = blockIdx.x * BN;

    float acc[TM][TN];
    #pragma unroll
    for (int m = 0; m < TM; m++)
        #pragma unroll
        for (int n = 0; n < TN; n++) acc[m][n] = 0.f;

    for (int k0 = 0; k0 < K; k0 += BK) {
        #pragma unroll
        for (int i = tid * 4; i < BM * BK; i += nthr * 4) {
            int r = i / BK, c = i % BK;
            float4 v = *(const float4*)&A[(size_t)(row0 + r) * K + k0 + c];
            As[c + 0][r] = v.x; As[c + 1][r] = v.y;
            As[c + 2][r] = v.z; As[c + 3][r] = v.w;
        }
        #pragma unroll
        for (int i = tid * 4; i < BK * BN; i += nthr * 4) {
            int r = i / BN, c = i % BN;
            *(float4*)&Ws[r][c] = *(const float4*)&W[(size_t)(k0 + r) * N + col0 + c];
        }
        __syncthreads();
        #pragma unroll
        for (int k = 0; k < BK; k++) {
            float a[TM], b[TN];
            #pragma unroll
            for (int m = 0; m < TM; m++) a[m] = As[k][tm * TM + m];
            #pragma unroll
            for (int n = 0; n < TN; n++) b[n] = Ws[k][tn * TN + n];
            #pragma unroll
            for (int m = 0; m < TM; m++)
                #pragma unroll
                for (int n = 0; n < TN; n++) acc[m][n] += a[m] * b[n];
        }
        __syncthreads();
    }
    #pragma unroll
    for (int m = 0; m < TM; m++) {
        int row = row0 + tm * TM + m;
        #pragma unroll
        for (int n = 0; n < TN; n++) {
            int col = col0 + tn * TN + n;
            float v = acc[m][n] + bias[col];
            if (RELU) v = fmaxf(v, 0.f);
            C[(size_t)row * N + col] = v;
        }
    }
}

// ---------------- launch ----------------------------------------------------
extern "C" void kernel_launch(void* const* d_in, const int* in_sizes, int n_in,
                              void* d_out, int out_size) {
    const float* obj = (const float*)d_in[0];
    const float* Rs  = (const float*)d_in[1];
    const float* Rrm = (const float*)d_in[2];
    const float* rw1 = (const float*)d_in[3];  const float* rb1 = (const float*)d_in[4];
    const float* rw2 = (const float*)d_in[5];  const float* rb2 = (const float*)d_in[6];
    const float* rw3 = (const float*)d_in[7];  const float* rb3 = (const float*)d_in[8];
    const float* rw4 = (const float*)d_in[9];  const float* rb4 = (const float*)d_in[10];
    const float* ow1 = (const float*)d_in[11]; const float* ob1 = (const float*)d_in[12];
    const float* ow2 = (const float*)d_in[13]; const float* ob2 = (const float*)d_in[14];
    float* out = (float*)d_out;

    __half *RsT, *RrT, *Rrh, *objT, *node, *h1, *h2, *h3, *edgeT, *upd;
    __half *w1h, *w2h, *w3h, *w4h, *o1h;
    float *agg2, *hobj;
    cudaGetSymbolAddress((void**)&RsT,  gh_RsT);
    cudaGetSymbolAddress((void**)&RrT,  gh_RrT);
    cudaGetSymbolAddress((void**)&Rrh,  gh_Rr);
    cudaGetSymbolAddress((void**)&objT, gh_objT);
    cudaGetSymbolAddress((void**)&node, gh_node);
    cudaGetSymbolAddress((void**)&h1,   gh_h1);
    cudaGetSymbolAddress((void**)&h2,   gh_h2);
    cudaGetSymbolAddress((void**)&h3,   gh_h3);
    cudaGetSymbolAddress((void**)&edgeT,gh_edgeT);
    cudaGetSymbolAddress((void**)&upd,  gh_upd);
    cudaGetSymbolAddress((void**)&agg2, g_agg);
    cudaGetSymbolAddress((void**)&hobj, g_hobj);
    cudaGetSymbolAddress((void**)&w1h,  gh_w1);
    cudaGetSymbolAddress((void**)&w2h,  gh_w2);
    cudaGetSymbolAddress((void**)&w3h,  gh_w3);
    cudaGetSymbolAddress((void**)&w4h,  gh_w4);
    cudaGetSymbolAddress((void**)&o1h,  gh_o1);

    // 0. conversions
    transpose_h_kernel<<<dim3(R_ / 32, N_ / 32), 256>>>(Rs,  RsT, nullptr);
    transpose_h_kernel<<<dim3(R_ / 32, N_ / 32), 256>>>(Rrm, RrT, Rrh);
    pack_objT_h_kernel<<<(N_ * 256 + 255) / 256, 256>>>(obj, objT);
    f2h_kernel<<<(64 * HID_ + 255) / 256, 256>>>(rw1, w1h, 64 * HID_);
    f2h_kernel<<<(HID_ * HID_ + 255) / 256, 256>>>(rw2, w2h, HID_ * HID_);
    f2h_kernel<<<(HID_ * 64 + 255) / 256, 256>>>(rw3, w3h, HID_ * 64);
    f2h_kernel<<<(64 * 64 + 255) / 256, 256>>>(rw4, w4h, 64 * 64);
    f2h_kernel<<<(96 * HID_ + 255) / 256, 256>>>(ow1, o1h, 96 * HID_);

    // 1. gathers: node[b,r,off+d] = sum_n RT[r,n] * objT[n, b*32+d]
    hmma_gemm<128, 128, 1, false><<<dim3(2, R_ / 128), 256>>>(
        RsT, objT, nullptr, node, 256, N_, N_, 0);
    hmma_gemm<128, 128, 1, false><<<dim3(2, R_ / 128), 256>>>(
        RrT, objT, nullptr, node, 256, N_, N_, 32);

    // 2. relational MLP
    hmma_gemm<128, 128, 0, true><<<dim3(HID_ / 128, MROWS / 128), 256>>>(
        node, w1h, rb1, h1, HID_, 64, 64, 0);
    hmma_gemm<128, 128, 0, true><<<dim3(HID_ / 128, MROWS / 128), 256>>>(
        h1, w2h, rb2, h2, HID_, HID_, HID_, 0);
    hmma_gemm<128, 64, 0, true><<<dim3(1, MROWS / 128), 128>>>(
        h2, w3h, rb3, h3, 64, HID_, HID_, 0);
    hmma_gemm<128, 64, 2, true><<<dim3(1, MROWS / 128), 128>>>(
        h3, w4h, rb4, edgeT, 64, 64, 64, 0);

    // 3. aggregate: agg2[n, b*64+e] = sum_r Rr[n,r] * edgeT[r, b*64+e] (split-K=8)
    zero_kernel<<<(N_ * 512 + 255) / 256, 256>>>(agg2, N_ * 512);
    hmma_gemm<128, 128, 3, false><<<dim3(4, N_ / 128, 8), 256>>>(
        Rrh, edgeT, nullptr, agg2, 512, R_, R_ / 8, 0);

    // 4. object MLP
    concat_h_kernel<<<(NROWS * 96 + 255) / 256, 256>>>(obj, agg2, upd);
    hmma_gemm<128, 128, 4, true><<<dim3(HID_ / 128, NROWS / 128), 256>>>(
        upd, o1h, ob1, hobj, HID_, 96, 96, 0);
    gemm_kernel<128, 32, 8, 8, 2, false><<<dim3(1, NROWS / 128), 256>>>(
        hobj, ow2, ob2, out, NROWS, HID_, 32);
}

// round 13
// speedup vs baseline: 5.8223x; 1.0727x over previous
#include <cuda_runtime.h>
#include <cuda_fp16.h>
#include <cstdint>

// Problem dims
#define B_    8
#define N_    1024
#define R_    16384
#define HID_  512
#define MROWS (B_ * R_)      // 131072
#define NROWS (B_ * N_)      // 8192

// ---------------- scratch (device globals; no allocations allowed) ----------
__device__ __align__(128) __half gh_RsT [R_ * N_];      // Rs^T fp16 [16384,1024]
__device__ __align__(128) __half gh_RrT [R_ * N_];      // Rr^T fp16 [16384,1024]
__device__ __align__(128) __half gh_Rr  [N_ * R_];      // Rr fp16 [1024,16384]
__device__ __align__(128) __half gh_objT[N_ * 256];     // objT fp16 [1024,256] col=b*32+d
__device__ __align__(128) __half gh_node[MROWS * 64];   // node fp16
__device__ __align__(128) __half gh_h1  [MROWS * HID_];
__device__ __align__(128) __half gh_h2  [MROWS * HID_];
__device__ __align__(128) __half gh_edgeT[R_ * 512];    // edgeT fp16 [16384,512] col=b*64+e
__device__ __align__(128) __half gh_upd [NROWS * 96];
__device__ __align__(128) float  g_agg  [N_ * 512];     // agg fp32 [1024,512]
__device__ __align__(128) float  g_hobj [NROWS * HID_];
// fp16 weights
__device__ __align__(128) __half gh_w1[64 * HID_];
__device__ __align__(128) __half gh_w2[HID_ * HID_];
__device__ __align__(128) __half gh_w3[HID_ * 64];
__device__ __align__(128) __half gh_w4[64 * 64];
__device__ __align__(128) __half gh_o1[96 * HID_];

// ---------------- asm helpers ------------------------------------------------
__device__ __forceinline__ void mma_f16(float d[4], uint32_t a0, uint32_t a1,
                                        uint32_t a2, uint32_t a3,
                                        uint32_t b0, uint32_t b1) {
    asm volatile(
        "mma.sync.aligned.m16n8k16.row.col.f32.f16.f16.f32 "
        "{%0,%1,%2,%3},{%4,%5,%6,%7},{%8,%9},{%0,%1,%2,%3};\n"
        : "+f"(d[0]), "+f"(d[1]), "+f"(d[2]), "+f"(d[3])
        : "r"(a0), "r"(a1), "r"(a2), "r"(a3), "r"(b0), "r"(b1));
}
__device__ __forceinline__ void ldsm_x4(uint32_t r[4], uint32_t addr) {
    asm volatile("ldmatrix.sync.aligned.m8n8.x4.shared.b16 {%0,%1,%2,%3}, [%4];"
                 : "=r"(r[0]), "=r"(r[1]), "=r"(r[2]), "=r"(r[3]) : "r"(addr));
}
__device__ __forceinline__ void ldsm_x4_t(uint32_t r[4], uint32_t addr) {
    asm volatile("ldmatrix.sync.aligned.m8n8.x4.trans.shared.b16 {%0,%1,%2,%3}, [%4];"
                 : "=r"(r[0]), "=r"(r[1]), "=r"(r[2]), "=r"(r[3]) : "r"(addr));
}
#define CP16(dst, src) \
    asm volatile("cp.async.cg.shared.global [%0], [%1], 16;" :: "r"(dst), "l"(src))
#define CP_COMMIT() asm volatile("cp.async.commit_group;")
#define CP_WAIT(n)  asm volatile("cp.async.wait_group %0;" :: "n"(n))

__device__ __forceinline__ uint32_t smem_u32(const void* p) {
    return (uint32_t)__cvta_generic_to_shared(p);
}

// ---------------- fp16 cp.async + ldmatrix GEMM (4-stage, dynamic smem) ------
// MODE: 0 = fp16 out  1 = gather-scatter fp16 node  2 = edgeT fp16  3 = atomic fp32  4 = fp32 out
template<int BM, int BN, int MODE, bool RELU>
__global__ __launch_bounds__((BM/64)*(BN/32)*32, 2) void hmma_gemm(
    const __half* __restrict__ A, const __half* __restrict__ W,
    const float* __restrict__ bias, void* __restrict__ C,
    int N, int lda, int klen, int off)
{
    constexpr int BK = 32, STAGES = 4;
    constexpr int NW_N = BN / 32;
    constexpr int THREADS = (BM/64) * NW_N * 32;
    constexpr int ACH = BM * 4;
    constexpr int BCHR = BN / 8;
    constexpr int BCH = BK * BCHR;
    constexpr int APT = ACH / THREADS, BPT = BCH / THREADS;
    extern __shared__ __align__(16) char dynsm[];
    const uint32_t a_s0 = smem_u32(dynsm);
    const uint32_t b_s0 = a_s0 + STAGES * BM * BK * 2;

    const int tid = threadIdx.x, lane = tid & 31, wid = tid >> 5;
    const int wm = (wid / NW_N) * 64, wn = (wid % NW_N) * 32;
    const int row0 = blockIdx.y * BM, col0 = blockIdx.x * BN;
    const int kstart = blockIdx.z * klen;
    const int ntiles = klen / BK;

    float acc[4][4][4];
    #pragma unroll
    for (int mi = 0; mi < 4; mi++)
        #pragma unroll
        for (int ni = 0; ni < 4; ni++)
            #pragma unroll
            for (int j = 0; j < 4; j++) acc[mi][ni][j] = 0.f;

    auto stage_copy = [&](int t, int st) {
        if (t < ntiles) {
            const int kk = kstart + t * BK;
            #pragma unroll
            for (int p = 0; p < APT; p++) {
                int q = tid + p * THREADS;
                int r = q >> 2, c = q & 3;
                uint32_t dst = a_s0 + (uint32_t)(st * BM * BK + (r * 4 + (c ^ ((r >> 1) & 3))) * 8) * 2;
                CP16(dst, &A[(size_t)(row0 + r) * lda + kk + c * 8]);
            }
            #pragma unroll
            for (int p = 0; p < BPT; p++) {
                int q = tid + p * THREADS;
                int k = q / BCHR, c = q % BCHR;
                uint32_t dst = b_s0 + (uint32_t)(st * BK * BN + (k * BCHR + (c ^ (k & 7))) * 8) * 2;
                CP16(dst, &W[(size_t)(kk + k) * N + col0 + c * 8]);
            }
        }
        CP_COMMIT();
    };

    #pragma unroll
    for (int t = 0; t < STAGES - 1; t++) stage_copy(t, t);

    for (int t = 0; t < ntiles; t++) {
        CP_WAIT(STAGES - 2);
        __syncthreads();
        stage_copy(t + STAGES - 1, (t + STAGES - 1) % STAGES);
        const int st = t % STAGES;
        const uint32_t abase = a_s0 + (uint32_t)(st * BM * BK) * 2;
        const uint32_t bbase = b_s0 + (uint32_t)(st * BK * BN) * 2;
        #pragma unroll
        for (int s = 0; s < 2; s++) {
            uint32_t af[4][4], bf[2][4];
            #pragma unroll
            for (int mi = 0; mi < 4; mi++) {
                int r = wm + mi * 16 + (lane & 15);
                int c = s * 2 + (lane >> 4);
                ldsm_x4(af[mi], abase + (uint32_t)((r * 4 + (c ^ ((r >> 1) & 3))) * 16));
            }
            #pragma unroll
            for (int np = 0; np < 2; np++) {
                int k = s * 16 + (lane & 15);
                int c = (wn >> 3) + np * 2 + (lane >> 4);
                ldsm_x4_t(bf[np], bbase + (uint32_t)((k * BCHR + (c ^ (k & 7))) * 16));
            }
            #pragma unroll
            for (int mi = 0; mi < 4; mi++)
                #pragma unroll
                for (int ni = 0; ni < 4; ni++)
                    mma_f16(acc[mi][ni], af[mi][0], af[mi][1], af[mi][2], af[mi][3],
                            bf[ni >> 1][(ni & 1) * 2], bf[ni >> 1][(ni & 1) * 2 + 1]);
        }
    }

    // epilogue
    const int lc = lane & 3, lg = lane >> 2;
    #pragma unroll
    for (int mi = 0; mi < 4; mi++) {
        int r0 = row0 + wm + mi * 16 + lg;
        #pragma unroll
        for (int ni = 0; ni < 4; ni++) {
            int c0 = col0 + wn + ni * 8 + lc * 2;
            #pragma unroll
            for (int h = 0; h < 2; h++) {
                int row = r0 + h * 8;
                float v0 = acc[mi][ni][h * 2 + 0];
                float v1 = acc[mi][ni][h * 2 + 1];
                if (MODE == 0 || MODE == 2 || MODE == 4) {
                    v0 += bias[c0]; v1 += bias[c0 + 1];
                    if (RELU) { v0 = fmaxf(v0, 0.f); v1 = fmaxf(v1, 0.f); }
                }
                if (MODE == 0) {
                    *(__half2*)&((__half*)C)[(size_t)row * N + c0] = __floats2half2_rn(v0, v1);
                } else if (MODE == 1) {
                    int b = c0 >> 5, d = c0 & 31;
                    *(__half2*)&((__half*)C)[(((size_t)b << 14) + row) * 64 + off + d] =
                        __floats2half2_rn(v0, v1);
                } else if (MODE == 2) {
                    int b = row >> 14, r = row & 16383;
                    *(__half2*)&((__half*)C)[(size_t)r * 512 + (b << 6) + c0] =
                        __floats2half2_rn(v0, v1);
                } else if (MODE == 3) {
                    atomicAdd(&((float*)C)[(size_t)row * N + c0], v0);
                    atomicAdd(&((float*)C)[(size_t)row * N + c0 + 1], v1);
                } else {
                    ((float*)C)[(size_t)row * N + c0]     = v0;
                    ((float*)C)[(size_t)row * N + c0 + 1] = v1;
                }
            }
        }
    }
}

// ---------------- fused rw3+rw4: edgeT = relu(relu(h2@W3+b3)@W4+b4) ----------
// BM=128, BN=64, 128 threads (4 warps, 2m x 2n), 4-stage phase1, smem phase2.
__global__ __launch_bounds__(128, 2) void rw34_kernel(
    const __half* __restrict__ A,   // h2 [MROWS, 512]
    const __half* __restrict__ W3, const float* __restrict__ b3,
    const __half* __restrict__ W4, const float* __restrict__ b4,
    __half* __restrict__ C)         // edgeT [16384, 512] col=b*64+e
{
    constexpr int BM = 128, BN = 64, BK = 32, STAGES = 4, THREADS = 128;
    constexpr int BCHR = BN / 8;   // 8
    constexpr int APT = (BM * 4) / THREADS;        // 4
    constexpr int BPT = (BK * BCHR) / THREADS;     // 2
    extern __shared__ __align__(16) char dynsm[];
    const uint32_t a_s0 = smem_u32(dynsm);
    const uint32_t b_s0 = a_s0 + STAGES * BM * BK * 2;
    __half* Asm = (__half*)dynsm;
    __half* Bsm = (__half*)(dynsm + STAGES * BM * BK * 2);

    const int tid = threadIdx.x, lane = tid & 31, wid = tid >> 5;
    const int wm = (wid >> 1) * 64, wn = (wid & 1) * 32;
    const int row0 = blockIdx.x * BM;
    const int ntiles = 512 / BK;   // 16
    const int lc = lane & 3, lg = lane >> 2;

    float acc[4][4][4];
    #pragma unroll
    for (int mi = 0; mi < 4; mi++)
        #pragma unroll
        for (int ni = 0; ni < 4; ni++)
            #pragma unroll
            for (int j = 0; j < 4; j++) acc[mi][ni][j] = 0.f;

    auto stage_copy = [&](int t, int st) {
        if (t < ntiles) {
            const int kk = t * BK;
            #pragma unroll
            for (int p = 0; p < APT; p++) {
                int q = tid + p * THREADS;
                int r = q >> 2, c = q & 3;
                uint32_t dst = a_s0 + (uint32_t)(st * BM * BK + (r * 4 + (c ^ ((r >> 1) & 3))) * 8) * 2;
                CP16(dst, &A[(size_t)(row0 + r) * 512 + kk + c * 8]);
            }
            #pragma unroll
            for (int p = 0; p < BPT; p++) {
                int q = tid + p * THREADS;
                int k = q / BCHR, c = q % BCHR;
                uint32_t dst = b_s0 + (uint32_t)(st * BK * BN + (k * BCHR + (c ^ (k & 7))) * 8) * 2;
                CP16(dst, &W3[(size_t)(kk + k) * BN + c * 8]);
            }
        }
        CP_COMMIT();
    };

    #pragma unroll
    for (int t = 0; t < STAGES - 1; t++) stage_copy(t, t);

    for (int t = 0; t < ntiles; t++) {
        CP_WAIT(STAGES - 2);
        __syncthreads();
        stage_copy(t + STAGES - 1, (t + STAGES - 1) % STAGES);
        const int st = t % STAGES;
        const uint32_t abase = a_s0 + (uint32_t)(st * BM * BK) * 2;
        const uint32_t bbase = b_s0 + (uint32_t)(st * BK * BN) * 2;
        #pragma unroll
        for (int s = 0; s < 2; s++) {
            uint32_t af[4][4], bf[2][4];
            #pragma unroll
            for (int mi = 0; mi < 4; mi++) {
                int r = wm + mi * 16 + (lane & 15);
                int c = s * 2 + (lane >> 4);
                ldsm_x4(af[mi], abase + (uint32_t)((r * 4 + (c ^ ((r >> 1) & 3))) * 16));
            }
            #pragma unroll
            for (int np = 0; np < 2; np++) {
                int k = s * 16 + (lane & 15);
                int c = (wn >> 3) + np * 2 + (lane >> 4);
                ldsm_x4_t(bf[np], bbase + (uint32_t)((k * BCHR + (c ^ (k & 7))) * 16));
            }
            #pragma unroll
            for (int mi = 0; mi < 4; mi++)
                #pragma unroll
                for (int ni = 0; ni < 4; ni++)
                    mma_f16(acc[mi][ni], af[mi][0], af[mi][1], af[mi][2], af[mi][3],
                            bf[ni >> 1][(ni & 1) * 2], bf[ni >> 1][(ni & 1) * 2 + 1]);
        }
    }

    // drain pipeline, then repurpose stages 0/1 for phase 2
    CP_WAIT(0);
    __syncthreads();

    // h3 = relu(acc + b3) -> Asm stages 0 (cols 0-31) and 1 (cols 32-63), A-swizzle layout
    #pragma unroll
    for (int mi = 0; mi < 4; mi++) {
        #pragma unroll
        for (int ni = 0; ni < 4; ni++) {
            int c0 = wn + ni * 8 + lc * 2;
            int st = c0 >> 5, ck = (c0 & 31) >> 3;
            #pragma unroll
            for (int h = 0; h < 2; h++) {
                int r = wm + mi * 16 + lg + h * 8;
                float v0 = fmaxf(acc[mi][ni][h * 2 + 0] + b3[c0],     0.f);
                float v1 = fmaxf(acc[mi][ni][h * 2 + 1] + b3[c0 + 1], 0.f);
                uint32_t offh = (uint32_t)(st * BM * BK + (r * 4 + (ck ^ ((r >> 1) & 3))) * 8 + (c0 & 7));
                *(__half2*)(Asm + offh) = __floats2half2_rn(v0, v1);
            }
        }
    }
    // W4 [64,64] -> Bsm stages 0 (k 0-31) and 1 (k 32-63), B-swizzle layout
    #pragma unroll
    for (int p = 0; p < 8; p++) {
        int i = tid * 4 + p * 512;
        int k = i >> 6, c = i & 63;
        uint2 v = *(const uint2*)&W4[(size_t)k * 64 + c];
        int stb = k >> 5, kk = k & 31;
        uint32_t offh = (uint32_t)(stb * BK * BN + (kk * BCHR + ((c >> 3) ^ (kk & 7))) * 8 + (c & 7));
        *(uint2*)(Bsm + offh) = v;
    }
    __syncthreads();

    // phase 2: edge = relu(h3 @ W4 + b4), K=64 = 2 tiles x 2 s-steps
    #pragma unroll
    for (int mi = 0; mi < 4; mi++)
        #pragma unroll
        for (int ni = 0; ni < 4; ni++)
            #pragma unroll
            for (int j = 0; j < 4; j++) acc[mi][ni][j] = 0.f;

    #pragma unroll
    for (int t2 = 0; t2 < 2; t2++) {
        const uint32_t abase = a_s0 + (uint32_t)(t2 * BM * BK) * 2;
        const uint32_t bbase = b_s0 + (uint32_t)(t2 * BK * BN) * 2;
        #pragma unroll
        for (int s = 0; s < 2; s++) {
            uint32_t af[4][4], bf[2][4];
            #pragma unroll
            for (int mi = 0; mi < 4; mi++) {
                int r = wm + mi * 16 + (lane & 15);
                int c = s * 2 + (lane >> 4);
                ldsm_x4(af[mi], abase + (uint32_t)((r * 4 + (c ^ ((r >> 1) & 3))) * 16));
            }
            #pragma unroll
            for (int np = 0; np < 2; np++) {
                int k = s * 16 + (lane & 15);
                int c = (wn >> 3) + np * 2 + (lane >> 4);
                ldsm_x4_t(bf[np], bbase + (uint32_t)((k * BCHR + (c ^ (k & 7))) * 16));
            }
            #pragma unroll
            for (int mi = 0; mi < 4; mi++)
                #pragma unroll
                for (int ni = 0; ni < 4; ni++)
                    mma_f16(acc[mi][ni], af[mi][0], af[mi][1], af[mi][2], af[mi][3],
                            bf[ni >> 1][(ni & 1) * 2], bf[ni >> 1][(ni & 1) * 2 + 1]);
        }
    }

    // epilogue: edgeT[r, b*64+e]
    #pragma unroll
    for (int mi = 0; mi < 4; mi++) {
        int r0 = row0 + wm + mi * 16 + lg;
        #pragma unroll
        for (int ni = 0; ni < 4; ni++) {
            int c0 = wn + ni * 8 + lc * 2;
            #pragma unroll
            for (int h = 0; h < 2; h++) {
                int row = r0 + h * 8;
                float v0 = fmaxf(acc[mi][ni][h * 2 + 0] + b4[c0],     0.f);
                float v1 = fmaxf(acc[mi][ni][h * 2 + 1] + b4[c0 + 1], 0.f);
                int b = row >> 14, r = row & 16383;
                *(__half2*)&C[(size_t)r * 512 + (b << 6) + c0] = __floats2half2_rn(v0, v1);
            }
        }
    }
}

// ---------------- transpose+convert: RT_h[r][n] = (half)R[n][r]; opt Rh copy --
__global__ __launch_bounds__(256) void transpose_h_kernel(
    const float* __restrict__ R, __half* __restrict__ RT, __half* Rh)
{
    __shared__ __half sm[32][33];
    const int tx = threadIdx.x & 31, ty = threadIdx.x >> 5;
    const int rb = blockIdx.x * 32, nb = blockIdx.y * 32;
    #pragma unroll
    for (int j = 0; j < 4; j++) {
        int n = nb + ty + j * 8, r = rb + tx;
        __half h = __float2half_rn(R[(size_t)n * R_ + r]);
        if (Rh) Rh[(size_t)n * R_ + r] = h;
        sm[ty + j * 8][tx] = h;
    }
    __syncthreads();
    #pragma unroll
    for (int j = 0; j < 4; j++) {
        int r = rb + ty + j * 8, n = nb + tx;
        RT[(size_t)r * N_ + n] = sm[tx][ty + j * 8];
    }
}

// ---------------- small utility kernels --------------------------------------
__global__ void f2h_kernel(const float* __restrict__ src, __half* __restrict__ dst, int n) {
    int i = blockIdx.x * blockDim.x + threadIdx.x;
    if (i < n) dst[i] = __float2half_rn(src[i]);
}

__global__ void f2h4_kernel(const float* s1, __half* d1,
                            const float* s2, __half* d2,
                            const float* s3, __half* d3,
                            const float* s4, __half* d4) {
    const int n1 = 64 * HID_, n2 = HID_ * 64, n3 = 64 * 64, n4 = 96 * HID_;
    int i = blockIdx.x * blockDim.x + threadIdx.x;
    if (i < n1) d1[i] = __float2half_rn(s1[i]);
    else if (i < n1 + n2) d2[i - n1] = __float2half_rn(s2[i - n1]);
    else if (i < n1 + n2 + n3) d3[i - n1 - n2] = __float2half_rn(s3[i - n1 - n2]);
    else if (i < n1 + n2 + n3 + n4) d4[i - n1 - n2 - n3] = __float2half_rn(s4[i - n1 - n2 - n3]);
}

__global__ void pack_objT_h_kernel(const float* __restrict__ obj, __half* __restrict__ objT) {
    int i = blockIdx.x * blockDim.x + threadIdx.x;
    if (i < N_ * 256) {
        int n = i >> 8, c = i & 255;
        int b = c >> 5, d = c & 31;
        objT[i] = __float2half_rn(obj[((size_t)b * N_ + n) * 32 + d]);
    }
}

__global__ void zero_kernel(float* p, int n) {
    int i = blockIdx.x * blockDim.x + threadIdx.x;
    if (i < n) p[i] = 0.f;
}

__global__ void concat_h_kernel(const float* __restrict__ obj,
                                const float* __restrict__ agg2,
                                __half* __restrict__ upd) {
    int i = blockIdx.x * blockDim.x + threadIdx.x;
    if (i < NROWS * 96) {
        int row = i / 96, j = i % 96;
        int b = row >> 10, n = row & 1023;
        float v = (j < 32) ? obj[(size_t)row * 32 + j]
                           : agg2[(size_t)n * 512 + (b << 6) + (j - 32)];
        upd[i] = __float2half_rn(v);
    }
}

// ---------------- SIMT fp32 GEMM (tiny final layer) --------------------------
template<int BM, int BN, int BK, int TM, int TN, bool RELU>
__global__ __launch_bounds__((BM/TM)*(BN/TN)) void gemm_kernel(
    const float* __restrict__ A, const float* __restrict__ W,
    const float* __restrict__ bias, float* __restrict__ C,
    int M, int K, int N)
{
    __shared__ float As[BK][BM];
    __shared__ float Ws[BK][BN];
    const int nthr = (BM / TM) * (BN / TN);
    const int tid = threadIdx.x;
    const int tn = tid % (BN / TN);
    const int tm = tid / (BN / TN);
    const int row0 = blockIdx.y * BM;
    const int col0 = blockIdx.x * BN;

    float acc[TM][TN];
    #pragma unroll
    for (int m = 0; m < TM; m++)
        #pragma unroll
        for (int n = 0; n < TN; n++) acc[m][n] = 0.f;

    for (int k0 = 0; k0 < K; k0 += BK) {
        #pragma unroll
        for (int i = tid * 4; i < BM * BK; i += nthr * 4) {
            int r = i / BK, c = i % BK;
            float4 v = *(const float4*)&A[(size_t)(row0 + r) * K + k0 + c];
            As[c + 0][r] = v.x; As[c + 1][r] = v.y;
            As[c + 2][r] = v.z; As[c + 3][r] = v.w;
        }
        #pragma unroll
        for (int i = tid * 4; i < BK * BN; i += nthr * 4) {
            int r = i / BN, c = i % BN;
            *(float4*)&Ws[r][c] = *(const float4*)&W[(size_t)(k0 + r) * N + col0 + c];
        }
        __syncthreads();
        #pragma unroll
        for (int k = 0; k < BK; k++) {
            float a[TM], b[TN];
            #pragma unroll
            for (int m = 0; m < TM; m++) a[m] = As[k][tm * TM + m];
            #pragma unroll
            for (int n = 0; n < TN; n++) b[n] = Ws[k][tn * TN + n];
            #pragma unroll
            for (int m = 0; m < TM; m++)
                #pragma unroll
                for (int n = 0; n < TN; n++) acc[m][n] += a[m] * b[n];
        }
        __syncthreads();
    }
    #pragma unroll
    for (int m = 0; m < TM; m++) {
        int row = row0 + tm * TM + m;
        #pragma unroll
        for (int n = 0; n < TN; n++) {
            int col = col0 + tn * TN + n;
            float v = acc[m][n] + bias[col];
            if (RELU) v = fmaxf(v, 0.f);
            C[(size_t)row * N + col] = v;
        }
    }
}

// ---------------- launch ----------------------------------------------------
#define HSMEM (4 * (128 * 32 + 32 * 128) * 2)       // 65536
#define RW34SMEM (4 * (128 * 32 + 32 * 64) * 2)     // 49152

extern "C" void kernel_launch(void* const* d_in, const int* in_sizes, int n_in,
                              void* d_out, int out_size) {
    const float* obj = (const float*)d_in[0];
    const float* Rs  = (const float*)d_in[1];
    const float* Rrm = (const float*)d_in[2];
    const float* rw1 = (const float*)d_in[3];  const float* rb1 = (const float*)d_in[4];
    const float* rw2 = (const float*)d_in[5];  const float* rb2 = (const float*)d_in[6];
    const float* rw3 = (const float*)d_in[7];  const float* rb3 = (const float*)d_in[8];
    const float* rw4 = (const float*)d_in[9];  const float* rb4 = (const float*)d_in[10];
    const float* ow1 = (const float*)d_in[11]; const float* ob1 = (const float*)d_in[12];
    const float* ow2 = (const float*)d_in[13]; const float* ob2 = (const float*)d_in[14];
    float* out = (float*)d_out;

    __half *RsT, *RrT, *Rrh, *objT, *node, *h1, *h2, *edgeT, *upd;
    __half *w1h, *w2h, *w3h, *w4h, *o1h;
    float *agg2, *hobj;
    cudaGetSymbolAddress((void**)&RsT,  gh_RsT);
    cudaGetSymbolAddress((void**)&RrT,  gh_RrT);
    cudaGetSymbolAddress((void**)&Rrh,  gh_Rr);
    cudaGetSymbolAddress((void**)&objT, gh_objT);
    cudaGetSymbolAddress((void**)&node, gh_node);
    cudaGetSymbolAddress((void**)&h1,   gh_h1);
    cudaGetSymbolAddress((void**)&h2,   gh_h2);
    cudaGetSymbolAddress((void**)&edgeT,gh_edgeT);
    cudaGetSymbolAddress((void**)&upd,  gh_upd);
    cudaGetSymbolAddress((void**)&agg2, g_agg);
    cudaGetSymbolAddress((void**)&hobj, g_hobj);
    cudaGetSymbolAddress((void**)&w1h,  gh_w1);
    cudaGetSymbolAddress((void**)&w2h,  gh_w2);
    cudaGetSymbolAddress((void**)&w3h,  gh_w3);
    cudaGetSymbolAddress((void**)&w4h,  gh_w4);
    cudaGetSymbolAddress((void**)&o1h,  gh_o1);

    // allow >48KB dynamic smem (idempotent; host-side attribute, not a stream op)
    cudaFuncSetAttribute(hmma_gemm<128, 128, 0, true>,
                         cudaFuncAttributeMaxDynamicSharedMemorySize, HSMEM);
    cudaFuncSetAttribute(hmma_gemm<128, 128, 1, false>,
                         cudaFuncAttributeMaxDynamicSharedMemorySize, HSMEM);
    cudaFuncSetAttribute(hmma_gemm<128, 128, 3, false>,
                         cudaFuncAttributeMaxDynamicSharedMemorySize, HSMEM);
    cudaFuncSetAttribute(hmma_gemm<128, 128, 4, true>,
                         cudaFuncAttributeMaxDynamicSharedMemorySize, HSMEM);
    cudaFuncSetAttribute(rw34_kernel,
                         cudaFuncAttributeMaxDynamicSharedMemorySize, RW34SMEM);

    // 0. conversions
    transpose_h_kernel<<<dim3(R_ / 32, N_ / 32), 256>>>(Rs,  RsT, nullptr);
    transpose_h_kernel<<<dim3(R_ / 32, N_ / 32), 256>>>(Rrm, RrT, Rrh);
    pack_objT_h_kernel<<<(N_ * 256 + 255) / 256, 256>>>(obj, objT);
    f2h_kernel<<<(HID_ * HID_ + 255) / 256, 256>>>(rw2, w2h, HID_ * HID_);
    {
        int total = 64 * HID_ + HID_ * 64 + 64 * 64 + 96 * HID_;
        f2h4_kernel<<<(total + 255) / 256, 256>>>(rw1, w1h, rw3, w3h, rw4, w4h, ow1, o1h);
    }

    // 1. gathers: node[b,r,off+d] = sum_n RT[r,n] * objT[n, b*32+d]
    hmma_gemm<128, 128, 1, false><<<dim3(2, R_ / 128), 256, HSMEM>>>(
        RsT, objT, nullptr, node, 256, N_, N_, 0);
    hmma_gemm<128, 128, 1, false><<<dim3(2, R_ / 128), 256, HSMEM>>>(
        RrT, objT, nullptr, node, 256, N_, N_, 32);

    // 2. relational MLP
    hmma_gemm<128, 128, 0, true><<<dim3(HID_ / 128, MROWS / 128), 256, HSMEM>>>(
        node, w1h, rb1, h1, HID_, 64, 64, 0);
    hmma_gemm<128, 128, 0, true><<<dim3(HID_ / 128, MROWS / 128), 256, HSMEM>>>(
        h1, w2h, rb2, h2, HID_, HID_, HID_, 0);
    rw34_kernel<<<MROWS / 128, 128, RW34SMEM>>>(h2, w3h, rb3, w4h, rb4, edgeT);

    // 3. aggregate: agg2[n, b*64+e] = sum_r Rr[n,r] * edgeT[r, b*64+e] (split-K=8)
    zero_kernel<<<(N_ * 512 + 255) / 256, 256>>>(agg2, N_ * 512);
    hmma_gemm<128, 128, 3, false><<<dim3(4, N_ / 128, 8), 256, HSMEM>>>(
        Rrh, edgeT, nullptr, agg2, 512, R_, R_ / 8, 0);

    // 4. object MLP
    concat_h_kernel<<<(NROWS * 96 + 255) / 256, 256>>>(obj, agg2, upd);
    hmma_gemm<128, 128, 4, true><<<dim3(HID_ / 128, NROWS / 128), 256, HSMEM>>>(
        upd, o1h, ob1, hobj, HID_, 96, 96, 0);
    gemm_kernel<128, 32, 8, 8, 2, false><<<dim3(1, NROWS / 128), 256>>>(
        hobj, ow2, ob2, out, NROWS, HID_, 32);
}

// round 14
// speedup vs baseline: 6.0444x; 1.0382x over previous
#include <cuda_runtime.h>
#include <cuda_fp16.h>
#include <cstdint>

// Problem dims
#define B_    8
#define N_    1024
#define R_    16384
#define HID_  512
#define MROWS (B_ * R_)      // 131072
#define NROWS (B_ * N_)      // 8192

// ---------------- scratch (device globals; no allocations allowed) ----------
__device__ __align__(128) __half gh_RsT [R_ * N_];      // Rs^T fp16 [16384,1024]
__device__ __align__(128) __half gh_RrT [R_ * N_];      // Rr^T fp16 [16384,1024]
__device__ __align__(128) __half gh_Rr  [N_ * R_];      // Rr fp16 [1024,16384]
__device__ __align__(128) __half gh_objT[N_ * 256];     // objT fp16 [1024,256] col=b*32+d
__device__ __align__(128) __half gh_node[MROWS * 64];   // node fp16
__device__ __align__(128) __half gh_edgeT[R_ * 512];    // edgeT fp16 [16384,512] col=b*64+e
__device__ __align__(128) __half gh_upd [NROWS * 96];
__device__ __align__(128) float  g_agg  [N_ * 512];     // agg fp32 [1024,512]
__device__ __align__(128) float  g_hobj [NROWS * HID_];
// fp16 weights
__device__ __align__(128) __half gh_w1[64 * HID_];
__device__ __align__(128) __half gh_w2[HID_ * HID_];
__device__ __align__(128) __half gh_w3[HID_ * 64];
__device__ __align__(128) __half gh_w4[64 * 64];
__device__ __align__(128) __half gh_o1[96 * HID_];

// ---------------- asm helpers ------------------------------------------------
__device__ __forceinline__ void mma_f16(float d[4], uint32_t a0, uint32_t a1,
                                        uint32_t a2, uint32_t a3,
                                        uint32_t b0, uint32_t b1) {
    asm volatile(
        "mma.sync.aligned.m16n8k16.row.col.f32.f16.f16.f32 "
        "{%0,%1,%2,%3},{%4,%5,%6,%7},{%8,%9},{%0,%1,%2,%3};\n"
        : "+f"(d[0]), "+f"(d[1]), "+f"(d[2]), "+f"(d[3])
        : "r"(a0), "r"(a1), "r"(a2), "r"(a3), "r"(b0), "r"(b1));
}
__device__ __forceinline__ void ldsm_x4(uint32_t r[4], uint32_t addr) {
    asm volatile("ldmatrix.sync.aligned.m8n8.x4.shared.b16 {%0,%1,%2,%3}, [%4];"
                 : "=r"(r[0]), "=r"(r[1]), "=r"(r[2]), "=r"(r[3]) : "r"(addr));
}
__device__ __forceinline__ void ldsm_x4_t(uint32_t r[4], uint32_t addr) {
    asm volatile("ldmatrix.sync.aligned.m8n8.x4.trans.shared.b16 {%0,%1,%2,%3}, [%4];"
                 : "=r"(r[0]), "=r"(r[1]), "=r"(r[2]), "=r"(r[3]) : "r"(addr));
}
#define CP16(dst, src) \
    asm volatile("cp.async.cg.shared.global [%0], [%1], 16;" :: "r"(dst), "l"(src))
#define CP_COMMIT() asm volatile("cp.async.commit_group;")
#define CP_WAIT(n)  asm volatile("cp.async.wait_group %0;" :: "n"(n))

__device__ __forceinline__ uint32_t smem_u32(const void* p) {
    return (uint32_t)__cvta_generic_to_shared(p);
}

// ================= fused relational MLP =======================================
// edgeT = relu(relu(relu(relu(node@W1+b1)@W2+b2)@W3+b3)@W4+b4)
// BM=64 rows/CTA, 256 threads (8 warps: 2M x 4N for A/B phases, 2M x 4N16 for C/D).
// smem: [h1/h2 buf 64KB][W stage ring 128KB][node/h3 8KB] = 200KB
#define RMLP_SMEM (65536 + 131072 + 8192)

__global__ __launch_bounds__(256, 1) void rmlp_kernel(
    const __half* __restrict__ Anode,
    const __half* __restrict__ W1, const float* __restrict__ b1,
    const __half* __restrict__ W2, const float* __restrict__ b2,
    const __half* __restrict__ W3, const float* __restrict__ b3,
    const __half* __restrict__ W4, const float* __restrict__ b4,
    __half* __restrict__ C)
{
    extern __shared__ __align__(16) char dynsm[];
    const uint32_t s0 = smem_u32(dynsm);
    const uint32_t h1o = s0;                 // 16 blocks x 4096B (64 rows x 32 cols fp16)
    const uint32_t wsto = s0 + 65536;        // 4 stages x 32768B (phase B) / W3+W4 (C,D)
    const uint32_t nodeo = s0 + 196608;      // 2 blocks x 4096B
    __half* h1p = (__half*)dynsm;
    __half* nodep = (__half*)(dynsm + 196608);

    const int tid = threadIdx.x, lane = tid & 31, wid = tid >> 5;
    const int wm = (wid >> 2) * 32;          // 2 M-groups of 32
    const int wn = (wid & 3) * 128;          // 4 N-groups of 128 (phases A,B)
    const int wn3 = (wid & 3) * 16;          // 4 N-groups of 16  (phases C,D)
    const int row0 = blockIdx.x * 64;
    const int lc = lane & 3, lg = lane >> 2;

    // ---- prologue: node tile + W1 ----
    {
        #pragma unroll
        for (int p = 0; p < 2; p++) {         // node: 512 chunks
            int q = tid * 2 + p;
            int r = q >> 3, c8 = q & 7, t = c8 >> 2, c = c8 & 3;
            CP16(nodeo + t * 4096 + (r * 4 + (c ^ ((r >> 1) & 3))) * 16,
                 &Anode[(size_t)(row0 + r) * 64 + c8 * 8]);
        }
        #pragma unroll
        for (int p = 0; p < 16; p++) {        // W1: 2 k-blocks of 32x512
            int q = tid + p * 256;
            int kb = q >> 11, rem = q & 2047, k = rem >> 6, c = rem & 63;
            CP16(wsto + kb * 32768 + (k * 64 + (c ^ (k & 7))) * 16,
                 &W1[(size_t)(kb * 32 + k) * 512 + c * 8]);
        }
        CP_COMMIT();
        CP_WAIT(0);
        __syncthreads();
    }

    float acc[2][16][4];
    #pragma unroll
    for (int mi = 0; mi < 2; mi++)
        #pragma unroll
        for (int ni = 0; ni < 16; ni++)
            #pragma unroll
            for (int j = 0; j < 4; j++) acc[mi][ni][j] = 0.f;

    // ---- phase A: h1 = relu(node @ W1 + b1), K=64 ----
    #pragma unroll
    for (int t = 0; t < 2; t++) {
        #pragma unroll
        for (int s = 0; s < 2; s++) {
            uint32_t af[2][4], bf[8][4];
            #pragma unroll
            for (int mi = 0; mi < 2; mi++) {
                int r = wm + mi * 16 + (lane & 15);
                int c = s * 2 + (lane >> 4);
                ldsm_x4(af[mi], nodeo + t * 4096 + (r * 4 + (c ^ ((r >> 1) & 3))) * 16);
            }
            #pragma unroll
            for (int np = 0; np < 8; np++) {
                int k = s * 16 + (lane & 15);
                int c = (wn >> 3) + np * 2 + (lane >> 4);
                ldsm_x4_t(bf[np], wsto + t * 32768 + (k * 64 + (c ^ (k & 7))) * 16);
            }
            #pragma unroll
            for (int mi = 0; mi < 2; mi++)
                #pragma unroll
                for (int ni = 0; ni < 16; ni++)
                    mma_f16(acc[mi][ni], af[mi][0], af[mi][1], af[mi][2], af[mi][3],
                            bf[ni >> 1][(ni & 1) * 2], bf[ni >> 1][(ni & 1) * 2 + 1]);
        }
    }
    __syncthreads();   // W1 stage reads complete

    // store h1 -> smem (A-swizzled) ; launch W2 prefetch stages 0..2
    #pragma unroll
    for (int mi = 0; mi < 2; mi++) {
        #pragma unroll
        for (int ni = 0; ni < 16; ni++) {
            int c0 = wn + ni * 8 + lc * 2;
            int kb2 = c0 >> 5, ck = (c0 >> 3) & 3;
            #pragma unroll
            for (int h = 0; h < 2; h++) {
                int r = wm + mi * 16 + lg + h * 8;
                float v0 = fmaxf(acc[mi][ni][h * 2 + 0] + b1[c0],     0.f);
                float v1 = fmaxf(acc[mi][ni][h * 2 + 1] + b1[c0 + 1], 0.f);
                *(__half2*)&h1p[(kb2 * 4096 + (r * 4 + (ck ^ ((r >> 1) & 3))) * 16 + (c0 & 7) * 2) / 2]
                    = __floats2half2_rn(v0, v1);
            }
        }
    }
    auto w2_stage = [&](int t, int st) {
        if (t < 16) {
            #pragma unroll
            for (int p = 0; p < 8; p++) {
                int q = tid + p * 256;
                int k = q >> 6, c = q & 63;
                CP16(wsto + st * 32768 + (k * 64 + (c ^ (k & 7))) * 16,
                     &W2[(size_t)(t * 32 + k) * 512 + c * 8]);
            }
        }
        CP_COMMIT();
    };
    w2_stage(0, 0); w2_stage(1, 1); w2_stage(2, 2);
    __syncthreads();   // h1 visible to all warps

    // reset acc for phase B
    #pragma unroll
    for (int mi = 0; mi < 2; mi++)
        #pragma unroll
        for (int ni = 0; ni < 16; ni++)
            #pragma unroll
            for (int j = 0; j < 4; j++) acc[mi][ni][j] = 0.f;

    // ---- phase B: h2 = relu(h1 @ W2 + b2), K=512, 4-stage W2 pipeline ----
    for (int kt = 0; kt < 16; kt++) {
        CP_WAIT(2);
        __syncthreads();
        w2_stage(kt + 3, (kt + 3) & 3);
        const int st = kt & 3;
        #pragma unroll
        for (int s = 0; s < 2; s++) {
            uint32_t af[2][4], bf[8][4];
            #pragma unroll
            for (int mi = 0; mi < 2; mi++) {
                int r = wm + mi * 16 + (lane & 15);
                int c = s * 2 + (lane >> 4);
                ldsm_x4(af[mi], h1o + kt * 4096 + (r * 4 + (c ^ ((r >> 1) & 3))) * 16);
            }
            #pragma unroll
            for (int np = 0; np < 8; np++) {
                int k = s * 16 + (lane & 15);
                int c = (wn >> 3) + np * 2 + (lane >> 4);
                ldsm_x4_t(bf[np], wsto + st * 32768 + (k * 64 + (c ^ (k & 7))) * 16);
            }
            #pragma unroll
            for (int mi = 0; mi < 2; mi++)
                #pragma unroll
                for (int ni = 0; ni < 16; ni++)
                    mma_f16(acc[mi][ni], af[mi][0], af[mi][1], af[mi][2], af[mi][3],
                            bf[ni >> 1][(ni & 1) * 2], bf[ni >> 1][(ni & 1) * 2 + 1]);
        }
    }
    CP_WAIT(0);
    __syncthreads();   // all h1 reads + W2 stage reads complete

    // h2 = relu(acc+b2) -> overwrite h1 buffer ; load W3 (16 blocks) + W4 (2 blocks)
    #pragma unroll
    for (int mi = 0; mi < 2; mi++) {
        #pragma unroll
        for (int ni = 0; ni < 16; ni++) {
            int c0 = wn + ni * 8 + lc * 2;
            int kb2 = c0 >> 5, ck = (c0 >> 3) & 3;
            #pragma unroll
            for (int h = 0; h < 2; h++) {
                int r = wm + mi * 16 + lg + h * 8;
                float v0 = fmaxf(acc[mi][ni][h * 2 + 0] + b2[c0],     0.f);
                float v1 = fmaxf(acc[mi][ni][h * 2 + 1] + b2[c0 + 1], 0.f);
                *(__half2*)&h1p[(kb2 * 4096 + (r * 4 + (ck ^ ((r >> 1) & 3))) * 16 + (c0 & 7) * 2) / 2]
                    = __floats2half2_rn(v0, v1);
            }
        }
    }
    {
        #pragma unroll
        for (int p = 0; p < 16; p++) {       // W3: 16 blocks of 32x64 (B-layout, BCHR=8)
            int q = tid + p * 256;
            int kb = q >> 8, rem = q & 255, k = rem >> 3, c = rem & 7;
            CP16(wsto + kb * 4096 + (k * 8 + (c ^ (k & 7))) * 16,
                 &W3[(size_t)(kb * 32 + k) * 64 + c * 8]);
        }
        #pragma unroll
        for (int p = 0; p < 2; p++) {        // W4: 2 blocks of 32x64
            int q = tid + p * 256;
            int kb = q >> 8, rem = q & 255, k = rem >> 3, c = rem & 7;
            CP16(wsto + 65536 + kb * 4096 + (k * 8 + (c ^ (k & 7))) * 16,
                 &W4[(size_t)(kb * 32 + k) * 64 + c * 8]);
        }
        CP_COMMIT();
        CP_WAIT(0);
        __syncthreads();
    }

    // ---- phase C: h3 = relu(h2 @ W3 + b3), K=512, N=64 (warp tile 32x16) ----
    float ac2[2][2][4];
    #pragma unroll
    for (int mi = 0; mi < 2; mi++)
        #pragma unroll
        for (int ni = 0; ni < 2; ni++)
            #pragma unroll
            for (int j = 0; j < 4; j++) ac2[mi][ni][j] = 0.f;

    for (int kt = 0; kt < 16; kt++) {
        #pragma unroll
        for (int s = 0; s < 2; s++) {
            uint32_t af[2][4], bf1[4];
            #pragma unroll
            for (int mi = 0; mi < 2; mi++) {
                int r = wm + mi * 16 + (lane & 15);
                int c = s * 2 + (lane >> 4);
                ldsm_x4(af[mi], h1o + kt * 4096 + (r * 4 + (c ^ ((r >> 1) & 3))) * 16);
            }
            {
                int k = s * 16 + (lane & 15);
                int c = (wn3 >> 3) + (lane >> 4);
                ldsm_x4_t(bf1, wsto + kt * 4096 + (k * 8 + (c ^ (k & 7))) * 16);
            }
            #pragma unroll
            for (int mi = 0; mi < 2; mi++)
                #pragma unroll
                for (int ni = 0; ni < 2; ni++)
                    mma_f16(ac2[mi][ni], af[mi][0], af[mi][1], af[mi][2], af[mi][3],
                            bf1[ni * 2], bf1[ni * 2 + 1]);
        }
    }

    // h3 -> node area (A-swizzled, 2 blocks)
    #pragma unroll
    for (int mi = 0; mi < 2; mi++) {
        #pragma unroll
        for (int ni = 0; ni < 2; ni++) {
            int c0 = wn3 + ni * 8 + lc * 2;
            int kb = c0 >> 5, ck = (c0 >> 3) & 3;
            #pragma unroll
            for (int h = 0; h < 2; h++) {
                int r = wm + mi * 16 + lg + h * 8;
                float v0 = fmaxf(ac2[mi][ni][h * 2 + 0] + b3[c0],     0.f);
                float v1 = fmaxf(ac2[mi][ni][h * 2 + 1] + b3[c0 + 1], 0.f);
                *(__half2*)&nodep[(kb * 4096 + (r * 4 + (ck ^ ((r >> 1) & 3))) * 16 + (c0 & 7) * 2) / 2]
                    = __floats2half2_rn(v0, v1);
            }
        }
    }
    __syncthreads();

    // ---- phase D: edge = relu(h3 @ W4 + b4), K=64 ----
    #pragma unroll
    for (int mi = 0; mi < 2; mi++)
        #pragma unroll
        for (int ni = 0; ni < 2; ni++)
            #pragma unroll
            for (int j = 0; j < 4; j++) ac2[mi][ni][j] = 0.f;

    #pragma unroll
    for (int t = 0; t < 2; t++) {
        #pragma unroll
        for (int s = 0; s < 2; s++) {
            uint32_t af[2][4], bf1[4];
            #pragma unroll
            for (int mi = 0; mi < 2; mi++) {
                int r = wm + mi * 16 + (lane & 15);
                int c = s * 2 + (lane >> 4);
                ldsm_x4(af[mi], nodeo + t * 4096 + (r * 4 + (c ^ ((r >> 1) & 3))) * 16);
            }
            {
                int k = s * 16 + (lane & 15);
                int c = (wn3 >> 3) + (lane >> 4);
                ldsm_x4_t(bf1, wsto + 65536 + t * 4096 + (k * 8 + (c ^ (k & 7))) * 16);
            }
            #pragma unroll
            for (int mi = 0; mi < 2; mi++)
                #pragma unroll
                for (int ni = 0; ni < 2; ni++)
                    mma_f16(ac2[mi][ni], af[mi][0], af[mi][1], af[mi][2], af[mi][3],
                            bf1[ni * 2], bf1[ni * 2 + 1]);
        }
    }

    // epilogue: edgeT[r, b*64+e]
    #pragma unroll
    for (int mi = 0; mi < 2; mi++) {
        #pragma unroll
        for (int ni = 0; ni < 2; ni++) {
            int c0 = wn3 + ni * 8 + lc * 2;
            #pragma unroll
            for (int h = 0; h < 2; h++) {
                int row = row0 + wm + mi * 16 + lg + h * 8;
                float v0 = fmaxf(ac2[mi][ni][h * 2 + 0] + b4[c0],     0.f);
                float v1 = fmaxf(ac2[mi][ni][h * 2 + 1] + b4[c0 + 1], 0.f);
                int b = row >> 14, r = row & 16383;
                *(__half2*)&C[(size_t)r * 512 + (b << 6) + c0] = __floats2half2_rn(v0, v1);
            }
        }
    }
}

// ---------------- fp16 cp.async + ldmatrix GEMM (4-stage, dynamic smem) ------
// MODE: 0 = fp16 out  1 = gather-scatter fp16 node  3 = atomic fp32  4 = fp32 out
template<int BM, int BN, int MODE, bool RELU>
__global__ __launch_bounds__((BM/64)*(BN/32)*32, 2) void hmma_gemm(
    const __half* __restrict__ A, const __half* __restrict__ W,
    const float* __restrict__ bias, void* __restrict__ C,
    int N, int lda, int klen, int off)
{
    constexpr int BK = 32, STAGES = 4;
    constexpr int NW_N = BN / 32;
    constexpr int THREADS = (BM/64) * NW_N * 32;
    constexpr int ACH = BM * 4;
    constexpr int BCHR = BN / 8;
    constexpr int BCH = BK * BCHR;
    constexpr int APT = ACH / THREADS, BPT = BCH / THREADS;
    extern __shared__ __align__(16) char dynsm[];
    const uint32_t a_s0 = smem_u32(dynsm);
    const uint32_t b_s0 = a_s0 + STAGES * BM * BK * 2;

    const int tid = threadIdx.x, lane = tid & 31, wid = tid >> 5;
    const int wm = (wid / NW_N) * 64, wn = (wid % NW_N) * 32;
    const int row0 = blockIdx.y * BM, col0 = blockIdx.x * BN;
    const int kstart = blockIdx.z * klen;
    const int ntiles = klen / BK;

    float acc[4][4][4];
    #pragma unroll
    for (int mi = 0; mi < 4; mi++)
        #pragma unroll
        for (int ni = 0; ni < 4; ni++)
            #pragma unroll
            for (int j = 0; j < 4; j++) acc[mi][ni][j] = 0.f;

    auto stage_copy = [&](int t, int st) {
        if (t < ntiles) {
            const int kk = kstart + t * BK;
            #pragma unroll
            for (int p = 0; p < APT; p++) {
                int q = tid + p * THREADS;
                int r = q >> 2, c = q & 3;
                uint32_t dst = a_s0 + (uint32_t)(st * BM * BK + (r * 4 + (c ^ ((r >> 1) & 3))) * 8) * 2;
                CP16(dst, &A[(size_t)(row0 + r) * lda + kk + c * 8]);
            }
            #pragma unroll
            for (int p = 0; p < BPT; p++) {
                int q = tid + p * THREADS;
                int k = q / BCHR, c = q % BCHR;
                uint32_t dst = b_s0 + (uint32_t)(st * BK * BN + (k * BCHR + (c ^ (k & 7))) * 8) * 2;
                CP16(dst, &W[(size_t)(kk + k) * N + col0 + c * 8]);
            }
        }
        CP_COMMIT();
    };

    #pragma unroll
    for (int t = 0; t < STAGES - 1; t++) stage_copy(t, t);

    for (int t = 0; t < ntiles; t++) {
        CP_WAIT(STAGES - 2);
        __syncthreads();
        stage_copy(t + STAGES - 1, (t + STAGES - 1) % STAGES);
        const int st = t % STAGES;
        const uint32_t abase = a_s0 + (uint32_t)(st * BM * BK) * 2;
        const uint32_t bbase = b_s0 + (uint32_t)(st * BK * BN) * 2;
        #pragma unroll
        for (int s = 0; s < 2; s++) {
            uint32_t af[4][4], bf[2][4];
            #pragma unroll
            for (int mi = 0; mi < 4; mi++) {
                int r = wm + mi * 16 + (lane & 15);
                int c = s * 2 + (lane >> 4);
                ldsm_x4(af[mi], abase + (uint32_t)((r * 4 + (c ^ ((r >> 1) & 3))) * 16));
            }
            #pragma unroll
            for (int np = 0; np < 2; np++) {
                int k = s * 16 + (lane & 15);
                int c = (wn >> 3) + np * 2 + (lane >> 4);
                ldsm_x4_t(bf[np], bbase + (uint32_t)((k * BCHR + (c ^ (k & 7))) * 16));
            }
            #pragma unroll
            for (int mi = 0; mi < 4; mi++)
                #pragma unroll
                for (int ni = 0; ni < 4; ni++)
                    mma_f16(acc[mi][ni], af[mi][0], af[mi][1], af[mi][2], af[mi][3],
                            bf[ni >> 1][(ni & 1) * 2], bf[ni >> 1][(ni & 1) * 2 + 1]);
        }
    }

    // epilogue
    const int lc = lane & 3, lg = lane >> 2;
    #pragma unroll
    for (int mi = 0; mi < 4; mi++) {
        int r0 = row0 + wm + mi * 16 + lg;
        #pragma unroll
        for (int ni = 0; ni < 4; ni++) {
            int c0 = col0 + wn + ni * 8 + lc * 2;
            #pragma unroll
            for (int h = 0; h < 2; h++) {
                int row = r0 + h * 8;
                float v0 = acc[mi][ni][h * 2 + 0];
                float v1 = acc[mi][ni][h * 2 + 1];
                if (MODE == 0 || MODE == 4) {
                    v0 += bias[c0]; v1 += bias[c0 + 1];
                    if (RELU) { v0 = fmaxf(v0, 0.f); v1 = fmaxf(v1, 0.f); }
                }
                if (MODE == 0) {
                    *(__half2*)&((__half*)C)[(size_t)row * N + c0] = __floats2half2_rn(v0, v1);
                } else if (MODE == 1) {
                    int b = c0 >> 5, d = c0 & 31;
                    *(__half2*)&((__half*)C)[(((size_t)b << 14) + row) * 64 + off + d] =
                        __floats2half2_rn(v0, v1);
                } else if (MODE == 3) {
                    atomicAdd(&((float*)C)[(size_t)row * N + c0], v0);
                    atomicAdd(&((float*)C)[(size_t)row * N + c0 + 1], v1);
                } else {
                    ((float*)C)[(size_t)row * N + c0]     = v0;
                    ((float*)C)[(size_t)row * N + c0 + 1] = v1;
                }
            }
        }
    }
}

// ---------------- transpose+convert: RT_h[r][n] = (half)R[n][r]; opt Rh copy --
__global__ __launch_bounds__(256) void transpose_h_kernel(
    const float* __restrict__ R, __half* __restrict__ RT, __half* Rh)
{
    __shared__ __half sm[32][33];
    const int tx = threadIdx.x & 31, ty = threadIdx.x >> 5;
    const int rb = blockIdx.x * 32, nb = blockIdx.y * 32;
    #pragma unroll
    for (int j = 0; j < 4; j++) {
        int n = nb + ty + j * 8, r = rb + tx;
        __half h = __float2half_rn(R[(size_t)n * R_ + r]);
        if (Rh) Rh[(size_t)n * R_ + r] = h;
        sm[ty + j * 8][tx] = h;
    }
    __syncthreads();
    #pragma unroll
    for (int j = 0; j < 4; j++) {
        int r = rb + ty + j * 8, n = nb + tx;
        RT[(size_t)r * N_ + n] = sm[tx][ty + j * 8];
    }
}

// ---------------- small utility kernels --------------------------------------
__global__ void f2h_kernel(const float* __restrict__ src, __half* __restrict__ dst, int n) {
    int i = blockIdx.x * blockDim.x + threadIdx.x;
    if (i < n) dst[i] = __float2half_rn(src[i]);
}

__global__ void f2h4_kernel(const float* s1, __half* d1,
                            const float* s2, __half* d2,
                            const float* s3, __half* d3,
                            const float* s4, __half* d4) {
    const int n1 = 64 * HID_, n2 = HID_ * 64, n3 = 64 * 64, n4 = 96 * HID_;
    int i = blockIdx.x * blockDim.x + threadIdx.x;
    if (i < n1) d1[i] = __float2half_rn(s1[i]);
    else if (i < n1 + n2) d2[i - n1] = __float2half_rn(s2[i - n1]);
    else if (i < n1 + n2 + n3) d3[i - n1 - n2] = __float2half_rn(s3[i - n1 - n2]);
    else if (i < n1 + n2 + n3 + n4) d4[i - n1 - n2 - n3] = __float2half_rn(s4[i - n1 - n2 - n3]);
}

__global__ void pack_objT_h_kernel(const float* __restrict__ obj, __half* __restrict__ objT) {
    int i = blockIdx.x * blockDim.x + threadIdx.x;
    if (i < N_ * 256) {
        int n = i >> 8, c = i & 255;
        int b = c >> 5, d = c & 31;
        objT[i] = __float2half_rn(obj[((size_t)b * N_ + n) * 32 + d]);
    }
}

__global__ void zero_kernel(float* p, int n) {
    int i = blockIdx.x * blockDim.x + threadIdx.x;
    if (i < n) p[i] = 0.f;
}

__global__ void concat_h_kernel(const float* __restrict__ obj,
                                const float* __restrict__ agg2,
                                __half* __restrict__ upd) {
    int i = blockIdx.x * blockDim.x + threadIdx.x;
    if (i < NROWS * 96) {
        int row = i / 96, j = i % 96;
        int b = row >> 10, n = row & 1023;
        float v = (j < 32) ? obj[(size_t)row * 32 + j]
                           : agg2[(size_t)n * 512 + (b << 6) + (j - 32)];
        upd[i] = __float2half_rn(v);
    }
}

// ---------------- SIMT fp32 GEMM (tiny final layer) --------------------------
template<int BM, int BN, int BK, int TM, int TN, bool RELU>
__global__ __launch_bounds__((BM/TM)*(BN/TN)) void gemm_kernel(
    const float* __restrict__ A, const float* __restrict__ W,
    const float* __restrict__ bias, float* __restrict__ C,
    int M, int K, int N)
{
    __shared__ float As[BK][BM];
    __shared__ float Ws[BK][BN];
    const int nthr = (BM / TM) * (BN / TN);
    const int tid = threadIdx.x;
    const int tn = tid % (BN / TN);
    const int tm = tid / (BN / TN);
    const int row0 = blockIdx.y * BM;
    const int col0 = blockIdx.x * BN;

    float acc[TM][TN];
    #pragma unroll
    for (int m = 0; m < TM; m++)
        #pragma unroll
        for (int n = 0; n < TN; n++) acc[m][n] = 0.f;

    for (int k0 = 0; k0 < K; k0 += BK) {
        #pragma unroll
        for (int i = tid * 4; i < BM * BK; i += nthr * 4) {
            int r = i / BK, c = i % BK;
            float4 v = *(const float4*)&A[(size_t)(row0 + r) * K + k0 + c];
            As[c + 0][r] = v.x; As[c + 1][r] = v.y;
            As[c + 2][r] = v.z; As[c + 3][r] = v.w;
        }
        #pragma unroll
        for (int i = tid * 4; i < BK * BN; i += nthr * 4) {
            int r = i / BN, c = i % BN;
            *(float4*)&Ws[r][c] = *(const float4*)&W[(size_t)(k0 + r) * N + col0 + c];
        }
        __syncthreads();
        #pragma unroll
        for (int k = 0; k < BK; k++) {
            float a[TM], b[TN];
            #pragma unroll
            for (int m = 0; m < TM; m++) a[m] = As[k][tm * TM + m];
            #pragma unroll
            for (int n = 0; n < TN; n++) b[n] = Ws[k][tn * TN + n];
            #pragma unroll
            for (int m = 0; m < TM; m++)
                #pragma unroll
                for (int n = 0; n < TN; n++) acc[m][n] += a[m] * b[n];
        }
        __syncthreads();
    }
    #pragma unroll
    for (int m = 0; m < TM; m++) {
        int row = row0 + tm * TM + m;
        #pragma unroll
        for (int n = 0; n < TN; n++) {
            int col = col0 + tn * TN + n;
            float v = acc[m][n] + bias[col];
            if (RELU) v = fmaxf(v, 0.f);
            C[(size_t)row * N + col] = v;
        }
    }
}

// ---------------- launch ----------------------------------------------------
#define HSMEM (4 * (128 * 32 + 32 * 128) * 2)       // 65536

extern "C" void kernel_launch(void* const* d_in, const int* in_sizes, int n_in,
                              void* d_out, int out_size) {
    const float* obj = (const float*)d_in[0];
    const float* Rs  = (const float*)d_in[1];
    const float* Rrm = (const float*)d_in[2];
    const float* rw1 = (const float*)d_in[3];  const float* rb1 = (const float*)d_in[4];
    const float* rw2 = (const float*)d_in[5];  const float* rb2 = (const float*)d_in[6];
    const float* rw3 = (const float*)d_in[7];  const float* rb3 = (const float*)d_in[8];
    const float* rw4 = (const float*)d_in[9];  const float* rb4 = (const float*)d_in[10];
    const float* ow1 = (const float*)d_in[11]; const float* ob1 = (const float*)d_in[12];
    const float* ow2 = (const float*)d_in[13]; const float* ob2 = (const float*)d_in[14];
    float* out = (float*)d_out;

    __half *RsT, *RrT, *Rrh, *objT, *node, *edgeT, *upd;
    __half *w1h, *w2h, *w3h, *w4h, *o1h;
    float *agg2, *hobj;
    cudaGetSymbolAddress((void**)&RsT,  gh_RsT);
    cudaGetSymbolAddress((void**)&RrT,  gh_RrT);
    cudaGetSymbolAddress((void**)&Rrh,  gh_Rr);
    cudaGetSymbolAddress((void**)&objT, gh_objT);
    cudaGetSymbolAddress((void**)&node, gh_node);
    cudaGetSymbolAddress((void**)&edgeT,gh_edgeT);
    cudaGetSymbolAddress((void**)&upd,  gh_upd);
    cudaGetSymbolAddress((void**)&agg2, g_agg);
    cudaGetSymbolAddress((void**)&hobj, g_hobj);
    cudaGetSymbolAddress((void**)&w1h,  gh_w1);
    cudaGetSymbolAddress((void**)&w2h,  gh_w2);
    cudaGetSymbolAddress((void**)&w3h,  gh_w3);
    cudaGetSymbolAddress((void**)&w4h,  gh_w4);
    cudaGetSymbolAddress((void**)&o1h,  gh_o1);

    cudaFuncSetAttribute(hmma_gemm<128, 128, 1, false>,
                         cudaFuncAttributeMaxDynamicSharedMemorySize, HSMEM);
    cudaFuncSetAttribute(hmma_gemm<128, 128, 3, false>,
                         cudaFuncAttributeMaxDynamicSharedMemorySize, HSMEM);
    cudaFuncSetAttribute(hmma_gemm<128, 128, 4, true>,
                         cudaFuncAttributeMaxDynamicSharedMemorySize, HSMEM);
    cudaFuncSetAttribute(rmlp_kernel,
                         cudaFuncAttributeMaxDynamicSharedMemorySize, RMLP_SMEM);

    // 0. conversions
    transpose_h_kernel<<<dim3(R_ / 32, N_ / 32), 256>>>(Rs,  RsT, nullptr);
    transpose_h_kernel<<<dim3(R_ / 32, N_ / 32), 256>>>(Rrm, RrT, Rrh);
    pack_objT_h_kernel<<<(N_ * 256 + 255) / 256, 256>>>(obj, objT);
    f2h_kernel<<<(HID_ * HID_ + 255) / 256, 256>>>(rw2, w2h, HID_ * HID_);
    {
        int total = 64 * HID_ + HID_ * 64 + 64 * 64 + 96 * HID_;
        f2h4_kernel<<<(total + 255) / 256, 256>>>(rw1, w1h, rw3, w3h, rw4, w4h, ow1, o1h);
    }

    // 1. gathers: node[b,r,off+d] = sum_n RT[r,n] * objT[n, b*32+d]
    hmma_gemm<128, 128, 1, false><<<dim3(2, R_ / 128), 256, HSMEM>>>(
        RsT, objT, nullptr, node, 256, N_, N_, 0);
    hmma_gemm<128, 128, 1, false><<<dim3(2, R_ / 128), 256, HSMEM>>>(
        RrT, objT, nullptr, node, 256, N_, N_, 32);

    // 2. fused relational MLP (node -> edgeT, all four layers, activations in smem)
    rmlp_kernel<<<MROWS / 64, 256, RMLP_SMEM>>>(
        node, w1h, rb1, w2h, rb2, w3h, rb3, w4h, rb4, edgeT);

    // 3. aggregate: agg2[n, b*64+e] = sum_r Rr[n,r] * edgeT[r, b*64+e] (split-K=8)
    zero_kernel<<<(N_ * 512 + 255) / 256, 256>>>(agg2, N_ * 512);
    hmma_gemm<128, 128, 3, false><<<dim3(4, N_ / 128, 8), 256, HSMEM>>>(
        Rrh, edgeT, nullptr, agg2, 512, R_, R_ / 8, 0);

    // 4. object MLP
    concat_h_kernel<<<(NROWS * 96 + 255) / 256, 256>>>(obj, agg2, upd);
    hmma_gemm<128, 128, 4, true><<<dim3(HID_ / 128, NROWS / 128), 256, HSMEM>>>(
        upd, o1h, ob1, hobj, HID_, 96, 96, 0);
    gemm_kernel<128, 32, 8, 8, 2, false><<<dim3(1, NROWS / 128), 256>>>(
        hobj, ow2, ob2, out, NROWS, HID_, 32);
}

// round 15
// speedup vs baseline: 6.0892x; 1.0074x over previous
#include <cuda_runtime.h>
#include <cuda_fp16.h>
#include <cstdint>

// Problem dims
#define B_    8
#define N_    1024
#define R_    16384
#define HID_  512
#define MROWS (B_ * R_)      // 131072
#define NROWS (B_ * N_)      // 8192

// ---------------- scratch (device globals; no allocations allowed) ----------
__device__ __align__(128) __half gh_RsT [R_ * N_];      // Rs^T fp16 [16384,1024]
__device__ __align__(128) __half gh_RrT [R_ * N_];      // Rr^T fp16 [16384,1024]
__device__ __align__(128) __half gh_Rr  [N_ * R_];      // Rr fp16 [1024,16384]
__device__ __align__(128) __half gh_objT[N_ * 256];     // objT fp16 [1024,256] col=b*32+d
__device__ __align__(128) __half gh_node[MROWS * 64];   // node fp16
__device__ __align__(128) __half gh_edgeT[R_ * 512];    // edgeT fp16 [16384,512] col=b*64+e
__device__ __align__(128) __half gh_upd [NROWS * 96];
__device__ __align__(128) float  g_agg  [N_ * 512];     // agg fp32 [1024,512]
__device__ __align__(128) float  g_hobj [NROWS * HID_];
// fp16 weights
__device__ __align__(128) __half gh_w1[64 * HID_];
__device__ __align__(128) __half gh_w2[HID_ * HID_];
__device__ __align__(128) __half gh_w3[HID_ * 64];
__device__ __align__(128) __half gh_w4[64 * 64];
__device__ __align__(128) __half gh_o1[96 * HID_];

// ---------------- asm helpers ------------------------------------------------
__device__ __forceinline__ void mma_f16(float d[4], uint32_t a0, uint32_t a1,
                                        uint32_t a2, uint32_t a3,
                                        uint32_t b0, uint32_t b1) {
    asm volatile(
        "mma.sync.aligned.m16n8k16.row.col.f32.f16.f16.f32 "
        "{%0,%1,%2,%3},{%4,%5,%6,%7},{%8,%9},{%0,%1,%2,%3};\n"
        : "+f"(d[0]), "+f"(d[1]), "+f"(d[2]), "+f"(d[3])
        : "r"(a0), "r"(a1), "r"(a2), "r"(a3), "r"(b0), "r"(b1));
}
__device__ __forceinline__ void ldsm_x4(uint32_t r[4], uint32_t addr) {
    asm volatile("ldmatrix.sync.aligned.m8n8.x4.shared.b16 {%0,%1,%2,%3}, [%4];"
                 : "=r"(r[0]), "=r"(r[1]), "=r"(r[2]), "=r"(r[3]) : "r"(addr));
}
__device__ __forceinline__ void ldsm_x4_t(uint32_t r[4], uint32_t addr) {
    asm volatile("ldmatrix.sync.aligned.m8n8.x4.trans.shared.b16 {%0,%1,%2,%3}, [%4];"
                 : "=r"(r[0]), "=r"(r[1]), "=r"(r[2]), "=r"(r[3]) : "r"(addr));
}
#define CP16(dst, src) \
    asm volatile("cp.async.cg.shared.global [%0], [%1], 16;" :: "r"(dst), "l"(src))
#define CP_COMMIT() asm volatile("cp.async.commit_group;")
#define CP_WAIT(n)  asm volatile("cp.async.wait_group %0;" :: "n"(n))

__device__ __forceinline__ uint32_t smem_u32(const void* p) {
    return (uint32_t)__cvta_generic_to_shared(p);
}

// ================= fused relational MLP =======================================
// edgeT = relu(relu(relu(relu(node@W1+b1)@W2+b2)@W3+b3)@W4+b4)
// BM=64 rows/CTA, 256 threads (8 warps: 2M x 4N for A/B phases, 2M x 4N16 for C/D).
#define RMLP_SMEM (65536 + 131072 + 8192)

__global__ __launch_bounds__(256, 1) void rmlp_kernel(
    const __half* __restrict__ Anode,
    const __half* __restrict__ W1, const float* __restrict__ b1,
    const __half* __restrict__ W2, const float* __restrict__ b2,
    const __half* __restrict__ W3, const float* __restrict__ b3,
    const __half* __restrict__ W4, const float* __restrict__ b4,
    __half* __restrict__ C)
{
    extern __shared__ __align__(16) char dynsm[];
    const uint32_t s0 = smem_u32(dynsm);
    const uint32_t h1o = s0;
    const uint32_t wsto = s0 + 65536;
    const uint32_t nodeo = s0 + 196608;
    __half* h1p = (__half*)dynsm;
    __half* nodep = (__half*)(dynsm + 196608);

    const int tid = threadIdx.x, lane = tid & 31, wid = tid >> 5;
    const int wm = (wid >> 2) * 32;
    const int wn = (wid & 3) * 128;
    const int wn3 = (wid & 3) * 16;
    const int row0 = blockIdx.x * 64;
    const int lc = lane & 3, lg = lane >> 2;

    // ---- prologue: node tile + W1 ----
    {
        #pragma unroll
        for (int p = 0; p < 2; p++) {
            int q = tid * 2 + p;
            int r = q >> 3, c8 = q & 7, t = c8 >> 2, c = c8 & 3;
            CP16(nodeo + t * 4096 + (r * 4 + (c ^ ((r >> 1) & 3))) * 16,
                 &Anode[(size_t)(row0 + r) * 64 + c8 * 8]);
        }
        #pragma unroll
        for (int p = 0; p < 16; p++) {
            int q = tid + p * 256;
            int kb = q >> 11, rem = q & 2047, k = rem >> 6, c = rem & 63;
            CP16(wsto + kb * 32768 + (k * 64 + (c ^ (k & 7))) * 16,
                 &W1[(size_t)(kb * 32 + k) * 512 + c * 8]);
        }
        CP_COMMIT();
        CP_WAIT(0);
        __syncthreads();
    }

    float acc[2][16][4];
    #pragma unroll
    for (int mi = 0; mi < 2; mi++)
        #pragma unroll
        for (int ni = 0; ni < 16; ni++)
            #pragma unroll
            for (int j = 0; j < 4; j++) acc[mi][ni][j] = 0.f;

    // ---- phase A: h1 = relu(node @ W1 + b1), K=64 ----
    #pragma unroll
    for (int t = 0; t < 2; t++) {
        #pragma unroll
        for (int s = 0; s < 2; s++) {
            uint32_t af[2][4], bf[8][4];
            #pragma unroll
            for (int mi = 0; mi < 2; mi++) {
                int r = wm + mi * 16 + (lane & 15);
                int c = s * 2 + (lane >> 4);
                ldsm_x4(af[mi], nodeo + t * 4096 + (r * 4 + (c ^ ((r >> 1) & 3))) * 16);
            }
            #pragma unroll
            for (int np = 0; np < 8; np++) {
                int k = s * 16 + (lane & 15);
                int c = (wn >> 3) + np * 2 + (lane >> 4);
                ldsm_x4_t(bf[np], wsto + t * 32768 + (k * 64 + (c ^ (k & 7))) * 16);
            }
            #pragma unroll
            for (int mi = 0; mi < 2; mi++)
                #pragma unroll
                for (int ni = 0; ni < 16; ni++)
                    mma_f16(acc[mi][ni], af[mi][0], af[mi][1], af[mi][2], af[mi][3],
                            bf[ni >> 1][(ni & 1) * 2], bf[ni >> 1][(ni & 1) * 2 + 1]);
        }
    }
    __syncthreads();

    #pragma unroll
    for (int mi = 0; mi < 2; mi++) {
        #pragma unroll
        for (int ni = 0; ni < 16; ni++) {
            int c0 = wn + ni * 8 + lc * 2;
            int kb2 = c0 >> 5, ck = (c0 >> 3) & 3;
            #pragma unroll
            for (int h = 0; h < 2; h++) {
                int r = wm + mi * 16 + lg + h * 8;
                float v0 = fmaxf(acc[mi][ni][h * 2 + 0] + b1[c0],     0.f);
                float v1 = fmaxf(acc[mi][ni][h * 2 + 1] + b1[c0 + 1], 0.f);
                *(__half2*)&h1p[(kb2 * 4096 + (r * 4 + (ck ^ ((r >> 1) & 3))) * 16 + (c0 & 7) * 2) / 2]
                    = __floats2half2_rn(v0, v1);
            }
        }
    }
    auto w2_stage = [&](int t, int st) {
        if (t < 16) {
            #pragma unroll
            for (int p = 0; p < 8; p++) {
                int q = tid + p * 256;
                int k = q >> 6, c = q & 63;
                CP16(wsto + st * 32768 + (k * 64 + (c ^ (k & 7))) * 16,
                     &W2[(size_t)(t * 32 + k) * 512 + c * 8]);
            }
        }
        CP_COMMIT();
    };
    w2_stage(0, 0); w2_stage(1, 1); w2_stage(2, 2);
    __syncthreads();

    #pragma unroll
    for (int mi = 0; mi < 2; mi++)
        #pragma unroll
        for (int ni = 0; ni < 16; ni++)
            #pragma unroll
            for (int j = 0; j < 4; j++) acc[mi][ni][j] = 0.f;

    // ---- phase B: h2 = relu(h1 @ W2 + b2), K=512 ----
    for (int kt = 0; kt < 16; kt++) {
        CP_WAIT(2);
        __syncthreads();
        w2_stage(kt + 3, (kt + 3) & 3);
        const int st = kt & 3;
        #pragma unroll
        for (int s = 0; s < 2; s++) {
            uint32_t af[2][4], bf[8][4];
            #pragma unroll
            for (int mi = 0; mi < 2; mi++) {
                int r = wm + mi * 16 + (lane & 15);
                int c = s * 2 + (lane >> 4);
                ldsm_x4(af[mi], h1o + kt * 4096 + (r * 4 + (c ^ ((r >> 1) & 3))) * 16);
            }
            #pragma unroll
            for (int np = 0; np < 8; np++) {
                int k = s * 16 + (lane & 15);
                int c = (wn >> 3) + np * 2 + (lane >> 4);
                ldsm_x4_t(bf[np], wsto + st * 32768 + (k * 64 + (c ^ (k & 7))) * 16);
            }
            #pragma unroll
            for (int mi = 0; mi < 2; mi++)
                #pragma unroll
                for (int ni = 0; ni < 16; ni++)
                    mma_f16(acc[mi][ni], af[mi][0], af[mi][1], af[mi][2], af[mi][3],
                            bf[ni >> 1][(ni & 1) * 2], bf[ni >> 1][(ni & 1) * 2 + 1]);
        }
    }
    CP_WAIT(0);
    __syncthreads();

    #pragma unroll
    for (int mi = 0; mi < 2; mi++) {
        #pragma unroll
        for (int ni = 0; ni < 16; ni++) {
            int c0 = wn + ni * 8 + lc * 2;
            int kb2 = c0 >> 5, ck = (c0 >> 3) & 3;
            #pragma unroll
            for (int h = 0; h < 2; h++) {
                int r = wm + mi * 16 + lg + h * 8;
                float v0 = fmaxf(acc[mi][ni][h * 2 + 0] + b2[c0],     0.f);
                float v1 = fmaxf(acc[mi][ni][h * 2 + 1] + b2[c0 + 1], 0.f);
                *(__half2*)&h1p[(kb2 * 4096 + (r * 4 + (ck ^ ((r >> 1) & 3))) * 16 + (c0 & 7) * 2) / 2]
                    = __floats2half2_rn(v0, v1);
            }
        }
    }
    {
        #pragma unroll
        for (int p = 0; p < 16; p++) {
            int q = tid + p * 256;
            int kb = q >> 8, rem = q & 255, k = rem >> 3, c = rem & 7;
            CP16(wsto + kb * 4096 + (k * 8 + (c ^ (k & 7))) * 16,
                 &W3[(size_t)(kb * 32 + k) * 64 + c * 8]);
        }
        #pragma unroll
        for (int p = 0; p < 2; p++) {
            int q = tid + p * 256;
            int kb = q >> 8, rem = q & 255, k = rem >> 3, c = rem & 7;
            CP16(wsto + 65536 + kb * 4096 + (k * 8 + (c ^ (k & 7))) * 16,
                 &W4[(size_t)(kb * 32 + k) * 64 + c * 8]);
        }
        CP_COMMIT();
        CP_WAIT(0);
        __syncthreads();
    }

    // ---- phase C: h3 = relu(h2 @ W3 + b3) ----
    float ac2[2][2][4];
    #pragma unroll
    for (int mi = 0; mi < 2; mi++)
        #pragma unroll
        for (int ni = 0; ni < 2; ni++)
            #pragma unroll
            for (int j = 0; j < 4; j++) ac2[mi][ni][j] = 0.f;

    for (int kt = 0; kt < 16; kt++) {
        #pragma unroll
        for (int s = 0; s < 2; s++) {
            uint32_t af[2][4], bf1[4];
            #pragma unroll
            for (int mi = 0; mi < 2; mi++) {
                int r = wm + mi * 16 + (lane & 15);
                int c = s * 2 + (lane >> 4);
                ldsm_x4(af[mi], h1o + kt * 4096 + (r * 4 + (c ^ ((r >> 1) & 3))) * 16);
            }
            {
                int k = s * 16 + (lane & 15);
                int c = (wn3 >> 3) + (lane >> 4);
                ldsm_x4_t(bf1, wsto + kt * 4096 + (k * 8 + (c ^ (k & 7))) * 16);
            }
            #pragma unroll
            for (int mi = 0; mi < 2; mi++)
                #pragma unroll
                for (int ni = 0; ni < 2; ni++)
                    mma_f16(ac2[mi][ni], af[mi][0], af[mi][1], af[mi][2], af[mi][3],
                            bf1[ni * 2], bf1[ni * 2 + 1]);
        }
    }

    #pragma unroll
    for (int mi = 0; mi < 2; mi++) {
        #pragma unroll
        for (int ni = 0; ni < 2; ni++) {
            int c0 = wn3 + ni * 8 + lc * 2;
            int kb = c0 >> 5, ck = (c0 >> 3) & 3;
            #pragma unroll
            for (int h = 0; h < 2; h++) {
                int r = wm + mi * 16 + lg + h * 8;
                float v0 = fmaxf(ac2[mi][ni][h * 2 + 0] + b3[c0],     0.f);
                float v1 = fmaxf(ac2[mi][ni][h * 2 + 1] + b3[c0 + 1], 0.f);
                *(__half2*)&nodep[(kb * 4096 + (r * 4 + (ck ^ ((r >> 1) & 3))) * 16 + (c0 & 7) * 2) / 2]
                    = __floats2half2_rn(v0, v1);
            }
        }
    }
    __syncthreads();

    // ---- phase D: edge = relu(h3 @ W4 + b4) ----
    #pragma unroll
    for (int mi = 0; mi < 2; mi++)
        #pragma unroll
        for (int ni = 0; ni < 2; ni++)
            #pragma unroll
            for (int j = 0; j < 4; j++) ac2[mi][ni][j] = 0.f;

    #pragma unroll
    for (int t = 0; t < 2; t++) {
        #pragma unroll
        for (int s = 0; s < 2; s++) {
            uint32_t af[2][4], bf1[4];
            #pragma unroll
            for (int mi = 0; mi < 2; mi++) {
                int r = wm + mi * 16 + (lane & 15);
                int c = s * 2 + (lane >> 4);
                ldsm_x4(af[mi], nodeo + t * 4096 + (r * 4 + (c ^ ((r >> 1) & 3))) * 16);
            }
            {
                int k = s * 16 + (lane & 15);
                int c = (wn3 >> 3) + (lane >> 4);
                ldsm_x4_t(bf1, wsto + 65536 + t * 4096 + (k * 8 + (c ^ (k & 7))) * 16);
            }
            #pragma unroll
            for (int mi = 0; mi < 2; mi++)
                #pragma unroll
                for (int ni = 0; ni < 2; ni++)
                    mma_f16(ac2[mi][ni], af[mi][0], af[mi][1], af[mi][2], af[mi][3],
                            bf1[ni * 2], bf1[ni * 2 + 1]);
        }
    }

    #pragma unroll
    for (int mi = 0; mi < 2; mi++) {
        #pragma unroll
        for (int ni = 0; ni < 2; ni++) {
            int c0 = wn3 + ni * 8 + lc * 2;
            #pragma unroll
            for (int h = 0; h < 2; h++) {
                int row = row0 + wm + mi * 16 + lg + h * 8;
                float v0 = fmaxf(ac2[mi][ni][h * 2 + 0] + b4[c0],     0.f);
                float v1 = fmaxf(ac2[mi][ni][h * 2 + 1] + b4[c0 + 1], 0.f);
                int b = row >> 14, r = row & 16383;
                *(__half2*)&C[(size_t)r * 512 + (b << 6) + c0] = __floats2half2_rn(v0, v1);
            }
        }
    }
}

// ---------------- fp16 cp.async + ldmatrix GEMM (4-stage, dynamic smem) ------
// MODE: 0 = fp16 out  1 = gather-scatter  3 = atomic fp32  4 = fp32 out
// MODE 5 = dual-gather: blockIdx.z selects A (0) / A2 (1), off = z*32, kstart=0.
template<int BM, int BN, int MODE, bool RELU>
__global__ __launch_bounds__((BM/64)*(BN/32)*32, 2) void hmma_gemm(
    const __half* __restrict__ A, const __half* __restrict__ A2,
    const __half* __restrict__ W,
    const float* __restrict__ bias, void* __restrict__ C,
    int N, int lda, int klen, int off)
{
    constexpr int BK = 32, STAGES = 4;
    constexpr int NW_N = BN / 32;
    constexpr int THREADS = (BM/64) * NW_N * 32;
    constexpr int ACH = BM * 4;
    constexpr int BCHR = BN / 8;
    constexpr int BCH = BK * BCHR;
    constexpr int APT = ACH / THREADS, BPT = BCH / THREADS;
    extern __shared__ __align__(16) char dynsm[];
    const uint32_t a_s0 = smem_u32(dynsm);
    const uint32_t b_s0 = a_s0 + STAGES * BM * BK * 2;

    const int tid = threadIdx.x, lane = tid & 31, wid = tid >> 5;
    const int wm = (wid / NW_N) * 64, wn = (wid % NW_N) * 32;
    const int row0 = blockIdx.y * BM, col0 = blockIdx.x * BN;
    const __half* Ap = (MODE == 5 && blockIdx.z) ? A2 : A;
    const int kstart = (MODE == 5) ? 0 : blockIdx.z * klen;
    const int offv = (MODE == 5) ? (int)blockIdx.z * 32 : off;
    const int ntiles = klen / BK;

    float acc[4][4][4];
    #pragma unroll
    for (int mi = 0; mi < 4; mi++)
        #pragma unroll
        for (int ni = 0; ni < 4; ni++)
            #pragma unroll
            for (int j = 0; j < 4; j++) acc[mi][ni][j] = 0.f;

    auto stage_copy = [&](int t, int st) {
        if (t < ntiles) {
            const int kk = kstart + t * BK;
            #pragma unroll
            for (int p = 0; p < APT; p++) {
                int q = tid + p * THREADS;
                int r = q >> 2, c = q & 3;
                uint32_t dst = a_s0 + (uint32_t)(st * BM * BK + (r * 4 + (c ^ ((r >> 1) & 3))) * 8) * 2;
                CP16(dst, &Ap[(size_t)(row0 + r) * lda + kk + c * 8]);
            }
            #pragma unroll
            for (int p = 0; p < BPT; p++) {
                int q = tid + p * THREADS;
                int k = q / BCHR, c = q % BCHR;
                uint32_t dst = b_s0 + (uint32_t)(st * BK * BN + (k * BCHR + (c ^ (k & 7))) * 8) * 2;
                CP16(dst, &W[(size_t)(kk + k) * N + col0 + c * 8]);
            }
        }
        CP_COMMIT();
    };

    #pragma unroll
    for (int t = 0; t < STAGES - 1; t++) stage_copy(t, t);

    for (int t = 0; t < ntiles; t++) {
        CP_WAIT(STAGES - 2);
        __syncthreads();
        stage_copy(t + STAGES - 1, (t + STAGES - 1) % STAGES);
        const int st = t % STAGES;
        const uint32_t abase = a_s0 + (uint32_t)(st * BM * BK) * 2;
        const uint32_t bbase = b_s0 + (uint32_t)(st * BK * BN) * 2;
        #pragma unroll
        for (int s = 0; s < 2; s++) {
            uint32_t af[4][4], bf[2][4];
            #pragma unroll
            for (int mi = 0; mi < 4; mi++) {
                int r = wm + mi * 16 + (lane & 15);
                int c = s * 2 + (lane >> 4);
                ldsm_x4(af[mi], abase + (uint32_t)((r * 4 + (c ^ ((r >> 1) & 3))) * 16));
            }
            #pragma unroll
            for (int np = 0; np < 2; np++) {
                int k = s * 16 + (lane & 15);
                int c = (wn >> 3) + np * 2 + (lane >> 4);
                ldsm_x4_t(bf[np], bbase + (uint32_t)((k * BCHR + (c ^ (k & 7))) * 16));
            }
            #pragma unroll
            for (int mi = 0; mi < 4; mi++)
                #pragma unroll
                for (int ni = 0; ni < 4; ni++)
                    mma_f16(acc[mi][ni], af[mi][0], af[mi][1], af[mi][2], af[mi][3],
                            bf[ni >> 1][(ni & 1) * 2], bf[ni >> 1][(ni & 1) * 2 + 1]);
        }
    }

    // epilogue
    const int lc = lane & 3, lg = lane >> 2;
    #pragma unroll
    for (int mi = 0; mi < 4; mi++) {
        int r0 = row0 + wm + mi * 16 + lg;
        #pragma unroll
        for (int ni = 0; ni < 4; ni++) {
            int c0 = col0 + wn + ni * 8 + lc * 2;
            #pragma unroll
            for (int h = 0; h < 2; h++) {
                int row = r0 + h * 8;
                float v0 = acc[mi][ni][h * 2 + 0];
                float v1 = acc[mi][ni][h * 2 + 1];
                if (MODE == 0 || MODE == 4) {
                    v0 += bias[c0]; v1 += bias[c0 + 1];
                    if (RELU) { v0 = fmaxf(v0, 0.f); v1 = fmaxf(v1, 0.f); }
                }
                if (MODE == 0) {
                    *(__half2*)&((__half*)C)[(size_t)row * N + c0] = __floats2half2_rn(v0, v1);
                } else if (MODE == 1 || MODE == 5) {
                    int b = c0 >> 5, d = c0 & 31;
                    *(__half2*)&((__half*)C)[(((size_t)b << 14) + row) * 64 + offv + d] =
                        __floats2half2_rn(v0, v1);
                } else if (MODE == 3) {
                    atomicAdd(&((float*)C)[(size_t)row * N + c0], v0);
                    atomicAdd(&((float*)C)[(size_t)row * N + c0 + 1], v1);
                } else {
                    ((float*)C)[(size_t)row * N + c0]     = v0;
                    ((float*)C)[(size_t)row * N + c0 + 1] = v1;
                }
            }
        }
    }
}

// ---------------- dual transpose+convert (z: 0=Rs, 1=Rr+Rrh) ----------------
__global__ __launch_bounds__(256) void transpose2_h_kernel(
    const float* __restrict__ Rs, __half* __restrict__ RsT,
    const float* __restrict__ Rr, __half* __restrict__ RrT, __half* __restrict__ Rrh)
{
    __shared__ __half sm[32][33];
    const float* R = blockIdx.z ? Rr : Rs;
    __half* RT = blockIdx.z ? RrT : RsT;
    __half* Rh = blockIdx.z ? Rrh : nullptr;
    const int tx = threadIdx.x & 31, ty = threadIdx.x >> 5;
    const int rb = blockIdx.x * 32, nb = blockIdx.y * 32;
    #pragma unroll
    for (int j = 0; j < 4; j++) {
        int n = nb + ty + j * 8, r = rb + tx;
        __half h = __float2half_rn(R[(size_t)n * R_ + r]);
        if (Rh) Rh[(size_t)n * R_ + r] = h;
        sm[ty + j * 8][tx] = h;
    }
    __syncthreads();
    #pragma unroll
    for (int j = 0; j < 4; j++) {
        int r = rb + ty + j * 8, n = nb + tx;
        RT[(size_t)r * N_ + n] = sm[tx][ty + j * 8];
    }
}

// ---------------- small utility kernels --------------------------------------
// all weight conversions in one kernel (w1, w3, w4, o1, w2)
__global__ void f2h5_kernel(const float* s1, __half* d1,
                            const float* s2, __half* d2,
                            const float* s3, __half* d3,
                            const float* s4, __half* d4,
                            const float* s5, __half* d5) {
    const int n1 = 64 * HID_, n2 = HID_ * 64, n3 = 64 * 64, n4 = 96 * HID_;
    const int n5 = HID_ * HID_;
    int i = blockIdx.x * blockDim.x + threadIdx.x;
    if (i < n1) d1[i] = __float2half_rn(s1[i]);
    else if (i < n1 + n2) d2[i - n1] = __float2half_rn(s2[i - n1]);
    else if (i < n1 + n2 + n3) d3[i - n1 - n2] = __float2half_rn(s3[i - n1 - n2]);
    else if (i < n1 + n2 + n3 + n4) d4[i - n1 - n2 - n3] = __float2half_rn(s4[i - n1 - n2 - n3]);
    else if (i < n1 + n2 + n3 + n4 + n5) d5[i - n1 - n2 - n3 - n4] = __float2half_rn(s5[i - n1 - n2 - n3 - n4]);
}

__global__ void pack_objT_h_kernel(const float* __restrict__ obj, __half* __restrict__ objT) {
    int i = blockIdx.x * blockDim.x + threadIdx.x;
    if (i < N_ * 256) {
        int n = i >> 8, c = i & 255;
        int b = c >> 5, d = c & 31;
        objT[i] = __float2half_rn(obj[((size_t)b * N_ + n) * 32 + d]);
    }
}

__global__ void zero_kernel(float* p, int n) {
    int i = blockIdx.x * blockDim.x + threadIdx.x;
    if (i < n) p[i] = 0.f;
}

__global__ void concat_h_kernel(const float* __restrict__ obj,
                                const float* __restrict__ agg2,
                                __half* __restrict__ upd) {
    int i = blockIdx.x * blockDim.x + threadIdx.x;
    if (i < NROWS * 96) {
        int row = i / 96, j = i % 96;
        int b = row >> 10, n = row & 1023;
        float v = (j < 32) ? obj[(size_t)row * 32 + j]
                           : agg2[(size_t)n * 512 + (b << 6) + (j - 32)];
        upd[i] = __float2half_rn(v);
    }
}

// ---------------- SIMT fp32 GEMM (tiny final layer) --------------------------
template<int BM, int BN, int BK, int TM, int TN, bool RELU>
__global__ __launch_bounds__((BM/TM)*(BN/TN)) void gemm_kernel(
    const float* __restrict__ A, const float* __restrict__ W,
    const float* __restrict__ bias, float* __restrict__ C,
    int M, int K, int N)
{
    __shared__ float As[BK][BM];
    __shared__ float Ws[BK][BN];
    const int nthr = (BM / TM) * (BN / TN);
    const int tid = threadIdx.x;
    const int tn = tid % (BN / TN);
    const int tm = tid / (BN / TN);
    const int row0 = blockIdx.y * BM;
    const int col0 = blockIdx.x * BN;

    float acc[TM][TN];
    #pragma unroll
    for (int m = 0; m < TM; m++)
        #pragma unroll
        for (int n = 0; n < TN; n++) acc[m][n] = 0.f;

    for (int k0 = 0; k0 < K; k0 += BK) {
        #pragma unroll
        for (int i = tid * 4; i < BM * BK; i += nthr * 4) {
            int r = i / BK, c = i % BK;
            float4 v = *(const float4*)&A[(size_t)(row0 + r) * K + k0 + c];
            As[c + 0][r] = v.x; As[c + 1][r] = v.y;
            As[c + 2][r] = v.z; As[c + 3][r] = v.w;
        }
        #pragma unroll
        for (int i = tid * 4; i < BK * BN; i += nthr * 4) {
            int r = i / BN, c = i % BN;
            *(float4*)&Ws[r][c] = *(const float4*)&W[(size_t)(k0 + r) * N + col0 + c];
        }
        __syncthreads();
        #pragma unroll
        for (int k = 0; k < BK; k++) {
            float a[TM], b[TN];
            #pragma unroll
            for (int m = 0; m < TM; m++) a[m] = As[k][tm * TM + m];
            #pragma unroll
            for (int n = 0; n < TN; n++) b[n] = Ws[k][tn * TN + n];
            #pragma unroll
            for (int m = 0; m < TM; m++)
                #pragma unroll
                for (int n = 0; n < TN; n++) acc[m][n] += a[m] * b[n];
        }
        __syncthreads();
    }
    #pragma unroll
    for (int m = 0; m < TM; m++) {
        int row = row0 + tm * TM + m;
        #pragma unroll
        for (int n = 0; n < TN; n++) {
            int col = col0 + tn * TN + n;
            float v = acc[m][n] + bias[col];
            if (RELU) v = fmaxf(v, 0.f);
            C[(size_t)row * N + col] = v;
        }
    }
}

// ---------------- launch ----------------------------------------------------
#define HSMEM (4 * (128 * 32 + 32 * 128) * 2)       // 65536

extern "C" void kernel_launch(void* const* d_in, const int* in_sizes, int n_in,
                              void* d_out, int out_size) {
    const float* obj = (const float*)d_in[0];
    const float* Rs  = (const float*)d_in[1];
    const float* Rrm = (const float*)d_in[2];
    const float* rw1 = (const float*)d_in[3];  const float* rb1 = (const float*)d_in[4];
    const float* rw2 = (const float*)d_in[5];  const float* rb2 = (const float*)d_in[6];
    const float* rw3 = (const float*)d_in[7];  const float* rb3 = (const float*)d_in[8];
    const float* rw4 = (const float*)d_in[9];  const float* rb4 = (const float*)d_in[10];
    const float* ow1 = (const float*)d_in[11]; const float* ob1 = (const float*)d_in[12];
    const float* ow2 = (const float*)d_in[13]; const float* ob2 = (const float*)d_in[14];
    float* out = (float*)d_out;

    __half *RsT, *RrT, *Rrh, *objT, *node, *edgeT, *upd;
    __half *w1h, *w2h, *w3h, *w4h, *o1h;
    float *agg2, *hobj;
    cudaGetSymbolAddress((void**)&RsT,  gh_RsT);
    cudaGetSymbolAddress((void**)&RrT,  gh_RrT);
    cudaGetSymbolAddress((void**)&Rrh,  gh_Rr);
    cudaGetSymbolAddress((void**)&objT, gh_objT);
    cudaGetSymbolAddress((void**)&node, gh_node);
    cudaGetSymbolAddress((void**)&edgeT,gh_edgeT);
    cudaGetSymbolAddress((void**)&upd,  gh_upd);
    cudaGetSymbolAddress((void**)&agg2, g_agg);
    cudaGetSymbolAddress((void**)&hobj, g_hobj);
    cudaGetSymbolAddress((void**)&w1h,  gh_w1);
    cudaGetSymbolAddress((void**)&w2h,  gh_w2);
    cudaGetSymbolAddress((void**)&w3h,  gh_w3);
    cudaGetSymbolAddress((void**)&w4h,  gh_w4);
    cudaGetSymbolAddress((void**)&o1h,  gh_o1);

    cudaFuncSetAttribute(hmma_gemm<128, 128, 5, false>,
                         cudaFuncAttributeMaxDynamicSharedMemorySize, HSMEM);
    cudaFuncSetAttribute(hmma_gemm<128, 128, 3, false>,
                         cudaFuncAttributeMaxDynamicSharedMemorySize, HSMEM);
    cudaFuncSetAttribute(hmma_gemm<128, 128, 4, true>,
                         cudaFuncAttributeMaxDynamicSharedMemorySize, HSMEM);
    cudaFuncSetAttribute(rmlp_kernel,
                         cudaFuncAttributeMaxDynamicSharedMemorySize, RMLP_SMEM);

    // 0. conversions (merged)
    transpose2_h_kernel<<<dim3(R_ / 32, N_ / 32, 2), 256>>>(Rs, RsT, Rrm, RrT, Rrh);
    pack_objT_h_kernel<<<(N_ * 256 + 255) / 256, 256>>>(obj, objT);
    {
        int total = 64 * HID_ + HID_ * 64 + 64 * 64 + 96 * HID_ + HID_ * HID_;
        f2h5_kernel<<<(total + 255) / 256, 256>>>(rw1, w1h, rw3, w3h, rw4, w4h,
                                                  ow1, o1h, rw2, w2h);
    }

    // 1. both gathers in ONE launch (z selects Rs/Rr), overlapping DRAM streams
    hmma_gemm<128, 128, 5, false><<<dim3(2, R_ / 128, 2), 256, HSMEM>>>(
        RsT, RrT, objT, nullptr, node, 256, N_, N_, 0);

    // 2. fused relational MLP (node -> edgeT)
    rmlp_kernel<<<MROWS / 64, 256, RMLP_SMEM>>>(
        node, w1h, rb1, w2h, rb2, w3h, rb3, w4h, rb4, edgeT);

    // 3. aggregate: agg2[n, b*64+e] = sum_r Rr[n,r] * edgeT[r, b*64+e] (split-K=16)
    zero_kernel<<<(N_ * 512 + 255) / 256, 256>>>(agg2, N_ * 512);
    hmma_gemm<128, 128, 3, false><<<dim3(4, N_ / 128, 16), 256, HSMEM>>>(
        Rrh, nullptr, edgeT, nullptr, agg2, 512, R_, R_ / 16, 0);

    // 4. object MLP
    concat_h_kernel<<<(NROWS * 96 + 255) / 256, 256>>>(obj, agg2, upd);
    hmma_gemm<128, 128, 4, true><<<dim3(HID_ / 128, NROWS / 128), 256, HSMEM>>>(
        upd, nullptr, o1h, ob1, hobj, HID_, 96, 96, 0);
    gemm_kernel<128, 32, 8, 8, 2, false><<<dim3(1, NROWS / 128), 256>>>(
        hobj, ow2, ob2, out, NROWS, HID_, 32);
}

// round 17
// speedup vs baseline: 6.1375x; 1.0079x over previous
#include <cuda_runtime.h>
#include <cuda_fp16.h>
#include <cstdint>

// Problem dims
#define B_    8
#define N_    1024
#define R_    16384
#define HID_  512
#define MROWS (B_ * R_)      // 131072
#define NROWS (B_ * N_)      // 8192

// ---------------- scratch (device globals; no allocations allowed) ----------
__device__ __align__(128) __half gh_RsT [R_ * N_];      // Rs^T fp16 [16384,1024]
__device__ __align__(128) __half gh_RrT [R_ * N_];      // Rr^T fp16 [16384,1024]
__device__ __align__(128) __half gh_Rr  [N_ * R_];      // Rr fp16 [1024,16384]
__device__ __align__(128) __half gh_objT[N_ * 256];     // objT fp16 [1024,256] col=b*32+d
__device__ __align__(128) __half gh_node[MROWS * 64];   // node fp16
__device__ __align__(128) __half gh_edgeT[R_ * 512];    // edgeT fp16 [16384,512] col=b*64+e
__device__ __align__(128) __half gh_upd [NROWS * 96];
__device__ __align__(128) float  g_agg  [N_ * 512];     // agg fp32 [1024,512]
__device__ __align__(128) float  g_hobj [NROWS * HID_];
// fp16 weights
__device__ __align__(128) __half gh_w1[64 * HID_];
__device__ __align__(128) __half gh_w2[HID_ * HID_];
__device__ __align__(128) __half gh_w3[HID_ * 64];
__device__ __align__(128) __half gh_w4[64 * 64];
__device__ __align__(128) __half gh_o1[96 * HID_];

// ---------------- asm helpers ------------------------------------------------
__device__ __forceinline__ void mma_f16(float d[4], uint32_t a0, uint32_t a1,
                                        uint32_t a2, uint32_t a3,
                                        uint32_t b0, uint32_t b1) {
    asm volatile(
        "mma.sync.aligned.m16n8k16.row.col.f32.f16.f16.f32 "
        "{%0,%1,%2,%3},{%4,%5,%6,%7},{%8,%9},{%0,%1,%2,%3};\n"
        : "+f"(d[0]), "+f"(d[1]), "+f"(d[2]), "+f"(d[3])
        : "r"(a0), "r"(a1), "r"(a2), "r"(a3), "r"(b0), "r"(b1));
}
__device__ __forceinline__ void ldsm_x4(uint32_t r[4], uint32_t addr) {
    asm volatile("ldmatrix.sync.aligned.m8n8.x4.shared.b16 {%0,%1,%2,%3}, [%4];"
                 : "=r"(r[0]), "=r"(r[1]), "=r"(r[2]), "=r"(r[3]) : "r"(addr));
}
__device__ __forceinline__ void ldsm_x4_t(uint32_t r[4], uint32_t addr) {
    asm volatile("ldmatrix.sync.aligned.m8n8.x4.trans.shared.b16 {%0,%1,%2,%3}, [%4];"
                 : "=r"(r[0]), "=r"(r[1]), "=r"(r[2]), "=r"(r[3]) : "r"(addr));
}
#define CP16(dst, src) \
    asm volatile("cp.async.cg.shared.global [%0], [%1], 16;" :: "r"(dst), "l"(src))
#define CP_COMMIT() asm volatile("cp.async.commit_group;")
#define CP_WAIT(n)  asm volatile("cp.async.wait_group %0;" :: "n"(n))

__device__ __forceinline__ uint32_t smem_u32(const void* p) {
    return (uint32_t)__cvta_generic_to_shared(p);
}

// ================= fused relational MLP (512 threads) =========================
// edgeT = relu(relu(relu(relu(node@W1+b1)@W2+b2)@W3+b3)@W4+b4)
// BM=64 rows/CTA, 512 threads (16 warps: 2M x 8N64 for A/B; 8 warps 2M x 4N16 for C/D).
#define RMLP_SMEM (65536 + 131072 + 8192)

__global__ __launch_bounds__(512, 1) void rmlp_kernel(
    const __half* __restrict__ Anode,
    const __half* __restrict__ W1, const float* __restrict__ b1,
    const __half* __restrict__ W2, const float* __restrict__ b2,
    const __half* __restrict__ W3, const float* __restrict__ b3,
    const __half* __restrict__ W4, const float* __restrict__ b4,
    __half* __restrict__ C)
{
    extern __shared__ __align__(16) char dynsm[];
    const uint32_t s0 = smem_u32(dynsm);
    const uint32_t h1o = s0;
    const uint32_t wsto = s0 + 65536;
    const uint32_t nodeo = s0 + 196608;
    __half* h1p = (__half*)dynsm;
    __half* nodep = (__half*)(dynsm + 196608);

    const int tid = threadIdx.x, lane = tid & 31, wid = tid >> 5;
    const int wm = (wid >> 3) * 32;          // 2 M-groups of 32
    const int wn = (wid & 7) * 64;           // 8 N-groups of 64 (phases A,B)
    const int wn3 = (wid & 3) * 16;          // phases C,D (8 active warps)
    const bool cd_active = (wid & 7) < 4;
    const int row0 = blockIdx.x * 64;
    const int lc = lane & 3, lg = lane >> 2;

    // ---- prologue: node tile + W1 ----
    {
        {   // node: 512 chunks, 1 per thread
            int q = tid;
            int r = q >> 3, c8 = q & 7, t = c8 >> 2, c = c8 & 3;
            CP16(nodeo + t * 4096 + (r * 4 + (c ^ ((r >> 1) & 3))) * 16,
                 &Anode[(size_t)(row0 + r) * 64 + c8 * 8]);
        }
        #pragma unroll
        for (int p = 0; p < 8; p++) {        // W1: 64x512 = 4096 chunks (FIXED: was 4)
            int q = tid + p * 512;
            int kb = q >> 11, rem = q & 2047, k = rem >> 6, c = rem & 63;
            CP16(wsto + kb * 32768 + (k * 64 + (c ^ (k & 7))) * 16,
                 &W1[(size_t)(kb * 32 + k) * 512 + c * 8]);
        }
        CP_COMMIT();
        CP_WAIT(0);
        __syncthreads();
    }

    float acc[2][8][4];
    #pragma unroll
    for (int mi = 0; mi < 2; mi++)
        #pragma unroll
        for (int ni = 0; ni < 8; ni++)
            #pragma unroll
            for (int j = 0; j < 4; j++) acc[mi][ni][j] = 0.f;

    // ---- phase A: h1 = relu(node @ W1 + b1), K=64 ----
    #pragma unroll
    for (int t = 0; t < 2; t++) {
        #pragma unroll
        for (int s = 0; s < 2; s++) {
            uint32_t af[2][4], bf[4][4];
            #pragma unroll
            for (int mi = 0; mi < 2; mi++) {
                int r = wm + mi * 16 + (lane & 15);
                int c = s * 2 + (lane >> 4);
                ldsm_x4(af[mi], nodeo + t * 4096 + (r * 4 + (c ^ ((r >> 1) & 3))) * 16);
            }
            #pragma unroll
            for (int np = 0; np < 4; np++) {
                int k = s * 16 + (lane & 15);
                int c = (wn >> 3) + np * 2 + (lane >> 4);
                ldsm_x4_t(bf[np], wsto + t * 32768 + (k * 64 + (c ^ (k & 7))) * 16);
            }
            #pragma unroll
            for (int mi = 0; mi < 2; mi++)
                #pragma unroll
                for (int ni = 0; ni < 8; ni++)
                    mma_f16(acc[mi][ni], af[mi][0], af[mi][1], af[mi][2], af[mi][3],
                            bf[ni >> 1][(ni & 1) * 2], bf[ni >> 1][(ni & 1) * 2 + 1]);
        }
    }
    __syncthreads();

    #pragma unroll
    for (int mi = 0; mi < 2; mi++) {
        #pragma unroll
        for (int ni = 0; ni < 8; ni++) {
            int c0 = wn + ni * 8 + lc * 2;
            int kb2 = c0 >> 5, ck = (c0 >> 3) & 3;
            #pragma unroll
            for (int h = 0; h < 2; h++) {
                int r = wm + mi * 16 + lg + h * 8;
                float v0 = fmaxf(acc[mi][ni][h * 2 + 0] + b1[c0],     0.f);
                float v1 = fmaxf(acc[mi][ni][h * 2 + 1] + b1[c0 + 1], 0.f);
                *(__half2*)&h1p[(kb2 * 4096 + (r * 4 + (ck ^ ((r >> 1) & 3))) * 16 + (c0 & 7) * 2) / 2]
                    = __floats2half2_rn(v0, v1);
            }
        }
    }
    auto w2_stage = [&](int t, int st) {
        if (t < 16) {
            #pragma unroll
            for (int p = 0; p < 4; p++) {    // 32x512 tile = 2048 chunks
                int q = tid + p * 512;
                int k = q >> 6, c = q & 63;
                CP16(wsto + st * 32768 + (k * 64 + (c ^ (k & 7))) * 16,
                     &W2[(size_t)(t * 32 + k) * 512 + c * 8]);
            }
        }
        CP_COMMIT();
    };
    w2_stage(0, 0); w2_stage(1, 1); w2_stage(2, 2);
    __syncthreads();

    #pragma unroll
    for (int mi = 0; mi < 2; mi++)
        #pragma unroll
        for (int ni = 0; ni < 8; ni++)
            #pragma unroll
            for (int j = 0; j < 4; j++) acc[mi][ni][j] = 0.f;

    // ---- phase B: h2 = relu(h1 @ W2 + b2), K=512, 4-stage W2 pipeline ----
    for (int kt = 0; kt < 16; kt++) {
        CP_WAIT(2);
        __syncthreads();
        w2_stage(kt + 3, (kt + 3) & 3);
        const int st = kt & 3;
        #pragma unroll
        for (int s = 0; s < 2; s++) {
            uint32_t af[2][4], bf[4][4];
            #pragma unroll
            for (int mi = 0; mi < 2; mi++) {
                int r = wm + mi * 16 + (lane & 15);
                int c = s * 2 + (lane >> 4);
                ldsm_x4(af[mi], h1o + kt * 4096 + (r * 4 + (c ^ ((r >> 1) & 3))) * 16);
            }
            #pragma unroll
            for (int np = 0; np < 4; np++) {
                int k = s * 16 + (lane & 15);
                int c = (wn >> 3) + np * 2 + (lane >> 4);
                ldsm_x4_t(bf[np], wsto + st * 32768 + (k * 64 + (c ^ (k & 7))) * 16);
            }
            #pragma unroll
            for (int mi = 0; mi < 2; mi++)
                #pragma unroll
                for (int ni = 0; ni < 8; ni++)
                    mma_f16(acc[mi][ni], af[mi][0], af[mi][1], af[mi][2], af[mi][3],
                            bf[ni >> 1][(ni & 1) * 2], bf[ni >> 1][(ni & 1) * 2 + 1]);
        }
    }
    CP_WAIT(0);
    __syncthreads();

    #pragma unroll
    for (int mi = 0; mi < 2; mi++) {
        #pragma unroll
        for (int ni = 0; ni < 8; ni++) {
            int c0 = wn + ni * 8 + lc * 2;
            int kb2 = c0 >> 5, ck = (c0 >> 3) & 3;
            #pragma unroll
            for (int h = 0; h < 2; h++) {
                int r = wm + mi * 16 + lg + h * 8;
                float v0 = fmaxf(acc[mi][ni][h * 2 + 0] + b2[c0],     0.f);
                float v1 = fmaxf(acc[mi][ni][h * 2 + 1] + b2[c0 + 1], 0.f);
                *(__half2*)&h1p[(kb2 * 4096 + (r * 4 + (ck ^ ((r >> 1) & 3))) * 16 + (c0 & 7) * 2) / 2]
                    = __floats2half2_rn(v0, v1);
            }
        }
    }
    {
        #pragma unroll
        for (int p = 0; p < 8; p++) {        // W3: 512x64 = 4096 chunks
            int q = tid + p * 512;
            int kb = q >> 8, rem = q & 255, k = rem >> 3, c = rem & 7;
            CP16(wsto + kb * 4096 + (k * 8 + (c ^ (k & 7))) * 16,
                 &W3[(size_t)(kb * 32 + k) * 64 + c * 8]);
        }
        {   // W4: 64x64 = 512 chunks, 1 per thread
            int q = tid;
            int kb = q >> 8, rem = q & 255, k = rem >> 3, c = rem & 7;
            CP16(wsto + 65536 + kb * 4096 + (k * 8 + (c ^ (k & 7))) * 16,
                 &W4[(size_t)(kb * 32 + k) * 64 + c * 8]);
        }
        CP_COMMIT();
        CP_WAIT(0);
        __syncthreads();
    }

    // ---- phase C: h3 = relu(h2 @ W3 + b3), K=512, N=64 (8 active warps) ----
    float ac2[2][2][4];
    #pragma unroll
    for (int mi = 0; mi < 2; mi++)
        #pragma unroll
        for (int ni = 0; ni < 2; ni++)
            #pragma unroll
            for (int j = 0; j < 4; j++) ac2[mi][ni][j] = 0.f;

    if (cd_active) {
        for (int kt = 0; kt < 16; kt++) {
            #pragma unroll
            for (int s = 0; s < 2; s++) {
                uint32_t af[2][4], bf1[4];
                #pragma unroll
                for (int mi = 0; mi < 2; mi++) {
                    int r = wm + mi * 16 + (lane & 15);
                    int c = s * 2 + (lane >> 4);
                    ldsm_x4(af[mi], h1o + kt * 4096 + (r * 4 + (c ^ ((r >> 1) & 3))) * 16);
                }
                {
                    int k = s * 16 + (lane & 15);
                    int c = (wn3 >> 3) + (lane >> 4);
                    ldsm_x4_t(bf1, wsto + kt * 4096 + (k * 8 + (c ^ (k & 7))) * 16);
                }
                #pragma unroll
                for (int mi = 0; mi < 2; mi++)
                    #pragma unroll
                    for (int ni = 0; ni < 2; ni++)
                        mma_f16(ac2[mi][ni], af[mi][0], af[mi][1], af[mi][2], af[mi][3],
                                bf1[ni * 2], bf1[ni * 2 + 1]);
            }
        }

        #pragma unroll
        for (int mi = 0; mi < 2; mi++) {
            #pragma unroll
            for (int ni = 0; ni < 2; ni++) {
                int c0 = wn3 + ni * 8 + lc * 2;
                int kb = c0 >> 5, ck = (c0 >> 3) & 3;
                #pragma unroll
                for (int h = 0; h < 2; h++) {
                    int r = wm + mi * 16 + lg + h * 8;
                    float v0 = fmaxf(ac2[mi][ni][h * 2 + 0] + b3[c0],     0.f);
                    float v1 = fmaxf(ac2[mi][ni][h * 2 + 1] + b3[c0 + 1], 0.f);
                    *(__half2*)&nodep[(kb * 4096 + (r * 4 + (ck ^ ((r >> 1) & 3))) * 16 + (c0 & 7) * 2) / 2]
                        = __floats2half2_rn(v0, v1);
                }
            }
        }
    }
    __syncthreads();

    // ---- phase D: edge = relu(h3 @ W4 + b4), K=64 ----
    if (cd_active) {
        #pragma unroll
        for (int mi = 0; mi < 2; mi++)
            #pragma unroll
            for (int ni = 0; ni < 2; ni++)
                #pragma unroll
                for (int j = 0; j < 4; j++) ac2[mi][ni][j] = 0.f;

        #pragma unroll
        for (int t = 0; t < 2; t++) {
            #pragma unroll
            for (int s = 0; s < 2; s++) {
                uint32_t af[2][4], bf1[4];
                #pragma unroll
                for (int mi = 0; mi < 2; mi++) {
                    int r = wm + mi * 16 + (lane & 15);
                    int c = s * 2 + (lane >> 4);
                    ldsm_x4(af[mi], nodeo + t * 4096 + (r * 4 + (c ^ ((r >> 1) & 3))) * 16);
                }
                {
                    int k = s * 16 + (lane & 15);
                    int c = (wn3 >> 3) + (lane >> 4);
                    ldsm_x4_t(bf1, wsto + 65536 + t * 4096 + (k * 8 + (c ^ (k & 7))) * 16);
                }
                #pragma unroll
                for (int mi = 0; mi < 2; mi++)
                    #pragma unroll
                    for (int ni = 0; ni < 2; ni++)
                        mma_f16(ac2[mi][ni], af[mi][0], af[mi][1], af[mi][2], af[mi][3],
                                bf1[ni * 2], bf1[ni * 2 + 1]);
            }
        }

        #pragma unroll
        for (int mi = 0; mi < 2; mi++) {
            #pragma unroll
            for (int ni = 0; ni < 2; ni++) {
                int c0 = wn3 + ni * 8 + lc * 2;
                #pragma unroll
                for (int h = 0; h < 2; h++) {
                    int row = row0 + wm + mi * 16 + lg + h * 8;
                    float v0 = fmaxf(ac2[mi][ni][h * 2 + 0] + b4[c0],     0.f);
                    float v1 = fmaxf(ac2[mi][ni][h * 2 + 1] + b4[c0 + 1], 0.f);
                    int b = row >> 14, r = row & 16383;
                    *(__half2*)&C[(size_t)r * 512 + (b << 6) + c0] = __floats2half2_rn(v0, v1);
                }
            }
        }
    }
}

// ---------------- fp16 cp.async + ldmatrix GEMM (4-stage, dynamic smem) ------
// MODE: 0 = fp16 out  1 = gather-scatter  3 = atomic fp32  4 = fp32 out
// MODE 5 = dual-gather: blockIdx.z selects A (0) / A2 (1), off = z*32, kstart=0.
template<int BM, int BN, int MODE, bool RELU>
__global__ __launch_bounds__((BM/64)*(BN/32)*32, 2) void hmma_gemm(
    const __half* __restrict__ A, const __half* __restrict__ A2,
    const __half* __restrict__ W,
    const float* __restrict__ bias, void* __restrict__ C,
    int N, int lda, int klen, int off)
{
    constexpr int BK = 32, STAGES = 4;
    constexpr int NW_N = BN / 32;
    constexpr int THREADS = (BM/64) * NW_N * 32;
    constexpr int ACH = BM * 4;
    constexpr int BCHR = BN / 8;
    constexpr int BCH = BK * BCHR;
    constexpr int APT = ACH / THREADS, BPT = BCH / THREADS;
    extern __shared__ __align__(16) char dynsm[];
    const uint32_t a_s0 = smem_u32(dynsm);
    const uint32_t b_s0 = a_s0 + STAGES * BM * BK * 2;

    const int tid = threadIdx.x, lane = tid & 31, wid = tid >> 5;
    const int wm = (wid / NW_N) * 64, wn = (wid % NW_N) * 32;
    const int row0 = blockIdx.y * BM, col0 = blockIdx.x * BN;
    const __half* Ap = (MODE == 5 && blockIdx.z) ? A2 : A;
    const int kstart = (MODE == 5) ? 0 : blockIdx.z * klen;
    const int offv = (MODE == 5) ? (int)blockIdx.z * 32 : off;
    const int ntiles = klen / BK;

    float acc[4][4][4];
    #pragma unroll
    for (int mi = 0; mi < 4; mi++)
        #pragma unroll
        for (int ni = 0; ni < 4; ni++)
            #pragma unroll
            for (int j = 0; j < 4; j++) acc[mi][ni][j] = 0.f;

    auto stage_copy = [&](int t, int st) {
        if (t < ntiles) {
            const int kk = kstart + t * BK;
            #pragma unroll
            for (int p = 0; p < APT; p++) {
                int q = tid + p * THREADS;
                int r = q >> 2, c = q & 3;
                uint32_t dst = a_s0 + (uint32_t)(st * BM * BK + (r * 4 + (c ^ ((r >> 1) & 3))) * 8) * 2;
                CP16(dst, &Ap[(size_t)(row0 + r) * lda + kk + c * 8]);
            }
            #pragma unroll
            for (int p = 0; p < BPT; p++) {
                int q = tid + p * THREADS;
                int k = q / BCHR, c = q % BCHR;
                uint32_t dst = b_s0 + (uint32_t)(st * BK * BN + (k * BCHR + (c ^ (k & 7))) * 8) * 2;
                CP16(dst, &W[(size_t)(kk + k) * N + col0 + c * 8]);
            }
        }
        CP_COMMIT();
    };

    #pragma unroll
    for (int t = 0; t < STAGES - 1; t++) stage_copy(t, t);

    for (int t = 0; t < ntiles; t++) {
        CP_WAIT(STAGES - 2);
        __syncthreads();
        stage_copy(t + STAGES - 1, (t + STAGES - 1) % STAGES);
        const int st = t % STAGES;
        const uint32_t abase = a_s0 + (uint32_t)(st * BM * BK) * 2;
        const uint32_t bbase = b_s0 + (uint32_t)(st * BK * BN) * 2;
        #pragma unroll
        for (int s = 0; s < 2; s++) {
            uint32_t af[4][4], bf[2][4];
            #pragma unroll
            for (int mi = 0; mi < 4; mi++) {
                int r = wm + mi * 16 + (lane & 15);
                int c = s * 2 + (lane >> 4);
                ldsm_x4(af[mi], abase + (uint32_t)((r * 4 + (c ^ ((r >> 1) & 3))) * 16));
            }
            #pragma unroll
            for (int np = 0; np < 2; np++) {
                int k = s * 16 + (lane & 15);
                int c = (wn >> 3) + np * 2 + (lane >> 4);
                ldsm_x4_t(bf[np], bbase + (uint32_t)((k * BCHR + (c ^ (k & 7))) * 16));
            }
            #pragma unroll
            for (int mi = 0; mi < 4; mi++)
                #pragma unroll
                for (int ni = 0; ni < 4; ni++)
                    mma_f16(acc[mi][ni], af[mi][0], af[mi][1], af[mi][2], af[mi][3],
                            bf[ni >> 1][(ni & 1) * 2], bf[ni >> 1][(ni & 1) * 2 + 1]);
        }
    }

    // epilogue
    const int lc = lane & 3, lg = lane >> 2;
    #pragma unroll
    for (int mi = 0; mi < 4; mi++) {
        int r0 = row0 + wm + mi * 16 + lg;
        #pragma unroll
        for (int ni = 0; ni < 4; ni++) {
            int c0 = col0 + wn + ni * 8 + lc * 2;
            #pragma unroll
            for (int h = 0; h < 2; h++) {
                int row = r0 + h * 8;
                float v0 = acc[mi][ni][h * 2 + 0];
                float v1 = acc[mi][ni][h * 2 + 1];
                if (MODE == 0 || MODE == 4) {
                    v0 += bias[c0]; v1 += bias[c0 + 1];
                    if (RELU) { v0 = fmaxf(v0, 0.f); v1 = fmaxf(v1, 0.f); }
                }
                if (MODE == 0) {
                    *(__half2*)&((__half*)C)[(size_t)row * N + c0] = __floats2half2_rn(v0, v1);
                } else if (MODE == 1 || MODE == 5) {
                    int b = c0 >> 5, d = c0 & 31;
                    *(__half2*)&((__half*)C)[(((size_t)b << 14) + row) * 64 + offv + d] =
                        __floats2half2_rn(v0, v1);
                } else if (MODE == 3) {
                    atomicAdd(&((float*)C)[(size_t)row * N + c0], v0);
                    atomicAdd(&((float*)C)[(size_t)row * N + c0 + 1], v1);
                } else {
                    ((float*)C)[(size_t)row * N + c0]     = v0;
                    ((float*)C)[(size_t)row * N + c0 + 1] = v1;
                }
            }
        }
    }
}

// ---------------- dual transpose+convert (z: 0=Rs, 1=Rr+Rrh) ----------------
__global__ __launch_bounds__(256) void transpose2_h_kernel(
    const float* __restrict__ Rs, __half* __restrict__ RsT,
    const float* __restrict__ Rr, __half* __restrict__ RrT, __half* __restrict__ Rrh)
{
    __shared__ __half sm[32][33];
    const float* R = blockIdx.z ? Rr : Rs;
    __half* RT = blockIdx.z ? RrT : RsT;
    __half* Rh = blockIdx.z ? Rrh : nullptr;
    const int tx = threadIdx.x & 31, ty = threadIdx.x >> 5;
    const int rb = blockIdx.x * 32, nb = blockIdx.y * 32;
    #pragma unroll
    for (int j = 0; j < 4; j++) {
        int n = nb + ty + j * 8, r = rb + tx;
        __half h = __float2half_rn(R[(size_t)n * R_ + r]);
        if (Rh) Rh[(size_t)n * R_ + r] = h;
        sm[ty + j * 8][tx] = h;
    }
    __syncthreads();
    #pragma unroll
    for (int j = 0; j < 4; j++) {
        int r = rb + ty + j * 8, n = nb + tx;
        RT[(size_t)r * N_ + n] = sm[tx][ty + j * 8];
    }
}

// ---------------- small utility kernels --------------------------------------
__global__ void f2h5_kernel(const float* s1, __half* d1,
                            const float* s2, __half* d2,
                            const float* s3, __half* d3,
                            const float* s4, __half* d4,
                            const float* s5, __half* d5) {
    const int n1 = 64 * HID_, n2 = HID_ * 64, n3 = 64 * 64, n4 = 96 * HID_;
    const int n5 = HID_ * HID_;
    int i = blockIdx.x * blockDim.x + threadIdx.x;
    if (i < n1) d1[i] = __float2half_rn(s1[i]);
    else if (i < n1 + n2) d2[i - n1] = __float2half_rn(s2[i - n1]);
    else if (i < n1 + n2 + n3) d3[i - n1 - n2] = __float2half_rn(s3[i - n1 - n2]);
    else if (i < n1 + n2 + n3 + n4) d4[i - n1 - n2 - n3] = __float2half_rn(s4[i - n1 - n2 - n3]);
    else if (i < n1 + n2 + n3 + n4 + n5) d5[i - n1 - n2 - n3 - n4] = __float2half_rn(s5[i - n1 - n2 - n3 - n4]);
}

__global__ void pack_objT_h_kernel(const float* __restrict__ obj, __half* __restrict__ objT) {
    int i = blockIdx.x * blockDim.x + threadIdx.x;
    if (i < N_ * 256) {
        int n = i >> 8, c = i & 255;
        int b = c >> 5, d = c & 31;
        objT[i] = __float2half_rn(obj[((size_t)b * N_ + n) * 32 + d]);
    }
}

__global__ void zero_kernel(float* p, int n) {
    int i = blockIdx.x * blockDim.x + threadIdx.x;
    if (i < n) p[i] = 0.f;
}

__global__ void concat_h_kernel(const float* __restrict__ obj,
                                const float* __restrict__ agg2,
                                __half* __restrict__ upd) {
    int i = blockIdx.x * blockDim.x + threadIdx.x;
    if (i < NROWS * 96) {
        int row = i / 96, j = i % 96;
        int b = row >> 10, n = row & 1023;
        float v = (j < 32) ? obj[(size_t)row * 32 + j]
                           : agg2[(size_t)n * 512 + (b << 6) + (j - 32)];
        upd[i] = __float2half_rn(v);
    }
}

// ---------------- SIMT fp32 GEMM (tiny final layer) --------------------------
template<int BM, int BN, int BK, int TM, int TN, bool RELU>
__global__ __launch_bounds__((BM/TM)*(BN/TN)) void gemm_kernel(
    const float* __restrict__ A, const float* __restrict__ W,
    const float* __restrict__ bias, float* __restrict__ C,
    int M, int K, int N)
{
    __shared__ float As[BK][BM];
    __shared__ float Ws[BK][BN];
    const int nthr = (BM / TM) * (BN / TN);
    const int tid = threadIdx.x;
    const int tn = tid % (BN / TN);
    const int tm = tid / (BN / TN);
    const int row0 = blockIdx.y * BM;
    const int col0 = blockIdx.x * BN;

    float acc[TM][TN];
    #pragma unroll
    for (int m = 0; m < TM; m++)
        #pragma unroll
        for (int n = 0; n < TN; n++) acc[m][n] = 0.f;

    for (int k0 = 0; k0 < K; k0 += BK) {
        #pragma unroll
        for (int i = tid * 4; i < BM * BK; i += nthr * 4) {
            int r = i / BK, c = i % BK;
            float4 v = *(const float4*)&A[(size_t)(row0 + r) * K + k0 + c];
            As[c + 0][r] = v.x; As[c + 1][r] = v.y;
            As[c + 2][r] = v.z; As[c + 3][r] = v.w;
        }
        #pragma unroll
        for (int i = tid * 4; i < BK * BN; i += nthr * 4) {
            int r = i / BN, c = i % BN;
            *(float4*)&Ws[r][c] = *(const float4*)&W[(size_t)(k0 + r) * N + col0 + c];
        }
        __syncthreads();
        #pragma unroll
        for (int k = 0; k < BK; k++) {
            float a[TM], b[TN];
            #pragma unroll
            for (int m = 0; m < TM; m++) a[m] = As[k][tm * TM + m];
            #pragma unroll
            for (int n = 0; n < TN; n++) b[n] = Ws[k][tn * TN + n];
            #pragma unroll
            for (int m = 0; m < TM; m++)
                #pragma unroll
                for (int n = 0; n < TN; n++) acc[m][n] += a[m] * b[n];
        }
        __syncthreads();
    }
    #pragma unroll
    for (int m = 0; m < TM; m++) {
        int row = row0 + tm * TM + m;
        #pragma unroll
        for (int n = 0; n < TN; n++) {
            int col = col0 + tn * TN + n;
            float v = acc[m][n] + bias[col];
            if (RELU) v = fmaxf(v, 0.f);
            C[(size_t)row * N + col] = v;
        }
    }
}

// ---------------- launch ----------------------------------------------------
#define HSMEM (4 * (128 * 32 + 32 * 128) * 2)       // 65536

extern "C" void kernel_launch(void* const* d_in, const int* in_sizes, int n_in,
                              void* d_out, int out_size) {
    const float* obj = (const float*)d_in[0];
    const float* Rs  = (const float*)d_in[1];
    const float* Rrm = (const float*)d_in[2];
    const float* rw1 = (const float*)d_in[3];  const float* rb1 = (const float*)d_in[4];
    const float* rw2 = (const float*)d_in[5];  const float* rb2 = (const float*)d_in[6];
    const float* rw3 = (const float*)d_in[7];  const float* rb3 = (const float*)d_in[8];
    const float* rw4 = (const float*)d_in[9];  const float* rb4 = (const float*)d_in[10];
    const float* ow1 = (const float*)d_in[11]; const float* ob1 = (const float*)d_in[12];
    const float* ow2 = (const float*)d_in[13]; const float* ob2 = (const float*)d_in[14];
    float* out = (float*)d_out;

    __half *RsT, *RrT, *Rrh, *objT, *node, *edgeT, *upd;
    __half *w1h, *w2h, *w3h, *w4h, *o1h;
    float *agg2, *hobj;
    cudaGetSymbolAddress((void**)&RsT,  gh_RsT);
    cudaGetSymbolAddress((void**)&RrT,  gh_RrT);
    cudaGetSymbolAddress((void**)&Rrh,  gh_Rr);
    cudaGetSymbolAddress((void**)&objT, gh_objT);
    cudaGetSymbolAddress((void**)&node, gh_node);
    cudaGetSymbolAddress((void**)&edgeT,gh_edgeT);
    cudaGetSymbolAddress((void**)&upd,  gh_upd);
    cudaGetSymbolAddress((void**)&agg2, g_agg);
    cudaGetSymbolAddress((void**)&hobj, g_hobj);
    cudaGetSymbolAddress((void**)&w1h,  gh_w1);
    cudaGetSymbolAddress((void**)&w2h,  gh_w2);
    cudaGetSymbolAddress((void**)&w3h,  gh_w3);
    cudaGetSymbolAddress((void**)&w4h,  gh_w4);
    cudaGetSymbolAddress((void**)&o1h,  gh_o1);

    cudaFuncSetAttribute(hmma_gemm<128, 128, 5, false>,
                         cudaFuncAttributeMaxDynamicSharedMemorySize, HSMEM);
    cudaFuncSetAttribute(hmma_gemm<128, 128, 3, false>,
                         cudaFuncAttributeMaxDynamicSharedMemorySize, HSMEM);
    cudaFuncSetAttribute(hmma_gemm<128, 128, 4, true>,
                         cudaFuncAttributeMaxDynamicSharedMemorySize, HSMEM);
    cudaFuncSetAttribute(rmlp_kernel,
                         cudaFuncAttributeMaxDynamicSharedMemorySize, RMLP_SMEM);

    // 0. conversions (merged)
    transpose2_h_kernel<<<dim3(R_ / 32, N_ / 32, 2), 256>>>(Rs, RsT, Rrm, RrT, Rrh);
    pack_objT_h_kernel<<<(N_ * 256 + 255) / 256, 256>>>(obj, objT);
    {
        int total = 64 * HID_ + HID_ * 64 + 64 * 64 + 96 * HID_ + HID_ * HID_;
        f2h5_kernel<<<(total + 255) / 256, 256>>>(rw1, w1h, rw3, w3h, rw4, w4h,
                                                  ow1, o1h, rw2, w2h);
    }

    // 1. both gathers in ONE launch (z selects Rs/Rr)
    hmma_gemm<128, 128, 5, false><<<dim3(2, R_ / 128, 2), 256, HSMEM>>>(
        RsT, RrT, objT, nullptr, node, 256, N_, N_, 0);

    // 2. fused relational MLP (node -> edgeT), 512 threads/CTA
    rmlp_kernel<<<MROWS / 64, 512, RMLP_SMEM>>>(
        node, w1h, rb1, w2h, rb2, w3h, rb3, w4h, rb4, edgeT);

    // 3. aggregate: agg2[n, b*64+e] = sum_r Rr[n,r] * edgeT[r, b*64+e] (split-K=16)
    zero_kernel<<<(N_ * 512 + 255) / 256, 256>>>(agg2, N_ * 512);
    hmma_gemm<128, 128, 3, false><<<dim3(4, N_ / 128, 16), 256, HSMEM>>>(
        Rrh, nullptr, edgeT, nullptr, agg2, 512, R_, R_ / 16, 0);

    // 4. object MLP
    concat_h_kernel<<<(NROWS * 96 + 255) / 256, 256>>>(obj, agg2, upd);
    hmma_gemm<128, 128, 4, true><<<dim3(HID_ / 128, NROWS / 128), 256, HSMEM>>>(
        upd, nullptr, o1h, ob1, hobj, HID_, 96, 96, 0);
    gemm_kernel<128, 32, 8, 8, 2, false><<<dim3(1, NROWS / 128), 256>>>(
        hobj, ow2, ob2, out, NROWS, HID_, 32);
}